// round 9
// baseline (speedup 1.0000x reference)
#include <cuda_runtime.h>
#include <cuda_bf16.h>
#include <stdint.h>
#include <math.h>

#define BS 4096
#define AGENTS 128
#define OBSD 128
#define ACT 8
#define SD 4096
#define EMB 32
#define H1 128
#define H2 64

// ---------------- scratch (static device globals; no allocation) ----------------
__device__ float g_qs[(size_t)BS * AGENTS];           // agent_qs [b][a]
__device__ float g_act_fallback[(size_t)BS * AGENTS];
__device__ float g_part[(size_t)64 * BS * EMB];       // GEMM partial sums [slab][b][e] 32MB
#define HKS 8
__device__ float g_hsp[(size_t)HKS * BS * 96];        // hyper_small partials [kz][b][96]

// bf16 split operands, plain row-major
__device__ __nv_bfloat16 g_Shi[(size_t)BS * SD];      // A hi  [m][k]
__device__ __nv_bfloat16 g_Slo[(size_t)BS * SD];      // A lo
__device__ __nv_bfloat16 g_Bhi[(size_t)SD * SD];      // B hi  [n][k]  (B[n][k] = Wh1[k][n])
__device__ __nv_bfloat16 g_Blo[(size_t)SD * SD];

// ============================ PTX helpers =====================================
__device__ __forceinline__ uint32_t smem_u32(const void* p) {
    uint32_t a;
    asm("{ .reg .u64 t; cvta.to.shared.u64 t, %1; cvt.u32.u64 %0, t; }" : "=r"(a) : "l"(p));
    return a;
}

__device__ __forceinline__ void cp16(uint32_t s, const void* g) {
    asm volatile("cp.async.cg.shared.global [%0], [%1], 16;" :: "r"(s), "l"(g));
}
#define CP_COMMIT() asm volatile("cp.async.commit_group;")
#define CP_WAIT2()  asm volatile("cp.async.wait_group 2;")

__device__ __forceinline__ void ldm4(uint32_t* r, uint32_t addr) {
    asm volatile("ldmatrix.sync.aligned.m8n8.x4.shared.b16 {%0,%1,%2,%3}, [%4];"
        : "=r"(r[0]), "=r"(r[1]), "=r"(r[2]), "=r"(r[3]) : "r"(addr));
}

__device__ __forceinline__ void mma_bf16(float* c, const uint32_t* a, const uint32_t* b) {
    asm volatile("mma.sync.aligned.m16n8k16.row.col.f32.bf16.bf16.f32 "
        "{%0,%1,%2,%3}, {%4,%5,%6,%7}, {%8,%9}, {%0,%1,%2,%3};"
        : "+f"(c[0]), "+f"(c[1]), "+f"(c[2]), "+f"(c[3])
        : "r"(a[0]), "r"(a[1]), "r"(a[2]), "r"(a[3]), "r"(b[0]), "r"(b[1]));
}

// =============================================================================
// Kernel 1: fused per-agent 3-layer MLP + max/argmax. 512 threads. (R7 version)
// =============================================================================
#define MLP_BT 64
#define MLP_SMEM ((64*132 + 64*68 + 64*132 + 128*128) * 4)

__global__ void __launch_bounds__(512) mlp_kernel(
    const float* __restrict__ obs,
    const float* __restrict__ W1, const float* __restrict__ b1,
    const float* __restrict__ W2, const float* __restrict__ b2,
    const float* __restrict__ W3, const float* __restrict__ b3,
    float* __restrict__ actions_out)
{
    extern __shared__ float sm[];
    float* x1s  = sm;                       // [64][132]
    float* x2s  = sm + 64*132;              // [64][68]
    float* obss = sm + 64*132 + 64*68;      // [64][132]
    float* ws   = sm + 64*132 + 64*68 + 64*132;  // up to [128][128]
    __shared__ float b1s[H1];
    __shared__ float b2s[H2];
    __shared__ float b3s[ACT];

    const int a   = blockIdx.x;
    const int b0  = blockIdx.y * MLP_BT;
    const int tid = threadIdx.x;

    if (tid < H1) b1s[tid] = b1[a*H1 + tid];
    if (tid < H2) b2s[tid] = b2[a*H2 + tid];
    if (tid < ACT) b3s[tid] = b3[a*ACT + tid];

    {
        const float4* w1g = (const float4*)(W1 + (size_t)a * OBSD * H1);
        float4* wd = (float4*)ws;
        for (int i = tid; i < OBSD*H1/4; i += 512) wd[i] = w1g[i];
    }
    for (int i = tid; i < MLP_BT * (OBSD/4); i += 512) {
        int r  = i >> 5;
        int c4 = i & 31;
        float4 v = ((const float4*)(obs + ((size_t)(b0 + r) * AGENTS + a) * OBSD))[c4];
        *(float4*)(obss + r*132 + c4*4) = v;
    }
    __syncthreads();

    // layer 1
    {
        const int ty = tid >> 5, tx = tid & 31;
        float acc[4][4];
        #pragma unroll
        for (int i = 0; i < 4; i++)
            #pragma unroll
            for (int j = 0; j < 4; j++) acc[i][j] = 0.f;

        #pragma unroll 4
        for (int k = 0; k < OBSD; k++) {
            float a0 = obss[(ty*4+0)*132 + k];
            float a1 = obss[(ty*4+1)*132 + k];
            float a2 = obss[(ty*4+2)*132 + k];
            float a3 = obss[(ty*4+3)*132 + k];
            float4 w = *(const float4*)(ws + k*H1 + tx*4);
            float wv[4] = {w.x, w.y, w.z, w.w};
            #pragma unroll
            for (int j = 0; j < 4; j++) {
                acc[0][j] = fmaf(a0, wv[j], acc[0][j]);
                acc[1][j] = fmaf(a1, wv[j], acc[1][j]);
                acc[2][j] = fmaf(a2, wv[j], acc[2][j]);
                acc[3][j] = fmaf(a3, wv[j], acc[3][j]);
            }
        }
        #pragma unroll
        for (int i = 0; i < 4; i++) {
            float4 o;
            float* ov = (float*)&o;
            #pragma unroll
            for (int j = 0; j < 4; j++) {
                float v = acc[i][j] + b1s[tx*4 + j];
                ov[j] = v > 0.f ? v : 0.f;
            }
            *(float4*)(x1s + (ty*4+i)*132 + tx*4) = o;
        }
    }
    __syncthreads();

    {
        const float4* w2g = (const float4*)(W2 + (size_t)a * H1 * H2);
        float4* wd = (float4*)ws;
        for (int i = tid; i < H1*H2/4; i += 512) wd[i] = w2g[i];
    }
    __syncthreads();

    // layer 2
    {
        const int ry = tid >> 4, tx = tid & 15;
        float acc[2][4];
        #pragma unroll
        for (int i = 0; i < 2; i++)
            #pragma unroll
            for (int j = 0; j < 4; j++) acc[i][j] = 0.f;

        #pragma unroll 4
        for (int k = 0; k < H1; k++) {
            float a0 = x1s[(ry*2+0)*132 + k];
            float a1 = x1s[(ry*2+1)*132 + k];
            float4 w = *(const float4*)(ws + k*H2 + tx*4);
            float wv[4] = {w.x, w.y, w.z, w.w};
            #pragma unroll
            for (int j = 0; j < 4; j++) {
                acc[0][j] = fmaf(a0, wv[j], acc[0][j]);
                acc[1][j] = fmaf(a1, wv[j], acc[1][j]);
            }
        }
        #pragma unroll
        for (int i = 0; i < 2; i++) {
            float4 o;
            float* ov = (float*)&o;
            #pragma unroll
            for (int j = 0; j < 4; j++) {
                float v = acc[i][j] + b2s[tx*4 + j];
                ov[j] = v > 0.f ? v : 0.f;
            }
            *(float4*)(x2s + (ry*2+i)*68 + tx*4) = o;
        }
    }
    __syncthreads();

    {
        const float4* w3g = (const float4*)(W3 + (size_t)a * H2 * ACT);
        float4* wd = (float4*)ws;
        for (int i = tid; i < H2*ACT/4; i += 512) wd[i] = w3g[i];
    }
    __syncthreads();

    // layer 3 + argmax
    if (tid < MLP_BT) {
        const int r = tid;
        float acc[8];
        #pragma unroll
        for (int c = 0; c < 8; c++) acc[c] = 0.f;
        #pragma unroll 4
        for (int k = 0; k < H2; k++) {
            float x = x2s[r*68 + k];
            float4 w0  = *(const float4*)(ws + k*ACT);
            float4 w1v = *(const float4*)(ws + k*ACT + 4);
            acc[0] = fmaf(x, w0.x, acc[0]);
            acc[1] = fmaf(x, w0.y, acc[1]);
            acc[2] = fmaf(x, w0.z, acc[2]);
            acc[3] = fmaf(x, w0.w, acc[3]);
            acc[4] = fmaf(x, w1v.x, acc[4]);
            acc[5] = fmaf(x, w1v.y, acc[5]);
            acc[6] = fmaf(x, w1v.z, acc[6]);
            acc[7] = fmaf(x, w1v.w, acc[7]);
        }
        float best = acc[0] + b3s[0];
        int bi = 0;
        #pragma unroll
        for (int c = 1; c < 8; c++) {
            float q = acc[c] + b3s[c];
            if (q > best) { best = q; bi = c; }
        }
        g_qs[(size_t)(b0 + r) * AGENTS + a]        = best;
        actions_out[(size_t)(b0 + r) * AGENTS + a] = (float)bi;
    }
}

// =============================================================================
// Conversion: states -> hi/lo bf16 row-major (elementwise, coalesced)
// =============================================================================
__global__ void __launch_bounds__(256) conv_S_kernel(const float* __restrict__ S)
{
    const size_t id = (size_t)blockIdx.x * 256 + threadIdx.x;   // one per 8 elems
    const float4* src = (const float4*)(S + id * 8);
    float4 v0 = src[0], v1 = src[1];
    float x[8] = {v0.x, v0.y, v0.z, v0.w, v1.x, v1.y, v1.z, v1.w};
    uint32_t hw[4], lw[4];
    #pragma unroll
    for (int p = 0; p < 4; p++) {
        __nv_bfloat16 h0 = __float2bfloat16(x[p*2]);
        __nv_bfloat16 h1 = __float2bfloat16(x[p*2+1]);
        __nv_bfloat16 l0 = __float2bfloat16(x[p*2]   - __bfloat162float(h0));
        __nv_bfloat16 l1 = __float2bfloat16(x[p*2+1] - __bfloat162float(h1));
        hw[p] = (uint32_t)__bfloat16_as_ushort(h0) | ((uint32_t)__bfloat16_as_ushort(h1) << 16);
        lw[p] = (uint32_t)__bfloat16_as_ushort(l0) | ((uint32_t)__bfloat16_as_ushort(l1) << 16);
    }
    ((uint4*)g_Shi)[id] = make_uint4(hw[0], hw[1], hw[2], hw[3]);
    ((uint4*)g_Slo)[id] = make_uint4(lw[0], lw[1], lw[2], lw[3]);
}

// =============================================================================
// Conversion + transpose: Wh1[k][n] -> B[n][k] hi/lo bf16 (64x64 smem tiles)
// =============================================================================
__global__ void __launch_bounds__(256) conv_W_kernel(const float* __restrict__ Wh1)
{
    __shared__ float tile[64][65];
    const int kt = blockIdx.x & 63;
    const int nt = blockIdx.x >> 6;
    const int tid = threadIdx.x;

    #pragma unroll
    for (int p = 0; p < 16; p++) {
        int idx = p * 256 + tid;
        int r = idx >> 6, c = idx & 63;      // r = k, c = n
        tile[r][c] = Wh1[(size_t)(kt*64 + r) * SD + nt*64 + c];
    }
    __syncthreads();

    #pragma unroll
    for (int p = 0; p < 2; p++) {
        int id = p * 256 + tid;
        int n = id >> 3, kc = id & 7;
        uint32_t hw[4], lw[4];
        #pragma unroll
        for (int q = 0; q < 4; q++) {
            float x0 = tile[kc*8 + q*2][n];
            float x1 = tile[kc*8 + q*2 + 1][n];
            __nv_bfloat16 h0 = __float2bfloat16(x0);
            __nv_bfloat16 h1 = __float2bfloat16(x1);
            __nv_bfloat16 l0 = __float2bfloat16(x0 - __bfloat162float(h0));
            __nv_bfloat16 l1 = __float2bfloat16(x1 - __bfloat162float(h1));
            hw[q] = (uint32_t)__bfloat16_as_ushort(h0) | ((uint32_t)__bfloat16_as_ushort(h1) << 16);
            lw[q] = (uint32_t)__bfloat16_as_ushort(l0) | ((uint32_t)__bfloat16_as_ushort(l1) << 16);
        }
        size_t off = ((size_t)(nt*64 + n) * SD + kt*64 + kc*8) / 8;
        ((uint4*)g_Bhi)[off] = make_uint4(hw[0], hw[1], hw[2], hw[3]);
        ((uint4*)g_Blo)[off] = make_uint4(lw[0], lw[1], lw[2], lw[3]);
    }
}

// =============================================================================
// mma.sync bf16 3-split GEMM (R7 version). 128x128 tile, BK=32, 4-stage
// cp.async, one __syncthreads per K-iter. Epilogue folds qs*|acc+bh1| and
// writes agent-reduced partials to g_part.
// =============================================================================
#define GSTAGES 4
#define OP_BYTES 10240
#define STAGE_BYTES (4 * OP_BYTES)
#define GEMM_SMEM (GSTAGES * STAGE_BYTES)
#define NKT (SD / 32)

__global__ void __launch_bounds__(256) hyper_gemm_mma(const float* __restrict__ bh1)
{
    extern __shared__ char gsm[];
    __shared__ float sbias[128];

    const int tid = threadIdx.x;
    const int wid = tid >> 5, lane = tid & 31;
    const int warpM = wid & 3, warpN = wid >> 2;
    const int bx = blockIdx.x >> 5;    // N tile
    const int by = blockIdx.x & 31;    // M tile

    const uint32_t sbase = smem_u32(gsm);

    if (tid < 128) sbias[tid] = bh1[bx*128 + tid];

    const char* Ahi_g = (const char*)(g_Shi + (size_t)(by*128) * SD);
    const char* Alo_g = (const char*)(g_Slo + (size_t)(by*128) * SD);
    const char* Bhi_g = (const char*)(g_Bhi + (size_t)(bx*128) * SD);
    const char* Blo_g = (const char*)(g_Blo + (size_t)(bx*128) * SD);

    const int id0 = tid, id1 = tid + 256;
    const int m0 = id0 >> 2, c0 = id0 & 3;
    const int m1 = id1 >> 2, c1 = id1 & 3;
    const uint32_t s_off0 = (uint32_t)(m0*5 + c0) * 16;
    const uint32_t s_off1 = (uint32_t)(m1*5 + c1) * 16;

    #define ISSUE_STAGE(stg, kt_) do { \
        const uint32_t sb_ = sbase + (stg) * STAGE_BYTES; \
        const size_t g0_ = ((size_t)m0 * SD + (size_t)(kt_)*32 + c0*8) * 2; \
        const size_t g1_ = ((size_t)m1 * SD + (size_t)(kt_)*32 + c1*8) * 2; \
        cp16(sb_ + 0*OP_BYTES + s_off0, Ahi_g + g0_); \
        cp16(sb_ + 0*OP_BYTES + s_off1, Ahi_g + g1_); \
        cp16(sb_ + 1*OP_BYTES + s_off0, Alo_g + g0_); \
        cp16(sb_ + 1*OP_BYTES + s_off1, Alo_g + g1_); \
        cp16(sb_ + 2*OP_BYTES + s_off0, Bhi_g + g0_); \
        cp16(sb_ + 2*OP_BYTES + s_off1, Bhi_g + g1_); \
        cp16(sb_ + 3*OP_BYTES + s_off0, Blo_g + g0_); \
        cp16(sb_ + 3*OP_BYTES + s_off1, Blo_g + g1_); \
        CP_COMMIT(); \
    } while (0)

    uint32_t offA[2][2], offB[4][2];
    {
        const int am = warpM*32 + (lane & 7) + ((lane >> 3) & 1) * 8;
        #pragma unroll
        for (int mt = 0; mt < 2; mt++)
            #pragma unroll
            for (int ks = 0; ks < 2; ks++)
                offA[mt][ks] = (uint32_t)((am + mt*16)*5 + ks*2 + (lane >> 4)) * 16;
        const int bn = warpN*64 + (lane & 7) + ((lane >> 4) & 1) * 8;
        #pragma unroll
        for (int ntp = 0; ntp < 4; ntp++)
            #pragma unroll
            for (int ks = 0; ks < 2; ks++)
                offB[ntp][ks] = (uint32_t)((bn + ntp*16)*5 + ks*2 + ((lane >> 3) & 1)) * 16;
    }

    float acc[2][8][4];
    #pragma unroll
    for (int mt = 0; mt < 2; mt++)
        #pragma unroll
        for (int nt = 0; nt < 8; nt++)
            #pragma unroll
            for (int q = 0; q < 4; q++) acc[mt][nt][q] = 0.f;

    // prologue: stages 0..2
    ISSUE_STAGE(0, 0);
    ISSUE_STAGE(1, 1);
    ISSUE_STAGE(2, 2);

    for (int kt = 0; kt < NKT; kt++) {
        CP_WAIT2();
        __syncthreads();

        if (kt + 3 < NKT) ISSUE_STAGE((kt + 3) & 3, kt + 3);

        const uint32_t stg = sbase + (kt & 3) * STAGE_BYTES;
        const uint32_t aHi = stg + 0*OP_BYTES, aLo = stg + 1*OP_BYTES;
        const uint32_t bHi = stg + 2*OP_BYTES, bLo = stg + 3*OP_BYTES;

        #pragma unroll
        for (int ks = 0; ks < 2; ks++) {
            uint32_t ah[2][4], al[2][4], bh[8][2], bl[8][2];
            #pragma unroll
            for (int mt = 0; mt < 2; mt++) {
                ldm4(ah[mt], aHi + offA[mt][ks]);
                ldm4(al[mt], aLo + offA[mt][ks]);
            }
            #pragma unroll
            for (int ntp = 0; ntp < 4; ntp++) {
                uint32_t r[4];
                ldm4(r, bHi + offB[ntp][ks]);
                bh[2*ntp][0] = r[0]; bh[2*ntp][1] = r[1];
                bh[2*ntp+1][0] = r[2]; bh[2*ntp+1][1] = r[3];
                ldm4(r, bLo + offB[ntp][ks]);
                bl[2*ntp][0] = r[0]; bl[2*ntp][1] = r[1];
                bl[2*ntp+1][0] = r[2]; bl[2*ntp+1][1] = r[3];
            }
            #pragma unroll
            for (int mt = 0; mt < 2; mt++)
                #pragma unroll
                for (int nt = 0; nt < 8; nt++) {
                    mma_bf16(acc[mt][nt], ah[mt], bh[nt]);
                    mma_bf16(acc[mt][nt], al[mt], bh[nt]);
                    mma_bf16(acc[mt][nt], ah[mt], bl[nt]);
                }
        }
    }

    // --------- epilogue: fold qs * |acc + bias|, reduce agents, store ---------
    const int slab = bx*2 + warpN;
    #pragma unroll
    for (int mt = 0; mt < 2; mt++) {
        #pragma unroll
        for (int rr = 0; rr < 2; rr++) {
            const int row = by*128 + warpM*32 + mt*16 + (lane >> 2) + rr*8;
            const float qv0 = g_qs[(size_t)row * AGENTS + bx*4 + warpN*2];
            const float qv1 = g_qs[(size_t)row * AGENTS + bx*4 + warpN*2 + 1];
            float part[8];
            #pragma unroll
            for (int s = 0; s < 8; s++) part[s] = 0.f;
            #pragma unroll
            for (int nt = 0; nt < 8; nt++) {
                const float qv = (nt < 4) ? qv0 : qv1;
                #pragma unroll
                for (int j = 0; j < 2; j++) {
                    const int col = warpN*64 + nt*8 + (lane & 3)*2 + j;
                    float v = acc[mt][nt][rr*2 + j] + sbias[col];
                    part[(nt & 3)*2 + j] = fmaf(qv, fabsf(v), part[(nt & 3)*2 + j]);
                }
            }
            float* dst = g_part + ((size_t)slab * BS + row) * EMB;
            #pragma unroll
            for (int k4 = 0; k4 < 4; k4++) {
                const int e = k4*8 + (lane & 3)*2;
                *(float2*)(dst + e) = make_float2(part[k4*2], part[k4*2 + 1]);
            }
        }
    }
}

// =============================================================================
// Skinny hypernet GEMMs, K-split by HKS. (R7 version)
// =============================================================================
__global__ void __launch_bounds__(256) hyper_small_kernel(
    const float* __restrict__ S,
    const float* __restrict__ Whb,
    const float* __restrict__ Whf,
    const float* __restrict__ Wv1)
{
    __shared__ __align__(16) float ss[64][36];
    __shared__ __align__(16) float wbs[64][32];
    __shared__ __align__(16) float wfs[64][32];
    __shared__ __align__(16) float wvs[64][32];

    const int b0  = blockIdx.x * 32;
    const int kz  = blockIdx.y;
    const int kbeg = kz * (SD / HKS);
    const int tid = threadIdx.x;
    const int e   = tid & 31;
    const int rg  = tid >> 5;

    float ab[4] = {0,0,0,0}, af[4] = {0,0,0,0}, av[4] = {0,0,0,0};

    for (int kc = 0; kc < SD/HKS; kc += 64) {
        const int k0 = kbeg + kc;
        __syncthreads();
        for (int i = tid; i < 512; i += 256) {
            int r = i >> 4, c4 = (i & 15) * 4;
            float4 v = *(const float4*)(S + (size_t)(b0 + r) * SD + k0 + c4);
            ss[c4+0][r] = v.x; ss[c4+1][r] = v.y; ss[c4+2][r] = v.z; ss[c4+3][r] = v.w;
        }
        for (int i = tid; i < 512; i += 256) {
            int kk = i >> 3, c = (i & 7) * 4;
            *(float4*)&wbs[kk][c] = *(const float4*)(Whb + (size_t)(k0+kk)*EMB + c);
            *(float4*)&wfs[kk][c] = *(const float4*)(Whf + (size_t)(k0+kk)*EMB + c);
            *(float4*)&wvs[kk][c] = *(const float4*)(Wv1 + (size_t)(k0+kk)*EMB + c);
        }
        __syncthreads();
        #pragma unroll 4
        for (int k = 0; k < 64; k++) {
            float wb = wbs[k][e], wf = wfs[k][e], wv = wvs[k][e];
            #pragma unroll
            for (int i = 0; i < 4; i++) {
                float s = ss[k][rg*4 + i];
                ab[i] = fmaf(s, wb, ab[i]);
                af[i] = fmaf(s, wf, af[i]);
                av[i] = fmaf(s, wv, av[i]);
            }
        }
    }
    #pragma unroll
    for (int i = 0; i < 4; i++) {
        int b = b0 + rg*4 + i;
        float* dst = g_hsp + ((size_t)kz * BS + b) * 96;
        dst[e]      = ab[i];
        dst[32 + e] = af[i];
        dst[64 + e] = av[i];
    }
}

// =============================================================================
// Final mixing (R7 version): reduce hyper_small K-slices (+bias/abs/relu),
// reduce GEMM slabs, elu, dot with w_final + V.
// =============================================================================
__global__ void __launch_bounds__(128) final_kernel(
    const float* __restrict__ bhb, const float* __restrict__ bhf,
    const float* __restrict__ bv1,
    const float* __restrict__ Wv2, const float* __restrict__ bv2,
    float* __restrict__ qtot)
{
    const int b = blockIdx.x * 4 + (threadIdx.x >> 5);
    const int e = threadIdx.x & 31;

    float sb = 0.f, wf = 0.f, rv = 0.f;
    #pragma unroll
    for (int kz = 0; kz < HKS; kz++) {
        const float* src = g_hsp + ((size_t)kz * BS + b) * 96;
        sb += src[e];
        wf += src[32 + e];
        rv += src[64 + e];
    }
    sb += bhb[e];
    wf = fabsf(wf + bhf[e]);
    rv += bv1[e];
    rv = rv > 0.f ? rv : 0.f;

    float s = 0.f;
    #pragma unroll
    for (int sl = 0; sl < 64; sl++)
        s += g_part[((size_t)sl * BS + b) * EMB + e];
    float hp = s + sb;
    float hidden = hp > 0.f ? hp : expm1f(hp);
    float contrib = hidden * wf + rv * Wv2[e];
    #pragma unroll
    for (int o = 16; o > 0; o >>= 1)
        contrib += __shfl_down_sync(0xffffffffu, contrib, o);
    if (e == 0) qtot[b] = contrib + bv2[0];
}

// =============================================================================
extern "C" void kernel_launch(void* const* d_in, const int* in_sizes, int n_in,
                              void* d_out, int out_size)
{
    const float* obs    = (const float*)d_in[0];
    const float* states = (const float*)d_in[1];
    const float* W1  = (const float*)d_in[2];
    const float* b1  = (const float*)d_in[3];
    const float* W2  = (const float*)d_in[4];
    const float* b2  = (const float*)d_in[5];
    const float* W3  = (const float*)d_in[6];
    const float* b3  = (const float*)d_in[7];
    const float* Wh1 = (const float*)d_in[8];
    const float* bh1 = (const float*)d_in[9];
    const float* Whb = (const float*)d_in[10];
    const float* bhb = (const float*)d_in[11];
    const float* Whf = (const float*)d_in[12];
    const float* bhf = (const float*)d_in[13];
    const float* Wv1 = (const float*)d_in[14];
    const float* bv1 = (const float*)d_in[15];
    const float* Wv2 = (const float*)d_in[16];
    const float* bv2 = (const float*)d_in[17];
    float* out = (float*)d_out;

    cudaFuncSetAttribute(mlp_kernel, cudaFuncAttributeMaxDynamicSharedMemorySize, MLP_SMEM);
    cudaFuncSetAttribute(hyper_gemm_mma, cudaFuncAttributeMaxDynamicSharedMemorySize, GEMM_SMEM);

    float* act_dst;
    if (out_size >= (int)(BS + BS*AGENTS)) {
        act_dst = out + BS;
    } else {
        void* p = 0;
        cudaGetSymbolAddress(&p, g_act_fallback);
        act_dst = (float*)p;
    }

    // One-time creation of side stream + events (first call = correctness run,
    // not captured; capture replays reuse the same handles).
    static cudaStream_t sB = 0;
    static cudaEvent_t evFork = 0, evConv = 0, evMLP = 0, evHS = 0;
    if (sB == 0) {
        cudaStreamCreateWithFlags(&sB, cudaStreamNonBlocking);
        cudaEventCreateWithFlags(&evFork, cudaEventDisableTiming);
        cudaEventCreateWithFlags(&evConv, cudaEventDisableTiming);
        cudaEventCreateWithFlags(&evMLP,  cudaEventDisableTiming);
        cudaEventCreateWithFlags(&evHS,   cudaEventDisableTiming);
    }

    if (sB != 0) {
        // fork
        cudaEventRecord(evFork, 0);
        cudaStreamWaitEvent(sB, evFork, 0);

        // side stream: DRAM-bound conversions overlap the compute-bound MLP
        conv_S_kernel<<<BS*SD/8/256, 256, 0, sB>>>(states);
        conv_W_kernel<<<4096, 256, 0, sB>>>(Wh1);
        cudaEventRecord(evConv, sB);

        // main stream: MLP (produces g_qs needed by GEMM epilogue)
        mlp_kernel<<<dim3(AGENTS, BS/MLP_BT), 512, MLP_SMEM>>>(
            obs, W1, b1, W2, b2, W3, b3, act_dst);
        cudaEventRecord(evMLP, 0);

        // side stream: hyper_small co-runs with the GEMM (34KB smem fits
        // beside the GEMM's 160KB; FFMA vs tensor pipes)
        cudaStreamWaitEvent(sB, evMLP, 0);
        hyper_small_kernel<<<dim3(BS/32, HKS), 256, 0, sB>>>(states, Whb, Whf, Wv1);
        cudaEventRecord(evHS, sB);

        // main stream: GEMM after conversions (and MLP, same stream)
        cudaStreamWaitEvent(0, evConv, 0);
        hyper_gemm_mma<<<1024, 256, GEMM_SMEM>>>(bh1);

        // join, then final mixing
        cudaStreamWaitEvent(0, evHS, 0);
        final_kernel<<<BS/4, 128>>>(bhb, bhf, bv1, Wv2, bv2, out);
    } else {
        // fallback: fully sequential (R7 order)
        mlp_kernel<<<dim3(AGENTS, BS/MLP_BT), 512, MLP_SMEM>>>(
            obs, W1, b1, W2, b2, W3, b3, act_dst);
        conv_S_kernel<<<BS*SD/8/256, 256>>>(states);
        conv_W_kernel<<<4096, 256>>>(Wh1);
        hyper_small_kernel<<<dim3(BS/32, HKS), 256>>>(states, Whb, Whf, Wv1);
        hyper_gemm_mma<<<1024, 256, GEMM_SMEM>>>(bh1);
        final_kernel<<<BS/4, 128>>>(bhb, bhf, bv1, Wv2, bv2, out);
    }
}

// round 10
// speedup vs baseline: 1.7692x; 1.7692x over previous
#include <cuda_runtime.h>
#include <cuda_fp16.h>
#include <stdint.h>
#include <math.h>

#define BS 4096
#define AGENTS 128
#define OBSD 128
#define ACT 8
#define SD 4096
#define EMB 32
#define H1 128
#define H2 64

// ---------------- scratch (static device globals; no allocation) ----------------
__device__ float g_qs[(size_t)BS * AGENTS];           // agent_qs [b][a]
__device__ float g_act_fallback[(size_t)BS * AGENTS];
__device__ float g_part[(size_t)64 * BS * EMB];       // GEMM partial sums [slab][b][e] 32MB
#define HKS 8
__device__ float g_hsp[(size_t)HKS * BS * 96];        // hyper_small partials [kz][b][96]

// fp16 operands, plain row-major
__device__ __half g_Shi[(size_t)BS * SD];             // A hi  [m][k]
__device__ __half g_Slo[(size_t)BS * SD];             // A lo  (fp16 residual)
__device__ __half g_B[(size_t)SD * SD];               // B     [n][k] = Wh1[k][n], single fp16

// ============================ PTX helpers =====================================
__device__ __forceinline__ uint32_t smem_u32(const void* p) {
    uint32_t a;
    asm("{ .reg .u64 t; cvta.to.shared.u64 t, %1; cvt.u32.u64 %0, t; }" : "=r"(a) : "l"(p));
    return a;
}

__device__ __forceinline__ void cp16(uint32_t s, const void* g) {
    asm volatile("cp.async.cg.shared.global [%0], [%1], 16;" :: "r"(s), "l"(g));
}
#define CP_COMMIT() asm volatile("cp.async.commit_group;")
#define CP_WAIT2()  asm volatile("cp.async.wait_group 2;")

__device__ __forceinline__ void ldm4(uint32_t* r, uint32_t addr) {
    asm volatile("ldmatrix.sync.aligned.m8n8.x4.shared.b16 {%0,%1,%2,%3}, [%4];"
        : "=r"(r[0]), "=r"(r[1]), "=r"(r[2]), "=r"(r[3]) : "r"(addr));
}

__device__ __forceinline__ void mma_fp16(float* c, const uint32_t* a, const uint32_t* b) {
    asm volatile("mma.sync.aligned.m16n8k16.row.col.f32.f16.f16.f32 "
        "{%0,%1,%2,%3}, {%4,%5,%6,%7}, {%8,%9}, {%0,%1,%2,%3};"
        : "+f"(c[0]), "+f"(c[1]), "+f"(c[2]), "+f"(c[3])
        : "r"(a[0]), "r"(a[1]), "r"(a[2]), "r"(a[3]), "r"(b[0]), "r"(b[1]));
}

// =============================================================================
// Kernel 1: fused per-agent 3-layer MLP + max/argmax. 512 threads. (R7 version)
// =============================================================================
#define MLP_BT 64
#define MLP_SMEM ((64*132 + 64*68 + 64*132 + 128*128) * 4)

__global__ void __launch_bounds__(512) mlp_kernel(
    const float* __restrict__ obs,
    const float* __restrict__ W1, const float* __restrict__ b1,
    const float* __restrict__ W2, const float* __restrict__ b2,
    const float* __restrict__ W3, const float* __restrict__ b3,
    float* __restrict__ actions_out)
{
    extern __shared__ float sm[];
    float* x1s  = sm;                       // [64][132]
    float* x2s  = sm + 64*132;              // [64][68]
    float* obss = sm + 64*132 + 64*68;      // [64][132]
    float* ws   = sm + 64*132 + 64*68 + 64*132;  // up to [128][128]
    __shared__ float b1s[H1];
    __shared__ float b2s[H2];
    __shared__ float b3s[ACT];

    const int a   = blockIdx.x;
    const int b0  = blockIdx.y * MLP_BT;
    const int tid = threadIdx.x;

    if (tid < H1) b1s[tid] = b1[a*H1 + tid];
    if (tid < H2) b2s[tid] = b2[a*H2 + tid];
    if (tid < ACT) b3s[tid] = b3[a*ACT + tid];

    {
        const float4* w1g = (const float4*)(W1 + (size_t)a * OBSD * H1);
        float4* wd = (float4*)ws;
        for (int i = tid; i < OBSD*H1/4; i += 512) wd[i] = w1g[i];
    }
    for (int i = tid; i < MLP_BT * (OBSD/4); i += 512) {
        int r  = i >> 5;
        int c4 = i & 31;
        float4 v = ((const float4*)(obs + ((size_t)(b0 + r) * AGENTS + a) * OBSD))[c4];
        *(float4*)(obss + r*132 + c4*4) = v;
    }
    __syncthreads();

    // layer 1
    {
        const int ty = tid >> 5, tx = tid & 31;
        float acc[4][4];
        #pragma unroll
        for (int i = 0; i < 4; i++)
            #pragma unroll
            for (int j = 0; j < 4; j++) acc[i][j] = 0.f;

        #pragma unroll 4
        for (int k = 0; k < OBSD; k++) {
            float a0 = obss[(ty*4+0)*132 + k];
            float a1 = obss[(ty*4+1)*132 + k];
            float a2 = obss[(ty*4+2)*132 + k];
            float a3 = obss[(ty*4+3)*132 + k];
            float4 w = *(const float4*)(ws + k*H1 + tx*4);
            float wv[4] = {w.x, w.y, w.z, w.w};
            #pragma unroll
            for (int j = 0; j < 4; j++) {
                acc[0][j] = fmaf(a0, wv[j], acc[0][j]);
                acc[1][j] = fmaf(a1, wv[j], acc[1][j]);
                acc[2][j] = fmaf(a2, wv[j], acc[2][j]);
                acc[3][j] = fmaf(a3, wv[j], acc[3][j]);
            }
        }
        #pragma unroll
        for (int i = 0; i < 4; i++) {
            float4 o;
            float* ov = (float*)&o;
            #pragma unroll
            for (int j = 0; j < 4; j++) {
                float v = acc[i][j] + b1s[tx*4 + j];
                ov[j] = v > 0.f ? v : 0.f;
            }
            *(float4*)(x1s + (ty*4+i)*132 + tx*4) = o;
        }
    }
    __syncthreads();

    {
        const float4* w2g = (const float4*)(W2 + (size_t)a * H1 * H2);
        float4* wd = (float4*)ws;
        for (int i = tid; i < H1*H2/4; i += 512) wd[i] = w2g[i];
    }
    __syncthreads();

    // layer 2
    {
        const int ry = tid >> 4, tx = tid & 15;
        float acc[2][4];
        #pragma unroll
        for (int i = 0; i < 2; i++)
            #pragma unroll
            for (int j = 0; j < 4; j++) acc[i][j] = 0.f;

        #pragma unroll 4
        for (int k = 0; k < H1; k++) {
            float a0 = x1s[(ry*2+0)*132 + k];
            float a1 = x1s[(ry*2+1)*132 + k];
            float4 w = *(const float4*)(ws + k*H2 + tx*4);
            float wv[4] = {w.x, w.y, w.z, w.w};
            #pragma unroll
            for (int j = 0; j < 4; j++) {
                acc[0][j] = fmaf(a0, wv[j], acc[0][j]);
                acc[1][j] = fmaf(a1, wv[j], acc[1][j]);
            }
        }
        #pragma unroll
        for (int i = 0; i < 2; i++) {
            float4 o;
            float* ov = (float*)&o;
            #pragma unroll
            for (int j = 0; j < 4; j++) {
                float v = acc[i][j] + b2s[tx*4 + j];
                ov[j] = v > 0.f ? v : 0.f;
            }
            *(float4*)(x2s + (ry*2+i)*68 + tx*4) = o;
        }
    }
    __syncthreads();

    {
        const float4* w3g = (const float4*)(W3 + (size_t)a * H2 * ACT);
        float4* wd = (float4*)ws;
        for (int i = tid; i < H2*ACT/4; i += 512) wd[i] = w3g[i];
    }
    __syncthreads();

    // layer 3 + argmax
    if (tid < MLP_BT) {
        const int r = tid;
        float acc[8];
        #pragma unroll
        for (int c = 0; c < 8; c++) acc[c] = 0.f;
        #pragma unroll 4
        for (int k = 0; k < H2; k++) {
            float x = x2s[r*68 + k];
            float4 w0  = *(const float4*)(ws + k*ACT);
            float4 w1v = *(const float4*)(ws + k*ACT + 4);
            acc[0] = fmaf(x, w0.x, acc[0]);
            acc[1] = fmaf(x, w0.y, acc[1]);
            acc[2] = fmaf(x, w0.z, acc[2]);
            acc[3] = fmaf(x, w0.w, acc[3]);
            acc[4] = fmaf(x, w1v.x, acc[4]);
            acc[5] = fmaf(x, w1v.y, acc[5]);
            acc[6] = fmaf(x, w1v.z, acc[6]);
            acc[7] = fmaf(x, w1v.w, acc[7]);
        }
        float best = acc[0] + b3s[0];
        int bi = 0;
        #pragma unroll
        for (int c = 1; c < 8; c++) {
            float q = acc[c] + b3s[c];
            if (q > best) { best = q; bi = c; }
        }
        g_qs[(size_t)(b0 + r) * AGENTS + a]        = best;
        actions_out[(size_t)(b0 + r) * AGENTS + a] = (float)bi;
    }
}

// =============================================================================
// Conversion: states -> hi/lo fp16 row-major (elementwise, coalesced)
// =============================================================================
__global__ void __launch_bounds__(256) conv_S_kernel(const float* __restrict__ S)
{
    const size_t id = (size_t)blockIdx.x * 256 + threadIdx.x;   // one per 8 elems
    const float4* src = (const float4*)(S + id * 8);
    float4 v0 = src[0], v1 = src[1];
    float x[8] = {v0.x, v0.y, v0.z, v0.w, v1.x, v1.y, v1.z, v1.w};
    uint32_t hw[4], lw[4];
    #pragma unroll
    for (int p = 0; p < 4; p++) {
        __half h0 = __float2half(x[p*2]);
        __half h1 = __float2half(x[p*2+1]);
        __half l0 = __float2half(x[p*2]   - __half2float(h0));
        __half l1 = __float2half(x[p*2+1] - __half2float(h1));
        hw[p] = (uint32_t)__half_as_ushort(h0) | ((uint32_t)__half_as_ushort(h1) << 16);
        lw[p] = (uint32_t)__half_as_ushort(l0) | ((uint32_t)__half_as_ushort(l1) << 16);
    }
    ((uint4*)g_Shi)[id] = make_uint4(hw[0], hw[1], hw[2], hw[3]);
    ((uint4*)g_Slo)[id] = make_uint4(lw[0], lw[1], lw[2], lw[3]);
}

// =============================================================================
// Conversion + transpose: Wh1[k][n] -> B[n][k] single fp16 (64x64 smem tiles)
// =============================================================================
__global__ void __launch_bounds__(256) conv_W_kernel(const float* __restrict__ Wh1)
{
    __shared__ float tile[64][65];
    const int kt = blockIdx.x & 63;
    const int nt = blockIdx.x >> 6;
    const int tid = threadIdx.x;

    #pragma unroll
    for (int p = 0; p < 16; p++) {
        int idx = p * 256 + tid;
        int r = idx >> 6, c = idx & 63;      // r = k, c = n
        tile[r][c] = Wh1[(size_t)(kt*64 + r) * SD + nt*64 + c];
    }
    __syncthreads();

    #pragma unroll
    for (int p = 0; p < 2; p++) {
        int id = p * 256 + tid;
        int n = id >> 3, kc = id & 7;
        uint32_t hw[4];
        #pragma unroll
        for (int q = 0; q < 4; q++) {
            __half h0 = __float2half(tile[kc*8 + q*2][n]);
            __half h1 = __float2half(tile[kc*8 + q*2 + 1][n]);
            hw[q] = (uint32_t)__half_as_ushort(h0) | ((uint32_t)__half_as_ushort(h1) << 16);
        }
        size_t off = ((size_t)(nt*64 + n) * SD + kt*64 + kc*8) / 8;
        ((uint4*)g_B)[off] = make_uint4(hw[0], hw[1], hw[2], hw[3]);
    }
}

// =============================================================================
// mma.sync fp16 2-pass GEMM: C = (Ahi + Alo) @ B, A fp16 2-term split,
// B single fp16. 128x128 tile, BK=32, 4-stage cp.async (3 operands/stage),
// one __syncthreads per K-iter. Epilogue folds qs*|acc+bh1| into g_part.
// =============================================================================
#define GSTAGES 4
#define OP_BYTES 10240
#define STAGE_BYTES (3 * OP_BYTES)
#define GEMM_SMEM (GSTAGES * STAGE_BYTES)
#define NKT (SD / 32)

__global__ void __launch_bounds__(256) hyper_gemm_mma(const float* __restrict__ bh1)
{
    extern __shared__ char gsm[];
    __shared__ float sbias[128];

    const int tid = threadIdx.x;
    const int wid = tid >> 5, lane = tid & 31;
    const int warpM = wid & 3, warpN = wid >> 2;
    const int bx = blockIdx.x >> 5;    // N tile
    const int by = blockIdx.x & 31;    // M tile

    const uint32_t sbase = smem_u32(gsm);

    if (tid < 128) sbias[tid] = bh1[bx*128 + tid];

    const char* Ahi_g = (const char*)(g_Shi + (size_t)(by*128) * SD);
    const char* Alo_g = (const char*)(g_Slo + (size_t)(by*128) * SD);
    const char* B_g   = (const char*)(g_B   + (size_t)(bx*128) * SD);

    const int id0 = tid, id1 = tid + 256;
    const int m0 = id0 >> 2, c0 = id0 & 3;
    const int m1 = id1 >> 2, c1 = id1 & 3;
    const uint32_t s_off0 = (uint32_t)(m0*5 + c0) * 16;
    const uint32_t s_off1 = (uint32_t)(m1*5 + c1) * 16;

    #define ISSUE_STAGE(stg, kt_) do { \
        const uint32_t sb_ = sbase + (stg) * STAGE_BYTES; \
        const size_t g0_ = ((size_t)m0 * SD + (size_t)(kt_)*32 + c0*8) * 2; \
        const size_t g1_ = ((size_t)m1 * SD + (size_t)(kt_)*32 + c1*8) * 2; \
        cp16(sb_ + 0*OP_BYTES + s_off0, Ahi_g + g0_); \
        cp16(sb_ + 0*OP_BYTES + s_off1, Ahi_g + g1_); \
        cp16(sb_ + 1*OP_BYTES + s_off0, Alo_g + g0_); \
        cp16(sb_ + 1*OP_BYTES + s_off1, Alo_g + g1_); \
        cp16(sb_ + 2*OP_BYTES + s_off0, B_g + g0_); \
        cp16(sb_ + 2*OP_BYTES + s_off1, B_g + g1_); \
        CP_COMMIT(); \
    } while (0)

    uint32_t offA[2][2], offB[4][2];
    {
        const int am = warpM*32 + (lane & 7) + ((lane >> 3) & 1) * 8;
        #pragma unroll
        for (int mt = 0; mt < 2; mt++)
            #pragma unroll
            for (int ks = 0; ks < 2; ks++)
                offA[mt][ks] = (uint32_t)((am + mt*16)*5 + ks*2 + (lane >> 4)) * 16;
        const int bn = warpN*64 + (lane & 7) + ((lane >> 4) & 1) * 8;
        #pragma unroll
        for (int ntp = 0; ntp < 4; ntp++)
            #pragma unroll
            for (int ks = 0; ks < 2; ks++)
                offB[ntp][ks] = (uint32_t)((bn + ntp*16)*5 + ks*2 + ((lane >> 3) & 1)) * 16;
    }

    float acc[2][8][4];
    #pragma unroll
    for (int mt = 0; mt < 2; mt++)
        #pragma unroll
        for (int nt = 0; nt < 8; nt++)
            #pragma unroll
            for (int q = 0; q < 4; q++) acc[mt][nt][q] = 0.f;

    // prologue: stages 0..2
    ISSUE_STAGE(0, 0);
    ISSUE_STAGE(1, 1);
    ISSUE_STAGE(2, 2);

    for (int kt = 0; kt < NKT; kt++) {
        CP_WAIT2();
        __syncthreads();

        if (kt + 3 < NKT) ISSUE_STAGE((kt + 3) & 3, kt + 3);

        const uint32_t stg = sbase + (kt & 3) * STAGE_BYTES;
        const uint32_t aHi = stg + 0*OP_BYTES, aLo = stg + 1*OP_BYTES;
        const uint32_t bOp = stg + 2*OP_BYTES;

        #pragma unroll
        for (int ks = 0; ks < 2; ks++) {
            uint32_t ah[2][4], al[2][4], bb[8][2];
            #pragma unroll
            for (int mt = 0; mt < 2; mt++) {
                ldm4(ah[mt], aHi + offA[mt][ks]);
                ldm4(al[mt], aLo + offA[mt][ks]);
            }
            #pragma unroll
            for (int ntp = 0; ntp < 4; ntp++) {
                uint32_t r[4];
                ldm4(r, bOp + offB[ntp][ks]);
                bb[2*ntp][0] = r[0]; bb[2*ntp][1] = r[1];
                bb[2*ntp+1][0] = r[2]; bb[2*ntp+1][1] = r[3];
            }
            #pragma unroll
            for (int mt = 0; mt < 2; mt++)
                #pragma unroll
                for (int nt = 0; nt < 8; nt++) {
                    mma_fp16(acc[mt][nt], ah[mt], bb[nt]);
                    mma_fp16(acc[mt][nt], al[mt], bb[nt]);
                }
        }
    }

    // --------- epilogue: fold qs * |acc + bias|, reduce agents, store ---------
    const int slab = bx*2 + warpN;
    #pragma unroll
    for (int mt = 0; mt < 2; mt++) {
        #pragma unroll
        for (int rr = 0; rr < 2; rr++) {
            const int row = by*128 + warpM*32 + mt*16 + (lane >> 2) + rr*8;
            const float qv0 = g_qs[(size_t)row * AGENTS + bx*4 + warpN*2];
            const float qv1 = g_qs[(size_t)row * AGENTS + bx*4 + warpN*2 + 1];
            float part[8];
            #pragma unroll
            for (int s = 0; s < 8; s++) part[s] = 0.f;
            #pragma unroll
            for (int nt = 0; nt < 8; nt++) {
                const float qv = (nt < 4) ? qv0 : qv1;
                #pragma unroll
                for (int j = 0; j < 2; j++) {
                    const int col = warpN*64 + nt*8 + (lane & 3)*2 + j;
                    float v = acc[mt][nt][rr*2 + j] + sbias[col];
                    part[(nt & 3)*2 + j] = fmaf(qv, fabsf(v), part[(nt & 3)*2 + j]);
                }
            }
            float* dst = g_part + ((size_t)slab * BS + row) * EMB;
            #pragma unroll
            for (int k4 = 0; k4 < 4; k4++) {
                const int e = k4*8 + (lane & 3)*2;
                *(float2*)(dst + e) = make_float2(part[k4*2], part[k4*2 + 1]);
            }
        }
    }
}

// =============================================================================
// Skinny hypernet GEMMs, K-split by HKS. (R7 version)
// =============================================================================
__global__ void __launch_bounds__(256) hyper_small_kernel(
    const float* __restrict__ S,
    const float* __restrict__ Whb,
    const float* __restrict__ Whf,
    const float* __restrict__ Wv1)
{
    __shared__ __align__(16) float ss[64][36];
    __shared__ __align__(16) float wbs[64][32];
    __shared__ __align__(16) float wfs[64][32];
    __shared__ __align__(16) float wvs[64][32];

    const int b0  = blockIdx.x * 32;
    const int kz  = blockIdx.y;
    const int kbeg = kz * (SD / HKS);
    const int tid = threadIdx.x;
    const int e   = tid & 31;
    const int rg  = tid >> 5;

    float ab[4] = {0,0,0,0}, af[4] = {0,0,0,0}, av[4] = {0,0,0,0};

    for (int kc = 0; kc < SD/HKS; kc += 64) {
        const int k0 = kbeg + kc;
        __syncthreads();
        for (int i = tid; i < 512; i += 256) {
            int r = i >> 4, c4 = (i & 15) * 4;
            float4 v = *(const float4*)(S + (size_t)(b0 + r) * SD + k0 + c4);
            ss[c4+0][r] = v.x; ss[c4+1][r] = v.y; ss[c4+2][r] = v.z; ss[c4+3][r] = v.w;
        }
        for (int i = tid; i < 512; i += 256) {
            int kk = i >> 3, c = (i & 7) * 4;
            *(float4*)&wbs[kk][c] = *(const float4*)(Whb + (size_t)(k0+kk)*EMB + c);
            *(float4*)&wfs[kk][c] = *(const float4*)(Whf + (size_t)(k0+kk)*EMB + c);
            *(float4*)&wvs[kk][c] = *(const float4*)(Wv1 + (size_t)(k0+kk)*EMB + c);
        }
        __syncthreads();
        #pragma unroll 4
        for (int k = 0; k < 64; k++) {
            float wb = wbs[k][e], wf = wfs[k][e], wv = wvs[k][e];
            #pragma unroll
            for (int i = 0; i < 4; i++) {
                float s = ss[k][rg*4 + i];
                ab[i] = fmaf(s, wb, ab[i]);
                af[i] = fmaf(s, wf, af[i]);
                av[i] = fmaf(s, wv, av[i]);
            }
        }
    }
    #pragma unroll
    for (int i = 0; i < 4; i++) {
        int b = b0 + rg*4 + i;
        float* dst = g_hsp + ((size_t)kz * BS + b) * 96;
        dst[e]      = ab[i];
        dst[32 + e] = af[i];
        dst[64 + e] = av[i];
    }
}

// =============================================================================
// Final mixing (R7 version): reduce hyper_small K-slices (+bias/abs/relu),
// reduce GEMM slabs, elu, dot with w_final + V.
// =============================================================================
__global__ void __launch_bounds__(128) final_kernel(
    const float* __restrict__ bhb, const float* __restrict__ bhf,
    const float* __restrict__ bv1,
    const float* __restrict__ Wv2, const float* __restrict__ bv2,
    float* __restrict__ qtot)
{
    const int b = blockIdx.x * 4 + (threadIdx.x >> 5);
    const int e = threadIdx.x & 31;

    float sb = 0.f, wf = 0.f, rv = 0.f;
    #pragma unroll
    for (int kz = 0; kz < HKS; kz++) {
        const float* src = g_hsp + ((size_t)kz * BS + b) * 96;
        sb += src[e];
        wf += src[32 + e];
        rv += src[64 + e];
    }
    sb += bhb[e];
    wf = fabsf(wf + bhf[e]);
    rv += bv1[e];
    rv = rv > 0.f ? rv : 0.f;

    float s = 0.f;
    #pragma unroll
    for (int sl = 0; sl < 64; sl++)
        s += g_part[((size_t)sl * BS + b) * EMB + e];
    float hp = s + sb;
    float hidden = hp > 0.f ? hp : expm1f(hp);
    float contrib = hidden * wf + rv * Wv2[e];
    #pragma unroll
    for (int o = 16; o > 0; o >>= 1)
        contrib += __shfl_down_sync(0xffffffffu, contrib, o);
    if (e == 0) qtot[b] = contrib + bv2[0];
}

// =============================================================================
extern "C" void kernel_launch(void* const* d_in, const int* in_sizes, int n_in,
                              void* d_out, int out_size)
{
    const float* obs    = (const float*)d_in[0];
    const float* states = (const float*)d_in[1];
    const float* W1  = (const float*)d_in[2];
    const float* b1  = (const float*)d_in[3];
    const float* W2  = (const float*)d_in[4];
    const float* b2  = (const float*)d_in[5];
    const float* W3  = (const float*)d_in[6];
    const float* b3  = (const float*)d_in[7];
    const float* Wh1 = (const float*)d_in[8];
    const float* bh1 = (const float*)d_in[9];
    const float* Whb = (const float*)d_in[10];
    const float* bhb = (const float*)d_in[11];
    const float* Whf = (const float*)d_in[12];
    const float* bhf = (const float*)d_in[13];
    const float* Wv1 = (const float*)d_in[14];
    const float* bv1 = (const float*)d_in[15];
    const float* Wv2 = (const float*)d_in[16];
    const float* bv2 = (const float*)d_in[17];
    float* out = (float*)d_out;

    cudaFuncSetAttribute(mlp_kernel, cudaFuncAttributeMaxDynamicSharedMemorySize, MLP_SMEM);
    cudaFuncSetAttribute(hyper_gemm_mma, cudaFuncAttributeMaxDynamicSharedMemorySize, GEMM_SMEM);

    float* act_dst;
    if (out_size >= (int)(BS + BS*AGENTS)) {
        act_dst = out + BS;
    } else {
        void* p = 0;
        cudaGetSymbolAddress(&p, g_act_fallback);
        act_dst = (float*)p;
    }

    // Strictly sequential, single stream: overlap attempts regressed twice
    // (L2 working-set pollution of the GEMM). R7 order.
    mlp_kernel<<<dim3(AGENTS, BS/MLP_BT), 512, MLP_SMEM>>>(
        obs, W1, b1, W2, b2, W3, b3, act_dst);
    conv_S_kernel<<<BS*SD/8/256, 256>>>(states);
    conv_W_kernel<<<4096, 256>>>(Wh1);
    hyper_small_kernel<<<dim3(BS/32, HKS), 256>>>(states, Whb, Whf, Wv1);
    hyper_gemm_mma<<<1024, 256, GEMM_SMEM>>>(bh1);
    final_kernel<<<BS/4, 128>>>(bhb, bhf, bv1, Wv2, bv2, out);
}

// round 11
// speedup vs baseline: 2.2473x; 1.2702x over previous
#include <cuda_runtime.h>
#include <cuda_fp16.h>
#include <stdint.h>
#include <math.h>

#define BS 4096
#define AGENTS 128
#define OBSD 128
#define ACT 8
#define SD 4096
#define EMB 32
#define H1 128
#define H2 64

// ---------------- scratch (static device globals; no allocation) ----------------
__device__ float g_qs[(size_t)BS * AGENTS];           // agent_qs [b][a]
__device__ float g_act_fallback[(size_t)BS * AGENTS];
__device__ float g_part[(size_t)64 * BS * EMB];       // GEMM partial sums [slab][b][e] 32MB
#define HKS 8
__device__ float g_hsp[(size_t)HKS * BS * 96];        // hyper_small partials [kz][b][96]

// fp16 operands, plain row-major (64MB total -> fully L2-resident)
__device__ __half g_A[(size_t)BS * SD];               // A [m][k] = states, fp16
__device__ __half g_B[(size_t)SD * SD];               // B [n][k] = Wh1[k][n], fp16

// ============================ PTX helpers =====================================
__device__ __forceinline__ uint32_t smem_u32(const void* p) {
    uint32_t a;
    asm("{ .reg .u64 t; cvta.to.shared.u64 t, %1; cvt.u32.u64 %0, t; }" : "=r"(a) : "l"(p));
    return a;
}

__device__ __forceinline__ void cp16(uint32_t s, const void* g) {
    asm volatile("cp.async.cg.shared.global [%0], [%1], 16;" :: "r"(s), "l"(g));
}
#define CP_COMMIT() asm volatile("cp.async.commit_group;")
#define CP_WAIT2()  asm volatile("cp.async.wait_group 2;")

__device__ __forceinline__ void ldm4(uint32_t* r, uint32_t addr) {
    asm volatile("ldmatrix.sync.aligned.m8n8.x4.shared.b16 {%0,%1,%2,%3}, [%4];"
        : "=r"(r[0]), "=r"(r[1]), "=r"(r[2]), "=r"(r[3]) : "r"(addr));
}

__device__ __forceinline__ void mma_fp16(float* c, const uint32_t* a, const uint32_t* b) {
    asm volatile("mma.sync.aligned.m16n8k16.row.col.f32.f16.f16.f32 "
        "{%0,%1,%2,%3}, {%4,%5,%6,%7}, {%8,%9}, {%0,%1,%2,%3};"
        : "+f"(c[0]), "+f"(c[1]), "+f"(c[2]), "+f"(c[3])
        : "r"(a[0]), "r"(a[1]), "r"(a[2]), "r"(a[3]), "r"(b[0]), "r"(b[1]));
}

// =============================================================================
// Kernel 1: fused per-agent 3-layer MLP + max/argmax. 512 threads. (R7 version)
// =============================================================================
#define MLP_BT 64
#define MLP_SMEM ((64*132 + 64*68 + 64*132 + 128*128) * 4)

__global__ void __launch_bounds__(512) mlp_kernel(
    const float* __restrict__ obs,
    const float* __restrict__ W1, const float* __restrict__ b1,
    const float* __restrict__ W2, const float* __restrict__ b2,
    const float* __restrict__ W3, const float* __restrict__ b3,
    float* __restrict__ actions_out)
{
    extern __shared__ float sm[];
    float* x1s  = sm;                       // [64][132]
    float* x2s  = sm + 64*132;              // [64][68]
    float* obss = sm + 64*132 + 64*68;      // [64][132]
    float* ws   = sm + 64*132 + 64*68 + 64*132;  // up to [128][128]
    __shared__ float b1s[H1];
    __shared__ float b2s[H2];
    __shared__ float b3s[ACT];

    const int a   = blockIdx.x;
    const int b0  = blockIdx.y * MLP_BT;
    const int tid = threadIdx.x;

    if (tid < H1) b1s[tid] = b1[a*H1 + tid];
    if (tid < H2) b2s[tid] = b2[a*H2 + tid];
    if (tid < ACT) b3s[tid] = b3[a*ACT + tid];

    {
        const float4* w1g = (const float4*)(W1 + (size_t)a * OBSD * H1);
        float4* wd = (float4*)ws;
        for (int i = tid; i < OBSD*H1/4; i += 512) wd[i] = w1g[i];
    }
    for (int i = tid; i < MLP_BT * (OBSD/4); i += 512) {
        int r  = i >> 5;
        int c4 = i & 31;
        float4 v = ((const float4*)(obs + ((size_t)(b0 + r) * AGENTS + a) * OBSD))[c4];
        *(float4*)(obss + r*132 + c4*4) = v;
    }
    __syncthreads();

    // layer 1
    {
        const int ty = tid >> 5, tx = tid & 31;
        float acc[4][4];
        #pragma unroll
        for (int i = 0; i < 4; i++)
            #pragma unroll
            for (int j = 0; j < 4; j++) acc[i][j] = 0.f;

        #pragma unroll 4
        for (int k = 0; k < OBSD; k++) {
            float a0 = obss[(ty*4+0)*132 + k];
            float a1 = obss[(ty*4+1)*132 + k];
            float a2 = obss[(ty*4+2)*132 + k];
            float a3 = obss[(ty*4+3)*132 + k];
            float4 w = *(const float4*)(ws + k*H1 + tx*4);
            float wv[4] = {w.x, w.y, w.z, w.w};
            #pragma unroll
            for (int j = 0; j < 4; j++) {
                acc[0][j] = fmaf(a0, wv[j], acc[0][j]);
                acc[1][j] = fmaf(a1, wv[j], acc[1][j]);
                acc[2][j] = fmaf(a2, wv[j], acc[2][j]);
                acc[3][j] = fmaf(a3, wv[j], acc[3][j]);
            }
        }
        #pragma unroll
        for (int i = 0; i < 4; i++) {
            float4 o;
            float* ov = (float*)&o;
            #pragma unroll
            for (int j = 0; j < 4; j++) {
                float v = acc[i][j] + b1s[tx*4 + j];
                ov[j] = v > 0.f ? v : 0.f;
            }
            *(float4*)(x1s + (ty*4+i)*132 + tx*4) = o;
        }
    }
    __syncthreads();

    {
        const float4* w2g = (const float4*)(W2 + (size_t)a * H1 * H2);
        float4* wd = (float4*)ws;
        for (int i = tid; i < H1*H2/4; i += 512) wd[i] = w2g[i];
    }
    __syncthreads();

    // layer 2
    {
        const int ry = tid >> 4, tx = tid & 15;
        float acc[2][4];
        #pragma unroll
        for (int i = 0; i < 2; i++)
            #pragma unroll
            for (int j = 0; j < 4; j++) acc[i][j] = 0.f;

        #pragma unroll 4
        for (int k = 0; k < H1; k++) {
            float a0 = x1s[(ry*2+0)*132 + k];
            float a1 = x1s[(ry*2+1)*132 + k];
            float4 w = *(const float4*)(ws + k*H2 + tx*4);
            float wv[4] = {w.x, w.y, w.z, w.w};
            #pragma unroll
            for (int j = 0; j < 4; j++) {
                acc[0][j] = fmaf(a0, wv[j], acc[0][j]);
                acc[1][j] = fmaf(a1, wv[j], acc[1][j]);
            }
        }
        #pragma unroll
        for (int i = 0; i < 2; i++) {
            float4 o;
            float* ov = (float*)&o;
            #pragma unroll
            for (int j = 0; j < 4; j++) {
                float v = acc[i][j] + b2s[tx*4 + j];
                ov[j] = v > 0.f ? v : 0.f;
            }
            *(float4*)(x2s + (ry*2+i)*68 + tx*4) = o;
        }
    }
    __syncthreads();

    {
        const float4* w3g = (const float4*)(W3 + (size_t)a * H2 * ACT);
        float4* wd = (float4*)ws;
        for (int i = tid; i < H2*ACT/4; i += 512) wd[i] = w3g[i];
    }
    __syncthreads();

    // layer 3 + argmax
    if (tid < MLP_BT) {
        const int r = tid;
        float acc[8];
        #pragma unroll
        for (int c = 0; c < 8; c++) acc[c] = 0.f;
        #pragma unroll 4
        for (int k = 0; k < H2; k++) {
            float x = x2s[r*68 + k];
            float4 w0  = *(const float4*)(ws + k*ACT);
            float4 w1v = *(const float4*)(ws + k*ACT + 4);
            acc[0] = fmaf(x, w0.x, acc[0]);
            acc[1] = fmaf(x, w0.y, acc[1]);
            acc[2] = fmaf(x, w0.z, acc[2]);
            acc[3] = fmaf(x, w0.w, acc[3]);
            acc[4] = fmaf(x, w1v.x, acc[4]);
            acc[5] = fmaf(x, w1v.y, acc[5]);
            acc[6] = fmaf(x, w1v.z, acc[6]);
            acc[7] = fmaf(x, w1v.w, acc[7]);
        }
        float best = acc[0] + b3s[0];
        int bi = 0;
        #pragma unroll
        for (int c = 1; c < 8; c++) {
            float q = acc[c] + b3s[c];
            if (q > best) { best = q; bi = c; }
        }
        g_qs[(size_t)(b0 + r) * AGENTS + a]        = best;
        actions_out[(size_t)(b0 + r) * AGENTS + a] = (float)bi;
    }
}

// =============================================================================
// Conversion: states -> single fp16 row-major
// =============================================================================
__global__ void __launch_bounds__(256) conv_S_kernel(const float* __restrict__ S)
{
    const size_t id = (size_t)blockIdx.x * 256 + threadIdx.x;   // one per 8 elems
    const float4* src = (const float4*)(S + id * 8);
    float4 v0 = src[0], v1 = src[1];
    float x[8] = {v0.x, v0.y, v0.z, v0.w, v1.x, v1.y, v1.z, v1.w};
    uint32_t hw[4];
    #pragma unroll
    for (int p = 0; p < 4; p++) {
        __half h0 = __float2half(x[p*2]);
        __half h1 = __float2half(x[p*2+1]);
        hw[p] = (uint32_t)__half_as_ushort(h0) | ((uint32_t)__half_as_ushort(h1) << 16);
    }
    ((uint4*)g_A)[id] = make_uint4(hw[0], hw[1], hw[2], hw[3]);
}

// =============================================================================
// Conversion + transpose: Wh1[k][n] -> B[n][k] single fp16 (64x64 smem tiles)
// =============================================================================
__global__ void __launch_bounds__(256) conv_W_kernel(const float* __restrict__ Wh1)
{
    __shared__ float tile[64][65];
    const int kt = blockIdx.x & 63;
    const int nt = blockIdx.x >> 6;
    const int tid = threadIdx.x;

    #pragma unroll
    for (int p = 0; p < 16; p++) {
        int idx = p * 256 + tid;
        int r = idx >> 6, c = idx & 63;      // r = k, c = n
        tile[r][c] = Wh1[(size_t)(kt*64 + r) * SD + nt*64 + c];
    }
    __syncthreads();

    #pragma unroll
    for (int p = 0; p < 2; p++) {
        int id = p * 256 + tid;
        int n = id >> 3, kc = id & 7;
        uint32_t hw[4];
        #pragma unroll
        for (int q = 0; q < 4; q++) {
            __half h0 = __float2half(tile[kc*8 + q*2][n]);
            __half h1 = __float2half(tile[kc*8 + q*2 + 1][n]);
            hw[q] = (uint32_t)__half_as_ushort(h0) | ((uint32_t)__half_as_ushort(h1) << 16);
        }
        size_t off = ((size_t)(nt*64 + n) * SD + kt*64 + kc*8) / 8;
        ((uint4*)g_B)[off] = make_uint4(hw[0], hw[1], hw[2], hw[3]);
    }
}

// =============================================================================
// mma.sync fp16 SINGLE-pass GEMM: C = A @ B^T, both plain fp16.
// 128x128 tile, BK=32, 4-stage cp.async (2 operands/stage, 80KB smem),
// one __syncthreads per K-iter. Epilogue folds qs*|acc+bh1| into g_part.
// =============================================================================
#define GSTAGES 4
#define OP_BYTES 10240
#define STAGE_BYTES (2 * OP_BYTES)
#define GEMM_SMEM (GSTAGES * STAGE_BYTES)
#define NKT (SD / 32)

__global__ void __launch_bounds__(256) hyper_gemm_mma(const float* __restrict__ bh1)
{
    extern __shared__ char gsm[];
    __shared__ float sbias[128];

    const int tid = threadIdx.x;
    const int wid = tid >> 5, lane = tid & 31;
    const int warpM = wid & 3, warpN = wid >> 2;
    const int bx = blockIdx.x >> 5;    // N tile
    const int by = blockIdx.x & 31;    // M tile

    const uint32_t sbase = smem_u32(gsm);

    if (tid < 128) sbias[tid] = bh1[bx*128 + tid];

    const char* A_g = (const char*)(g_A + (size_t)(by*128) * SD);
    const char* B_g = (const char*)(g_B + (size_t)(bx*128) * SD);

    const int id0 = tid, id1 = tid + 256;
    const int m0 = id0 >> 2, c0 = id0 & 3;
    const int m1 = id1 >> 2, c1 = id1 & 3;
    const uint32_t s_off0 = (uint32_t)(m0*5 + c0) * 16;
    const uint32_t s_off1 = (uint32_t)(m1*5 + c1) * 16;

    #define ISSUE_STAGE(stg, kt_) do { \
        const uint32_t sb_ = sbase + (stg) * STAGE_BYTES; \
        const size_t g0_ = ((size_t)m0 * SD + (size_t)(kt_)*32 + c0*8) * 2; \
        const size_t g1_ = ((size_t)m1 * SD + (size_t)(kt_)*32 + c1*8) * 2; \
        cp16(sb_ + 0*OP_BYTES + s_off0, A_g + g0_); \
        cp16(sb_ + 0*OP_BYTES + s_off1, A_g + g1_); \
        cp16(sb_ + 1*OP_BYTES + s_off0, B_g + g0_); \
        cp16(sb_ + 1*OP_BYTES + s_off1, B_g + g1_); \
        CP_COMMIT(); \
    } while (0)

    uint32_t offA[2][2], offB[4][2];
    {
        const int am = warpM*32 + (lane & 7) + ((lane >> 3) & 1) * 8;
        #pragma unroll
        for (int mt = 0; mt < 2; mt++)
            #pragma unroll
            for (int ks = 0; ks < 2; ks++)
                offA[mt][ks] = (uint32_t)((am + mt*16)*5 + ks*2 + (lane >> 4)) * 16;
        const int bn = warpN*64 + (lane & 7) + ((lane >> 4) & 1) * 8;
        #pragma unroll
        for (int ntp = 0; ntp < 4; ntp++)
            #pragma unroll
            for (int ks = 0; ks < 2; ks++)
                offB[ntp][ks] = (uint32_t)((bn + ntp*16)*5 + ks*2 + ((lane >> 3) & 1)) * 16;
    }

    float acc[2][8][4];
    #pragma unroll
    for (int mt = 0; mt < 2; mt++)
        #pragma unroll
        for (int nt = 0; nt < 8; nt++)
            #pragma unroll
            for (int q = 0; q < 4; q++) acc[mt][nt][q] = 0.f;

    // prologue: stages 0..2
    ISSUE_STAGE(0, 0);
    ISSUE_STAGE(1, 1);
    ISSUE_STAGE(2, 2);

    for (int kt = 0; kt < NKT; kt++) {
        CP_WAIT2();
        __syncthreads();

        if (kt + 3 < NKT) ISSUE_STAGE((kt + 3) & 3, kt + 3);

        const uint32_t stg = sbase + (kt & 3) * STAGE_BYTES;
        const uint32_t aOp = stg + 0*OP_BYTES;
        const uint32_t bOp = stg + 1*OP_BYTES;

        #pragma unroll
        for (int ks = 0; ks < 2; ks++) {
            uint32_t aa[2][4], bb[8][2];
            #pragma unroll
            for (int mt = 0; mt < 2; mt++) {
                ldm4(aa[mt], aOp + offA[mt][ks]);
            }
            #pragma unroll
            for (int ntp = 0; ntp < 4; ntp++) {
                uint32_t r[4];
                ldm4(r, bOp + offB[ntp][ks]);
                bb[2*ntp][0] = r[0]; bb[2*ntp][1] = r[1];
                bb[2*ntp+1][0] = r[2]; bb[2*ntp+1][1] = r[3];
            }
            #pragma unroll
            for (int mt = 0; mt < 2; mt++)
                #pragma unroll
                for (int nt = 0; nt < 8; nt++) {
                    mma_fp16(acc[mt][nt], aa[mt], bb[nt]);
                }
        }
    }

    // --------- epilogue: fold qs * |acc + bias|, reduce agents, store ---------
    const int slab = bx*2 + warpN;
    #pragma unroll
    for (int mt = 0; mt < 2; mt++) {
        #pragma unroll
        for (int rr = 0; rr < 2; rr++) {
            const int row = by*128 + warpM*32 + mt*16 + (lane >> 2) + rr*8;
            const float qv0 = g_qs[(size_t)row * AGENTS + bx*4 + warpN*2];
            const float qv1 = g_qs[(size_t)row * AGENTS + bx*4 + warpN*2 + 1];
            float part[8];
            #pragma unroll
            for (int s = 0; s < 8; s++) part[s] = 0.f;
            #pragma unroll
            for (int nt = 0; nt < 8; nt++) {
                const float qv = (nt < 4) ? qv0 : qv1;
                #pragma unroll
                for (int j = 0; j < 2; j++) {
                    const int col = warpN*64 + nt*8 + (lane & 3)*2 + j;
                    float v = acc[mt][nt][rr*2 + j] + sbias[col];
                    part[(nt & 3)*2 + j] = fmaf(qv, fabsf(v), part[(nt & 3)*2 + j]);
                }
            }
            float* dst = g_part + ((size_t)slab * BS + row) * EMB;
            #pragma unroll
            for (int k4 = 0; k4 < 4; k4++) {
                const int e = k4*8 + (lane & 3)*2;
                *(float2*)(dst + e) = make_float2(part[k4*2], part[k4*2 + 1]);
            }
        }
    }
}

// =============================================================================
// Skinny hypernet GEMMs, K-split by HKS. (R7 version)
// =============================================================================
__global__ void __launch_bounds__(256) hyper_small_kernel(
    const float* __restrict__ S,
    const float* __restrict__ Whb,
    const float* __restrict__ Whf,
    const float* __restrict__ Wv1)
{
    __shared__ __align__(16) float ss[64][36];
    __shared__ __align__(16) float wbs[64][32];
    __shared__ __align__(16) float wfs[64][32];
    __shared__ __align__(16) float wvs[64][32];

    const int b0  = blockIdx.x * 32;
    const int kz  = blockIdx.y;
    const int kbeg = kz * (SD / HKS);
    const int tid = threadIdx.x;
    const int e   = tid & 31;
    const int rg  = tid >> 5;

    float ab[4] = {0,0,0,0}, af[4] = {0,0,0,0}, av[4] = {0,0,0,0};

    for (int kc = 0; kc < SD/HKS; kc += 64) {
        const int k0 = kbeg + kc;
        __syncthreads();
        for (int i = tid; i < 512; i += 256) {
            int r = i >> 4, c4 = (i & 15) * 4;
            float4 v = *(const float4*)(S + (size_t)(b0 + r) * SD + k0 + c4);
            ss[c4+0][r] = v.x; ss[c4+1][r] = v.y; ss[c4+2][r] = v.z; ss[c4+3][r] = v.w;
        }
        for (int i = tid; i < 512; i += 256) {
            int kk = i >> 3, c = (i & 7) * 4;
            *(float4*)&wbs[kk][c] = *(const float4*)(Whb + (size_t)(k0+kk)*EMB + c);
            *(float4*)&wfs[kk][c] = *(const float4*)(Whf + (size_t)(k0+kk)*EMB + c);
            *(float4*)&wvs[kk][c] = *(const float4*)(Wv1 + (size_t)(k0+kk)*EMB + c);
        }
        __syncthreads();
        #pragma unroll 4
        for (int k = 0; k < 64; k++) {
            float wb = wbs[k][e], wf = wfs[k][e], wv = wvs[k][e];
            #pragma unroll
            for (int i = 0; i < 4; i++) {
                float s = ss[k][rg*4 + i];
                ab[i] = fmaf(s, wb, ab[i]);
                af[i] = fmaf(s, wf, af[i]);
                av[i] = fmaf(s, wv, av[i]);
            }
        }
    }
    #pragma unroll
    for (int i = 0; i < 4; i++) {
        int b = b0 + rg*4 + i;
        float* dst = g_hsp + ((size_t)kz * BS + b) * 96;
        dst[e]      = ab[i];
        dst[32 + e] = af[i];
        dst[64 + e] = av[i];
    }
}

// =============================================================================
// Final mixing (R7 version): reduce hyper_small K-slices (+bias/abs/relu),
// reduce GEMM slabs, elu, dot with w_final + V.
// =============================================================================
__global__ void __launch_bounds__(128) final_kernel(
    const float* __restrict__ bhb, const float* __restrict__ bhf,
    const float* __restrict__ bv1,
    const float* __restrict__ Wv2, const float* __restrict__ bv2,
    float* __restrict__ qtot)
{
    const int b = blockIdx.x * 4 + (threadIdx.x >> 5);
    const int e = threadIdx.x & 31;

    float sb = 0.f, wf = 0.f, rv = 0.f;
    #pragma unroll
    for (int kz = 0; kz < HKS; kz++) {
        const float* src = g_hsp + ((size_t)kz * BS + b) * 96;
        sb += src[e];
        wf += src[32 + e];
        rv += src[64 + e];
    }
    sb += bhb[e];
    wf = fabsf(wf + bhf[e]);
    rv += bv1[e];
    rv = rv > 0.f ? rv : 0.f;

    float s = 0.f;
    #pragma unroll
    for (int sl = 0; sl < 64; sl++)
        s += g_part[((size_t)sl * BS + b) * EMB + e];
    float hp = s + sb;
    float hidden = hp > 0.f ? hp : expm1f(hp);
    float contrib = hidden * wf + rv * Wv2[e];
    #pragma unroll
    for (int o = 16; o > 0; o >>= 1)
        contrib += __shfl_down_sync(0xffffffffu, contrib, o);
    if (e == 0) qtot[b] = contrib + bv2[0];
}

// =============================================================================
extern "C" void kernel_launch(void* const* d_in, const int* in_sizes, int n_in,
                              void* d_out, int out_size)
{
    const float* obs    = (const float*)d_in[0];
    const float* states = (const float*)d_in[1];
    const float* W1  = (const float*)d_in[2];
    const float* b1  = (const float*)d_in[3];
    const float* W2  = (const float*)d_in[4];
    const float* b2  = (const float*)d_in[5];
    const float* W3  = (const float*)d_in[6];
    const float* b3  = (const float*)d_in[7];
    const float* Wh1 = (const float*)d_in[8];
    const float* bh1 = (const float*)d_in[9];
    const float* Whb = (const float*)d_in[10];
    const float* bhb = (const float*)d_in[11];
    const float* Whf = (const float*)d_in[12];
    const float* bhf = (const float*)d_in[13];
    const float* Wv1 = (const float*)d_in[14];
    const float* bv1 = (const float*)d_in[15];
    const float* Wv2 = (const float*)d_in[16];
    const float* bv2 = (const float*)d_in[17];
    float* out = (float*)d_out;

    cudaFuncSetAttribute(mlp_kernel, cudaFuncAttributeMaxDynamicSharedMemorySize, MLP_SMEM);
    cudaFuncSetAttribute(hyper_gemm_mma, cudaFuncAttributeMaxDynamicSharedMemorySize, GEMM_SMEM);

    float* act_dst;
    if (out_size >= (int)(BS + BS*AGENTS)) {
        act_dst = out + BS;
    } else {
        void* p = 0;
        cudaGetSymbolAddress(&p, g_act_fallback);
        act_dst = (float*)p;
    }

    // Strictly sequential, single stream (overlap regressed twice: L2 pollution).
    mlp_kernel<<<dim3(AGENTS, BS/MLP_BT), 512, MLP_SMEM>>>(
        obs, W1, b1, W2, b2, W3, b3, act_dst);
    conv_S_kernel<<<BS*SD/8/256, 256>>>(states);
    conv_W_kernel<<<4096, 256>>>(Wh1);
    hyper_small_kernel<<<dim3(BS/32, HKS), 256>>>(states, Whb, Whf, Wv1);
    hyper_gemm_mma<<<1024, 256, GEMM_SMEM>>>(bh1);
    final_kernel<<<BS/4, 128>>>(bhb, bhf, bv1, Wv2, bv2, out);
}

// round 12
// speedup vs baseline: 2.3789x; 1.0586x over previous
#include <cuda_runtime.h>
#include <cuda_fp16.h>
#include <stdint.h>
#include <math.h>

#define BS 4096
#define AGENTS 128
#define OBSD 128
#define ACT 8
#define SD 4096
#define EMB 32
#define H1 128
#define H2 64

// ---------------- scratch (static device globals; no allocation) ----------------
__device__ float g_qs[(size_t)BS * AGENTS];           // agent_qs [b][a]
__device__ float g_act_fallback[(size_t)BS * AGENTS];
__device__ float g_part[(size_t)64 * BS * EMB];       // GEMM partial sums [slab][b][e] 32MB
#define HKS 8
__device__ float g_hsp[(size_t)HKS * BS * 96];        // hyper_small partials [kz][b][96]

// fp16 operands, plain row-major (64MB total -> fully L2-resident)
__device__ __half g_A[(size_t)BS * SD];               // A [m][k] = states, fp16
__device__ __half g_B[(size_t)SD * SD];               // B [n][k] = Wh1[k][n], fp16

// ============================ PTX helpers =====================================
__device__ __forceinline__ uint32_t smem_u32(const void* p) {
    uint32_t a;
    asm("{ .reg .u64 t; cvta.to.shared.u64 t, %1; cvt.u32.u64 %0, t; }" : "=r"(a) : "l"(p));
    return a;
}

__device__ __forceinline__ void cp16(uint32_t s, const void* g) {
    asm volatile("cp.async.cg.shared.global [%0], [%1], 16;" :: "r"(s), "l"(g));
}
#define CP_COMMIT() asm volatile("cp.async.commit_group;")
#define CP_WAIT2()  asm volatile("cp.async.wait_group 2;")

__device__ __forceinline__ void ldm4(uint32_t* r, uint32_t addr) {
    asm volatile("ldmatrix.sync.aligned.m8n8.x4.shared.b16 {%0,%1,%2,%3}, [%4];"
        : "=r"(r[0]), "=r"(r[1]), "=r"(r[2]), "=r"(r[3]) : "r"(addr));
}

__device__ __forceinline__ void mma_fp16(float* c, const uint32_t* a, const uint32_t* b) {
    asm volatile("mma.sync.aligned.m16n8k16.row.col.f32.f16.f16.f32 "
        "{%0,%1,%2,%3}, {%4,%5,%6,%7}, {%8,%9}, {%0,%1,%2,%3};"
        : "+f"(c[0]), "+f"(c[1]), "+f"(c[2]), "+f"(c[3])
        : "r"(a[0]), "r"(a[1]), "r"(a[2]), "r"(a[3]), "r"(b[0]), "r"(b[1]));
}

// ---- packed fp32x2 FMA (Blackwell; ptxas never auto-fuses, PTX-only) ----
__device__ __forceinline__ uint64_t pk2(float lo, float hi) {
    uint64_t r;
    asm("mov.b64 %0, {%1, %2};" : "=l"(r) : "f"(lo), "f"(hi));
    return r;
}
__device__ __forceinline__ void fma2(uint64_t& d, uint64_t a, uint64_t b) {
    asm("fma.rn.f32x2 %0, %1, %2, %0;" : "+l"(d) : "l"(a), "l"(b));
}
__device__ __forceinline__ float2 upk2(uint64_t v) {
    float2 f;
    asm("mov.b64 {%0, %1}, %2;" : "=f"(f.x), "=f"(f.y) : "l"(v));
    return f;
}

// =============================================================================
// Kernel 1: fused per-agent 3-layer MLP + max/argmax. 512 threads.
// Layers 1-2 use packed fma.rn.f32x2 (2 accumulators per register; per-
// accumulator summation order identical to scalar fp32 -> bitwise-same result).
// =============================================================================
#define MLP_BT 64
#define MLP_SMEM ((64*132 + 64*68 + 64*132 + 128*128) * 4)

__global__ void __launch_bounds__(512) mlp_kernel(
    const float* __restrict__ obs,
    const float* __restrict__ W1, const float* __restrict__ b1,
    const float* __restrict__ W2, const float* __restrict__ b2,
    const float* __restrict__ W3, const float* __restrict__ b3,
    float* __restrict__ actions_out)
{
    extern __shared__ float sm[];
    float* x1s  = sm;                       // [64][132]
    float* x2s  = sm + 64*132;              // [64][68]
    float* obss = sm + 64*132 + 64*68;      // [64][132]
    float* ws   = sm + 64*132 + 64*68 + 64*132;  // up to [128][128]
    __shared__ float b1s[H1];
    __shared__ float b2s[H2];
    __shared__ float b3s[ACT];

    const int a   = blockIdx.x;
    const int b0  = blockIdx.y * MLP_BT;
    const int tid = threadIdx.x;

    if (tid < H1) b1s[tid] = b1[a*H1 + tid];
    if (tid < H2) b2s[tid] = b2[a*H2 + tid];
    if (tid < ACT) b3s[tid] = b3[a*ACT + tid];

    {
        const float4* w1g = (const float4*)(W1 + (size_t)a * OBSD * H1);
        float4* wd = (float4*)ws;
        for (int i = tid; i < OBSD*H1/4; i += 512) wd[i] = w1g[i];
    }
    for (int i = tid; i < MLP_BT * (OBSD/4); i += 512) {
        int r  = i >> 5;
        int c4 = i & 31;
        float4 v = ((const float4*)(obs + ((size_t)(b0 + r) * AGENTS + a) * OBSD))[c4];
        *(float4*)(obss + r*132 + c4*4) = v;
    }
    __syncthreads();

    // ---- layer 1: x1[64][128] = relu(obs @ W1 + b1); 4x4 per thread, f32x2 ----
    {
        const int ty = tid >> 5, tx = tid & 31;
        uint64_t acc01[4], acc23[4];     // [row i]: packed (j0,j1) and (j2,j3)
        #pragma unroll
        for (int i = 0; i < 4; i++) { acc01[i] = 0ull; acc23[i] = 0ull; }

        #pragma unroll 4
        for (int k = 0; k < OBSD; k++) {
            float a0 = obss[(ty*4+0)*132 + k];
            float a1 = obss[(ty*4+1)*132 + k];
            float a2 = obss[(ty*4+2)*132 + k];
            float a3 = obss[(ty*4+3)*132 + k];
            float4 w = *(const float4*)(ws + k*H1 + tx*4);
            uint64_t w01 = pk2(w.x, w.y);
            uint64_t w23 = pk2(w.z, w.w);
            uint64_t aa;
            aa = pk2(a0, a0); fma2(acc01[0], aa, w01); fma2(acc23[0], aa, w23);
            aa = pk2(a1, a1); fma2(acc01[1], aa, w01); fma2(acc23[1], aa, w23);
            aa = pk2(a2, a2); fma2(acc01[2], aa, w01); fma2(acc23[2], aa, w23);
            aa = pk2(a3, a3); fma2(acc01[3], aa, w01); fma2(acc23[3], aa, w23);
        }
        #pragma unroll
        for (int i = 0; i < 4; i++) {
            float2 p0 = upk2(acc01[i]);
            float2 p1 = upk2(acc23[i]);
            float4 o;
            o.x = p0.x + b1s[tx*4 + 0]; o.x = o.x > 0.f ? o.x : 0.f;
            o.y = p0.y + b1s[tx*4 + 1]; o.y = o.y > 0.f ? o.y : 0.f;
            o.z = p1.x + b1s[tx*4 + 2]; o.z = o.z > 0.f ? o.z : 0.f;
            o.w = p1.y + b1s[tx*4 + 3]; o.w = o.w > 0.f ? o.w : 0.f;
            *(float4*)(x1s + (ty*4+i)*132 + tx*4) = o;
        }
    }
    __syncthreads();

    {
        const float4* w2g = (const float4*)(W2 + (size_t)a * H1 * H2);
        float4* wd = (float4*)ws;
        for (int i = tid; i < H1*H2/4; i += 512) wd[i] = w2g[i];
    }
    __syncthreads();

    // ---- layer 2: x2[64][64] = relu(x1 @ W2 + b2); 2x4 per thread, f32x2 ----
    {
        const int ry = tid >> 4, tx = tid & 15;
        uint64_t acc01[2], acc23[2];
        #pragma unroll
        for (int i = 0; i < 2; i++) { acc01[i] = 0ull; acc23[i] = 0ull; }

        #pragma unroll 4
        for (int k = 0; k < H1; k++) {
            float a0 = x1s[(ry*2+0)*132 + k];
            float a1 = x1s[(ry*2+1)*132 + k];
            float4 w = *(const float4*)(ws + k*H2 + tx*4);
            uint64_t w01 = pk2(w.x, w.y);
            uint64_t w23 = pk2(w.z, w.w);
            uint64_t aa;
            aa = pk2(a0, a0); fma2(acc01[0], aa, w01); fma2(acc23[0], aa, w23);
            aa = pk2(a1, a1); fma2(acc01[1], aa, w01); fma2(acc23[1], aa, w23);
        }
        #pragma unroll
        for (int i = 0; i < 2; i++) {
            float2 p0 = upk2(acc01[i]);
            float2 p1 = upk2(acc23[i]);
            float4 o;
            o.x = p0.x + b2s[tx*4 + 0]; o.x = o.x > 0.f ? o.x : 0.f;
            o.y = p0.y + b2s[tx*4 + 1]; o.y = o.y > 0.f ? o.y : 0.f;
            o.z = p1.x + b2s[tx*4 + 2]; o.z = o.z > 0.f ? o.z : 0.f;
            o.w = p1.y + b2s[tx*4 + 3]; o.w = o.w > 0.f ? o.w : 0.f;
            *(float4*)(x2s + (ry*2+i)*68 + tx*4) = o;
        }
    }
    __syncthreads();

    {
        const float4* w3g = (const float4*)(W3 + (size_t)a * H2 * ACT);
        float4* wd = (float4*)ws;
        for (int i = tid; i < H2*ACT/4; i += 512) wd[i] = w3g[i];
    }
    __syncthreads();

    // layer 3 + argmax (scalar fp32, tiny)
    if (tid < MLP_BT) {
        const int r = tid;
        float acc[8];
        #pragma unroll
        for (int c = 0; c < 8; c++) acc[c] = 0.f;
        #pragma unroll 4
        for (int k = 0; k < H2; k++) {
            float x = x2s[r*68 + k];
            float4 w0  = *(const float4*)(ws + k*ACT);
            float4 w1v = *(const float4*)(ws + k*ACT + 4);
            acc[0] = fmaf(x, w0.x, acc[0]);
            acc[1] = fmaf(x, w0.y, acc[1]);
            acc[2] = fmaf(x, w0.z, acc[2]);
            acc[3] = fmaf(x, w0.w, acc[3]);
            acc[4] = fmaf(x, w1v.x, acc[4]);
            acc[5] = fmaf(x, w1v.y, acc[5]);
            acc[6] = fmaf(x, w1v.z, acc[6]);
            acc[7] = fmaf(x, w1v.w, acc[7]);
        }
        float best = acc[0] + b3s[0];
        int bi = 0;
        #pragma unroll
        for (int c = 1; c < 8; c++) {
            float q = acc[c] + b3s[c];
            if (q > best) { best = q; bi = c; }
        }
        g_qs[(size_t)(b0 + r) * AGENTS + a]        = best;
        actions_out[(size_t)(b0 + r) * AGENTS + a] = (float)bi;
    }
}

// =============================================================================
// Conversion: states -> single fp16 row-major
// =============================================================================
__global__ void __launch_bounds__(256) conv_S_kernel(const float* __restrict__ S)
{
    const size_t id = (size_t)blockIdx.x * 256 + threadIdx.x;   // one per 8 elems
    const float4* src = (const float4*)(S + id * 8);
    float4 v0 = src[0], v1 = src[1];
    float x[8] = {v0.x, v0.y, v0.z, v0.w, v1.x, v1.y, v1.z, v1.w};
    uint32_t hw[4];
    #pragma unroll
    for (int p = 0; p < 4; p++) {
        __half h0 = __float2half(x[p*2]);
        __half h1 = __float2half(x[p*2+1]);
        hw[p] = (uint32_t)__half_as_ushort(h0) | ((uint32_t)__half_as_ushort(h1) << 16);
    }
    ((uint4*)g_A)[id] = make_uint4(hw[0], hw[1], hw[2], hw[3]);
}

// =============================================================================
// Conversion + transpose: Wh1[k][n] -> B[n][k] single fp16 (64x64 smem tiles)
// =============================================================================
__global__ void __launch_bounds__(256) conv_W_kernel(const float* __restrict__ Wh1)
{
    __shared__ float tile[64][65];
    const int kt = blockIdx.x & 63;
    const int nt = blockIdx.x >> 6;
    const int tid = threadIdx.x;

    #pragma unroll
    for (int p = 0; p < 16; p++) {
        int idx = p * 256 + tid;
        int r = idx >> 6, c = idx & 63;      // r = k, c = n
        tile[r][c] = Wh1[(size_t)(kt*64 + r) * SD + nt*64 + c];
    }
    __syncthreads();

    #pragma unroll
    for (int p = 0; p < 2; p++) {
        int id = p * 256 + tid;
        int n = id >> 3, kc = id & 7;
        uint32_t hw[4];
        #pragma unroll
        for (int q = 0; q < 4; q++) {
            __half h0 = __float2half(tile[kc*8 + q*2][n]);
            __half h1 = __float2half(tile[kc*8 + q*2 + 1][n]);
            hw[q] = (uint32_t)__half_as_ushort(h0) | ((uint32_t)__half_as_ushort(h1) << 16);
        }
        size_t off = ((size_t)(nt*64 + n) * SD + kt*64 + kc*8) / 8;
        ((uint4*)g_B)[off] = make_uint4(hw[0], hw[1], hw[2], hw[3]);
    }
}

// =============================================================================
// mma.sync fp16 SINGLE-pass GEMM: C = A @ B^T, both plain fp16. (R11 version)
// =============================================================================
#define GSTAGES 4
#define OP_BYTES 10240
#define STAGE_BYTES (2 * OP_BYTES)
#define GEMM_SMEM (GSTAGES * STAGE_BYTES)
#define NKT (SD / 32)

__global__ void __launch_bounds__(256) hyper_gemm_mma(const float* __restrict__ bh1)
{
    extern __shared__ char gsm[];
    __shared__ float sbias[128];

    const int tid = threadIdx.x;
    const int wid = tid >> 5, lane = tid & 31;
    const int warpM = wid & 3, warpN = wid >> 2;
    const int bx = blockIdx.x >> 5;    // N tile
    const int by = blockIdx.x & 31;    // M tile

    const uint32_t sbase = smem_u32(gsm);

    if (tid < 128) sbias[tid] = bh1[bx*128 + tid];

    const char* A_g = (const char*)(g_A + (size_t)(by*128) * SD);
    const char* B_g = (const char*)(g_B + (size_t)(bx*128) * SD);

    const int id0 = tid, id1 = tid + 256;
    const int m0 = id0 >> 2, c0 = id0 & 3;
    const int m1 = id1 >> 2, c1 = id1 & 3;
    const uint32_t s_off0 = (uint32_t)(m0*5 + c0) * 16;
    const uint32_t s_off1 = (uint32_t)(m1*5 + c1) * 16;

    #define ISSUE_STAGE(stg, kt_) do { \
        const uint32_t sb_ = sbase + (stg) * STAGE_BYTES; \
        const size_t g0_ = ((size_t)m0 * SD + (size_t)(kt_)*32 + c0*8) * 2; \
        const size_t g1_ = ((size_t)m1 * SD + (size_t)(kt_)*32 + c1*8) * 2; \
        cp16(sb_ + 0*OP_BYTES + s_off0, A_g + g0_); \
        cp16(sb_ + 0*OP_BYTES + s_off1, A_g + g1_); \
        cp16(sb_ + 1*OP_BYTES + s_off0, B_g + g0_); \
        cp16(sb_ + 1*OP_BYTES + s_off1, B_g + g1_); \
        CP_COMMIT(); \
    } while (0)

    uint32_t offA[2][2], offB[4][2];
    {
        const int am = warpM*32 + (lane & 7) + ((lane >> 3) & 1) * 8;
        #pragma unroll
        for (int mt = 0; mt < 2; mt++)
            #pragma unroll
            for (int ks = 0; ks < 2; ks++)
                offA[mt][ks] = (uint32_t)((am + mt*16)*5 + ks*2 + (lane >> 4)) * 16;
        const int bn = warpN*64 + (lane & 7) + ((lane >> 4) & 1) * 8;
        #pragma unroll
        for (int ntp = 0; ntp < 4; ntp++)
            #pragma unroll
            for (int ks = 0; ks < 2; ks++)
                offB[ntp][ks] = (uint32_t)((bn + ntp*16)*5 + ks*2 + ((lane >> 3) & 1)) * 16;
    }

    float acc[2][8][4];
    #pragma unroll
    for (int mt = 0; mt < 2; mt++)
        #pragma unroll
        for (int nt = 0; nt < 8; nt++)
            #pragma unroll
            for (int q = 0; q < 4; q++) acc[mt][nt][q] = 0.f;

    // prologue: stages 0..2
    ISSUE_STAGE(0, 0);
    ISSUE_STAGE(1, 1);
    ISSUE_STAGE(2, 2);

    for (int kt = 0; kt < NKT; kt++) {
        CP_WAIT2();
        __syncthreads();

        if (kt + 3 < NKT) ISSUE_STAGE((kt + 3) & 3, kt + 3);

        const uint32_t stg = sbase + (kt & 3) * STAGE_BYTES;
        const uint32_t aOp = stg + 0*OP_BYTES;
        const uint32_t bOp = stg + 1*OP_BYTES;

        #pragma unroll
        for (int ks = 0; ks < 2; ks++) {
            uint32_t aa[2][4], bb[8][2];
            #pragma unroll
            for (int mt = 0; mt < 2; mt++) {
                ldm4(aa[mt], aOp + offA[mt][ks]);
            }
            #pragma unroll
            for (int ntp = 0; ntp < 4; ntp++) {
                uint32_t r[4];
                ldm4(r, bOp + offB[ntp][ks]);
                bb[2*ntp][0] = r[0]; bb[2*ntp][1] = r[1];
                bb[2*ntp+1][0] = r[2]; bb[2*ntp+1][1] = r[3];
            }
            #pragma unroll
            for (int mt = 0; mt < 2; mt++)
                #pragma unroll
                for (int nt = 0; nt < 8; nt++) {
                    mma_fp16(acc[mt][nt], aa[mt], bb[nt]);
                }
        }
    }

    // --------- epilogue: fold qs * |acc + bias|, reduce agents, store ---------
    const int slab = bx*2 + warpN;
    #pragma unroll
    for (int mt = 0; mt < 2; mt++) {
        #pragma unroll
        for (int rr = 0; rr < 2; rr++) {
            const int row = by*128 + warpM*32 + mt*16 + (lane >> 2) + rr*8;
            const float qv0 = g_qs[(size_t)row * AGENTS + bx*4 + warpN*2];
            const float qv1 = g_qs[(size_t)row * AGENTS + bx*4 + warpN*2 + 1];
            float part[8];
            #pragma unroll
            for (int s = 0; s < 8; s++) part[s] = 0.f;
            #pragma unroll
            for (int nt = 0; nt < 8; nt++) {
                const float qv = (nt < 4) ? qv0 : qv1;
                #pragma unroll
                for (int j = 0; j < 2; j++) {
                    const int col = warpN*64 + nt*8 + (lane & 3)*2 + j;
                    float v = acc[mt][nt][rr*2 + j] + sbias[col];
                    part[(nt & 3)*2 + j] = fmaf(qv, fabsf(v), part[(nt & 3)*2 + j]);
                }
            }
            float* dst = g_part + ((size_t)slab * BS + row) * EMB;
            #pragma unroll
            for (int k4 = 0; k4 < 4; k4++) {
                const int e = k4*8 + (lane & 3)*2;
                *(float2*)(dst + e) = make_float2(part[k4*2], part[k4*2 + 1]);
            }
        }
    }
}

// =============================================================================
// Skinny hypernet GEMMs, K-split by HKS. (R7 version)
// =============================================================================
__global__ void __launch_bounds__(256) hyper_small_kernel(
    const float* __restrict__ S,
    const float* __restrict__ Whb,
    const float* __restrict__ Whf,
    const float* __restrict__ Wv1)
{
    __shared__ __align__(16) float ss[64][36];
    __shared__ __align__(16) float wbs[64][32];
    __shared__ __align__(16) float wfs[64][32];
    __shared__ __align__(16) float wvs[64][32];

    const int b0  = blockIdx.x * 32;
    const int kz  = blockIdx.y;
    const int kbeg = kz * (SD / HKS);
    const int tid = threadIdx.x;
    const int e   = tid & 31;
    const int rg  = tid >> 5;

    float ab[4] = {0,0,0,0}, af[4] = {0,0,0,0}, av[4] = {0,0,0,0};

    for (int kc = 0; kc < SD/HKS; kc += 64) {
        const int k0 = kbeg + kc;
        __syncthreads();
        for (int i = tid; i < 512; i += 256) {
            int r = i >> 4, c4 = (i & 15) * 4;
            float4 v = *(const float4*)(S + (size_t)(b0 + r) * SD + k0 + c4);
            ss[c4+0][r] = v.x; ss[c4+1][r] = v.y; ss[c4+2][r] = v.z; ss[c4+3][r] = v.w;
        }
        for (int i = tid; i < 512; i += 256) {
            int kk = i >> 3, c = (i & 7) * 4;
            *(float4*)&wbs[kk][c] = *(const float4*)(Whb + (size_t)(k0+kk)*EMB + c);
            *(float4*)&wfs[kk][c] = *(const float4*)(Whf + (size_t)(k0+kk)*EMB + c);
            *(float4*)&wvs[kk][c] = *(const float4*)(Wv1 + (size_t)(k0+kk)*EMB + c);
        }
        __syncthreads();
        #pragma unroll 4
        for (int k = 0; k < 64; k++) {
            float wb = wbs[k][e], wf = wfs[k][e], wv = wvs[k][e];
            #pragma unroll
            for (int i = 0; i < 4; i++) {
                float s = ss[k][rg*4 + i];
                ab[i] = fmaf(s, wb, ab[i]);
                af[i] = fmaf(s, wf, af[i]);
                av[i] = fmaf(s, wv, av[i]);
            }
        }
    }
    #pragma unroll
    for (int i = 0; i < 4; i++) {
        int b = b0 + rg*4 + i;
        float* dst = g_hsp + ((size_t)kz * BS + b) * 96;
        dst[e]      = ab[i];
        dst[32 + e] = af[i];
        dst[64 + e] = av[i];
    }
}

// =============================================================================
// Final mixing (R7 version): reduce hyper_small K-slices (+bias/abs/relu),
// reduce GEMM slabs, elu, dot with w_final + V.
// =============================================================================
__global__ void __launch_bounds__(128) final_kernel(
    const float* __restrict__ bhb, const float* __restrict__ bhf,
    const float* __restrict__ bv1,
    const float* __restrict__ Wv2, const float* __restrict__ bv2,
    float* __restrict__ qtot)
{
    const int b = blockIdx.x * 4 + (threadIdx.x >> 5);
    const int e = threadIdx.x & 31;

    float sb = 0.f, wf = 0.f, rv = 0.f;
    #pragma unroll
    for (int kz = 0; kz < HKS; kz++) {
        const float* src = g_hsp + ((size_t)kz * BS + b) * 96;
        sb += src[e];
        wf += src[32 + e];
        rv += src[64 + e];
    }
    sb += bhb[e];
    wf = fabsf(wf + bhf[e]);
    rv += bv1[e];
    rv = rv > 0.f ? rv : 0.f;

    float s = 0.f;
    #pragma unroll
    for (int sl = 0; sl < 64; sl++)
        s += g_part[((size_t)sl * BS + b) * EMB + e];
    float hp = s + sb;
    float hidden = hp > 0.f ? hp : expm1f(hp);
    float contrib = hidden * wf + rv * Wv2[e];
    #pragma unroll
    for (int o = 16; o > 0; o >>= 1)
        contrib += __shfl_down_sync(0xffffffffu, contrib, o);
    if (e == 0) qtot[b] = contrib + bv2[0];
}

// =============================================================================
extern "C" void kernel_launch(void* const* d_in, const int* in_sizes, int n_in,
                              void* d_out, int out_size)
{
    const float* obs    = (const float*)d_in[0];
    const float* states = (const float*)d_in[1];
    const float* W1  = (const float*)d_in[2];
    const float* b1  = (const float*)d_in[3];
    const float* W2  = (const float*)d_in[4];
    const float* b2  = (const float*)d_in[5];
    const float* W3  = (const float*)d_in[6];
    const float* b3  = (const float*)d_in[7];
    const float* Wh1 = (const float*)d_in[8];
    const float* bh1 = (const float*)d_in[9];
    const float* Whb = (const float*)d_in[10];
    const float* bhb = (const float*)d_in[11];
    const float* Whf = (const float*)d_in[12];
    const float* bhf = (const float*)d_in[13];
    const float* Wv1 = (const float*)d_in[14];
    const float* bv1 = (const float*)d_in[15];
    const float* Wv2 = (const float*)d_in[16];
    const float* bv2 = (const float*)d_in[17];
    float* out = (float*)d_out;

    cudaFuncSetAttribute(mlp_kernel, cudaFuncAttributeMaxDynamicSharedMemorySize, MLP_SMEM);
    cudaFuncSetAttribute(hyper_gemm_mma, cudaFuncAttributeMaxDynamicSharedMemorySize, GEMM_SMEM);

    float* act_dst;
    if (out_size >= (int)(BS + BS*AGENTS)) {
        act_dst = out + BS;
    } else {
        void* p = 0;
        cudaGetSymbolAddress(&p, g_act_fallback);
        act_dst = (float*)p;
    }

    // Strictly sequential, single stream (overlap regressed twice: L2 pollution).
    mlp_kernel<<<dim3(AGENTS, BS/MLP_BT), 512, MLP_SMEM>>>(
        obs, W1, b1, W2, b2, W3, b3, act_dst);
    conv_S_kernel<<<BS*SD/8/256, 256>>>(states);
    conv_W_kernel<<<4096, 256>>>(Wh1);
    hyper_small_kernel<<<dim3(BS/32, HKS), 256>>>(states, Whb, Whf, Wv1);
    hyper_gemm_mma<<<1024, 256, GEMM_SMEM>>>(bh1);
    final_kernel<<<BS/4, 128>>>(bhb, bhf, bv1, Wv2, bv2, out);
}

// round 13
// speedup vs baseline: 2.6084x; 1.0965x over previous
#include <cuda_runtime.h>
#include <cuda_fp16.h>
#include <stdint.h>
#include <math.h>

#define BS 4096
#define AGENTS 128
#define OBSD 128
#define ACT 8
#define SD 4096
#define EMB 32
#define H1 128
#define H2 64

// ---------------- scratch (static device globals; no allocation) ----------------
__device__ float g_qs[(size_t)BS * AGENTS];           // agent_qs [b][a]
__device__ float g_act_fallback[(size_t)BS * AGENTS];
__device__ float g_part[(size_t)64 * BS * EMB];       // GEMM partial sums [slab][b][e] 32MB
__device__ float g_ext[(size_t)BS * 128];             // raw states@{Whb|Whf|Wv1} dots (2MB)

// fp16 operands, plain row-major
__device__ __half g_A[(size_t)BS * SD];               // A [m][k] = states, fp16
__device__ __half g_B[(size_t)SD * SD];               // B [n][k] = Wh1[k][n], fp16
__device__ __half g_Bx[(size_t)128 * SD];             // Bx[n][k]: n<32 Whb, 32..63 Whf, 64..95 Wv1, 96..127 zero

// ============================ PTX helpers =====================================
__device__ __forceinline__ uint32_t smem_u32(const void* p) {
    uint32_t a;
    asm("{ .reg .u64 t; cvta.to.shared.u64 t, %1; cvt.u32.u64 %0, t; }" : "=r"(a) : "l"(p));
    return a;
}

__device__ __forceinline__ void cp16(uint32_t s, const void* g) {
    asm volatile("cp.async.cg.shared.global [%0], [%1], 16;" :: "r"(s), "l"(g));
}
#define CP_COMMIT() asm volatile("cp.async.commit_group;")
#define CP_WAIT2()  asm volatile("cp.async.wait_group 2;")

__device__ __forceinline__ void ldm4(uint32_t* r, uint32_t addr) {
    asm volatile("ldmatrix.sync.aligned.m8n8.x4.shared.b16 {%0,%1,%2,%3}, [%4];"
        : "=r"(r[0]), "=r"(r[1]), "=r"(r[2]), "=r"(r[3]) : "r"(addr));
}

__device__ __forceinline__ void mma_fp16(float* c, const uint32_t* a, const uint32_t* b) {
    asm volatile("mma.sync.aligned.m16n8k16.row.col.f32.f16.f16.f32 "
        "{%0,%1,%2,%3}, {%4,%5,%6,%7}, {%8,%9}, {%0,%1,%2,%3};"
        : "+f"(c[0]), "+f"(c[1]), "+f"(c[2]), "+f"(c[3])
        : "r"(a[0]), "r"(a[1]), "r"(a[2]), "r"(a[3]), "r"(b[0]), "r"(b[1]));
}

// ---- packed fp32x2 FMA (Blackwell; PTX-only) ----
__device__ __forceinline__ uint64_t pk2(float lo, float hi) {
    uint64_t r;
    asm("mov.b64 %0, {%1, %2};" : "=l"(r) : "f"(lo), "f"(hi));
    return r;
}
__device__ __forceinline__ void fma2(uint64_t& d, uint64_t a, uint64_t b) {
    asm("fma.rn.f32x2 %0, %1, %2, %0;" : "+l"(d) : "l"(a), "l"(b));
}
__device__ __forceinline__ float2 upk2(uint64_t v) {
    float2 f;
    asm("mov.b64 {%0, %1}, %2;" : "=f"(f.x), "=f"(f.y) : "l"(v));
    return f;
}

// =============================================================================
// Kernel 1: fused per-agent 3-layer MLP + max/argmax. 512 threads, f32x2.
// =============================================================================
#define MLP_BT 64
#define MLP_SMEM ((64*132 + 64*68 + 64*132 + 128*128) * 4)

__global__ void __launch_bounds__(512) mlp_kernel(
    const float* __restrict__ obs,
    const float* __restrict__ W1, const float* __restrict__ b1,
    const float* __restrict__ W2, const float* __restrict__ b2,
    const float* __restrict__ W3, const float* __restrict__ b3,
    float* __restrict__ actions_out)
{
    extern __shared__ float sm[];
    float* x1s  = sm;                       // [64][132]
    float* x2s  = sm + 64*132;              // [64][68]
    float* obss = sm + 64*132 + 64*68;      // [64][132]
    float* ws   = sm + 64*132 + 64*68 + 64*132;  // up to [128][128]
    __shared__ float b1s[H1];
    __shared__ float b2s[H2];
    __shared__ float b3s[ACT];

    const int a   = blockIdx.x;
    const int b0  = blockIdx.y * MLP_BT;
    const int tid = threadIdx.x;

    if (tid < H1) b1s[tid] = b1[a*H1 + tid];
    if (tid < H2) b2s[tid] = b2[a*H2 + tid];
    if (tid < ACT) b3s[tid] = b3[a*ACT + tid];

    {
        const float4* w1g = (const float4*)(W1 + (size_t)a * OBSD * H1);
        float4* wd = (float4*)ws;
        for (int i = tid; i < OBSD*H1/4; i += 512) wd[i] = w1g[i];
    }
    for (int i = tid; i < MLP_BT * (OBSD/4); i += 512) {
        int r  = i >> 5;
        int c4 = i & 31;
        float4 v = ((const float4*)(obs + ((size_t)(b0 + r) * AGENTS + a) * OBSD))[c4];
        *(float4*)(obss + r*132 + c4*4) = v;
    }
    __syncthreads();

    // ---- layer 1: 4x4 per thread, f32x2 ----
    {
        const int ty = tid >> 5, tx = tid & 31;
        uint64_t acc01[4], acc23[4];
        #pragma unroll
        for (int i = 0; i < 4; i++) { acc01[i] = 0ull; acc23[i] = 0ull; }

        #pragma unroll 4
        for (int k = 0; k < OBSD; k++) {
            float a0 = obss[(ty*4+0)*132 + k];
            float a1 = obss[(ty*4+1)*132 + k];
            float a2 = obss[(ty*4+2)*132 + k];
            float a3 = obss[(ty*4+3)*132 + k];
            float4 w = *(const float4*)(ws + k*H1 + tx*4);
            uint64_t w01 = pk2(w.x, w.y);
            uint64_t w23 = pk2(w.z, w.w);
            uint64_t aa;
            aa = pk2(a0, a0); fma2(acc01[0], aa, w01); fma2(acc23[0], aa, w23);
            aa = pk2(a1, a1); fma2(acc01[1], aa, w01); fma2(acc23[1], aa, w23);
            aa = pk2(a2, a2); fma2(acc01[2], aa, w01); fma2(acc23[2], aa, w23);
            aa = pk2(a3, a3); fma2(acc01[3], aa, w01); fma2(acc23[3], aa, w23);
        }
        #pragma unroll
        for (int i = 0; i < 4; i++) {
            float2 p0 = upk2(acc01[i]);
            float2 p1 = upk2(acc23[i]);
            float4 o;
            o.x = p0.x + b1s[tx*4 + 0]; o.x = o.x > 0.f ? o.x : 0.f;
            o.y = p0.y + b1s[tx*4 + 1]; o.y = o.y > 0.f ? o.y : 0.f;
            o.z = p1.x + b1s[tx*4 + 2]; o.z = o.z > 0.f ? o.z : 0.f;
            o.w = p1.y + b1s[tx*4 + 3]; o.w = o.w > 0.f ? o.w : 0.f;
            *(float4*)(x1s + (ty*4+i)*132 + tx*4) = o;
        }
    }
    __syncthreads();

    {
        const float4* w2g = (const float4*)(W2 + (size_t)a * H1 * H2);
        float4* wd = (float4*)ws;
        for (int i = tid; i < H1*H2/4; i += 512) wd[i] = w2g[i];
    }
    __syncthreads();

    // ---- layer 2: 2x4 per thread, f32x2 ----
    {
        const int ry = tid >> 4, tx = tid & 15;
        uint64_t acc01[2], acc23[2];
        #pragma unroll
        for (int i = 0; i < 2; i++) { acc01[i] = 0ull; acc23[i] = 0ull; }

        #pragma unroll 4
        for (int k = 0; k < H1; k++) {
            float a0 = x1s[(ry*2+0)*132 + k];
            float a1 = x1s[(ry*2+1)*132 + k];
            float4 w = *(const float4*)(ws + k*H2 + tx*4);
            uint64_t w01 = pk2(w.x, w.y);
            uint64_t w23 = pk2(w.z, w.w);
            uint64_t aa;
            aa = pk2(a0, a0); fma2(acc01[0], aa, w01); fma2(acc23[0], aa, w23);
            aa = pk2(a1, a1); fma2(acc01[1], aa, w01); fma2(acc23[1], aa, w23);
        }
        #pragma unroll
        for (int i = 0; i < 2; i++) {
            float2 p0 = upk2(acc01[i]);
            float2 p1 = upk2(acc23[i]);
            float4 o;
            o.x = p0.x + b2s[tx*4 + 0]; o.x = o.x > 0.f ? o.x : 0.f;
            o.y = p0.y + b2s[tx*4 + 1]; o.y = o.y > 0.f ? o.y : 0.f;
            o.z = p1.x + b2s[tx*4 + 2]; o.z = o.z > 0.f ? o.z : 0.f;
            o.w = p1.y + b2s[tx*4 + 3]; o.w = o.w > 0.f ? o.w : 0.f;
            *(float4*)(x2s + (ry*2+i)*68 + tx*4) = o;
        }
    }
    __syncthreads();

    {
        const float4* w3g = (const float4*)(W3 + (size_t)a * H2 * ACT);
        float4* wd = (float4*)ws;
        for (int i = tid; i < H2*ACT/4; i += 512) wd[i] = w3g[i];
    }
    __syncthreads();

    // layer 3 + argmax (scalar fp32)
    if (tid < MLP_BT) {
        const int r = tid;
        float acc[8];
        #pragma unroll
        for (int c = 0; c < 8; c++) acc[c] = 0.f;
        #pragma unroll 4
        for (int k = 0; k < H2; k++) {
            float x = x2s[r*68 + k];
            float4 w0  = *(const float4*)(ws + k*ACT);
            float4 w1v = *(const float4*)(ws + k*ACT + 4);
            acc[0] = fmaf(x, w0.x, acc[0]);
            acc[1] = fmaf(x, w0.y, acc[1]);
            acc[2] = fmaf(x, w0.z, acc[2]);
            acc[3] = fmaf(x, w0.w, acc[3]);
            acc[4] = fmaf(x, w1v.x, acc[4]);
            acc[5] = fmaf(x, w1v.y, acc[5]);
            acc[6] = fmaf(x, w1v.z, acc[6]);
            acc[7] = fmaf(x, w1v.w, acc[7]);
        }
        float best = acc[0] + b3s[0];
        int bi = 0;
        #pragma unroll
        for (int c = 1; c < 8; c++) {
            float q = acc[c] + b3s[c];
            if (q > best) { best = q; bi = c; }
        }
        g_qs[(size_t)(b0 + r) * AGENTS + a]        = best;
        actions_out[(size_t)(b0 + r) * AGENTS + a] = (float)bi;
    }
}

// =============================================================================
// Conversion: states -> single fp16 row-major
// =============================================================================
__global__ void __launch_bounds__(256) conv_S_kernel(const float* __restrict__ S)
{
    const size_t id = (size_t)blockIdx.x * 256 + threadIdx.x;
    const float4* src = (const float4*)(S + id * 8);
    float4 v0 = src[0], v1 = src[1];
    float x[8] = {v0.x, v0.y, v0.z, v0.w, v1.x, v1.y, v1.z, v1.w};
    uint32_t hw[4];
    #pragma unroll
    for (int p = 0; p < 4; p++) {
        __half h0 = __float2half(x[p*2]);
        __half h1 = __float2half(x[p*2+1]);
        hw[p] = (uint32_t)__half_as_ushort(h0) | ((uint32_t)__half_as_ushort(h1) << 16);
    }
    ((uint4*)g_A)[id] = make_uint4(hw[0], hw[1], hw[2], hw[3]);
}

// =============================================================================
// Conversion + transpose: Wh1[k][n] -> B[n][k] single fp16 (64x64 smem tiles)
// =============================================================================
__global__ void __launch_bounds__(256) conv_W_kernel(const float* __restrict__ Wh1)
{
    __shared__ float tile[64][65];
    const int kt = blockIdx.x & 63;
    const int nt = blockIdx.x >> 6;
    const int tid = threadIdx.x;

    #pragma unroll
    for (int p = 0; p < 16; p++) {
        int idx = p * 256 + tid;
        int r = idx >> 6, c = idx & 63;
        tile[r][c] = Wh1[(size_t)(kt*64 + r) * SD + nt*64 + c];
    }
    __syncthreads();

    #pragma unroll
    for (int p = 0; p < 2; p++) {
        int id = p * 256 + tid;
        int n = id >> 3, kc = id & 7;
        uint32_t hw[4];
        #pragma unroll
        for (int q = 0; q < 4; q++) {
            __half h0 = __float2half(tile[kc*8 + q*2][n]);
            __half h1 = __float2half(tile[kc*8 + q*2 + 1][n]);
            hw[q] = (uint32_t)__half_as_ushort(h0) | ((uint32_t)__half_as_ushort(h1) << 16);
        }
        size_t off = ((size_t)(nt*64 + n) * SD + kt*64 + kc*8) / 8;
        ((uint4*)g_B)[off] = make_uint4(hw[0], hw[1], hw[2], hw[3]);
    }
}

// =============================================================================
// Conversion + transpose of the skinny weights into g_Bx[n][k]:
// n 0..31 = Whb cols, 32..63 = Whf, 64..95 = Wv1, 96..127 = zeros.
// grid 64 (kt blocks of 64 k), 256 threads.
// =============================================================================
__global__ void __launch_bounds__(256) conv_Wx_kernel(
    const float* __restrict__ Whb,
    const float* __restrict__ Whf,
    const float* __restrict__ Wv1)
{
    __shared__ float tile[64][100];
    const int kt = blockIdx.x;
    const int tid = threadIdx.x;

    for (int i = tid; i < 64*32; i += 256) {
        int k = i >> 5, c = i & 31;
        tile[k][c]      = Whb[(size_t)(kt*64 + k) * EMB + c];
        tile[k][32 + c] = Whf[(size_t)(kt*64 + k) * EMB + c];
        tile[k][64 + c] = Wv1[(size_t)(kt*64 + k) * EMB + c];
    }
    __syncthreads();

    for (int i = tid; i < 128*64; i += 256) {
        int n = i >> 6, kk = i & 63;
        float v = (n < 96) ? tile[kk][n] : 0.f;
        g_Bx[(size_t)n * SD + kt*64 + kk] = __float2half(v);
    }
}

// =============================================================================
// mma.sync fp16 single-pass GEMM, 2 CTAs/SM. Grid 1056:
//   blocks [0,1024): C = A @ B^T tile (bx,by); epilogue folds qs*|acc+bh1|.
//   blocks [1024,1056): C = A @ Bx^T (skinny hypernet dots); raw acc -> g_ext.
// =============================================================================
#define GSTAGES 4
#define OP_BYTES 10240
#define STAGE_BYTES (2 * OP_BYTES)
#define GEMM_SMEM (GSTAGES * STAGE_BYTES)
#define NKT (SD / 32)

__global__ void __launch_bounds__(256, 2) hyper_gemm_mma(const float* __restrict__ bh1)
{
    extern __shared__ char gsm[];
    __shared__ float sbias[128];

    const int tid = threadIdx.x;
    const int wid = tid >> 5, lane = tid & 31;
    const int warpM = wid & 3, warpN = wid >> 2;

    const int bidx = blockIdx.x;
    const bool ext = (bidx >= 1024);
    const int bx = ext ? 32 : (bidx >> 5);
    const int by = ext ? (bidx - 1024) : (bidx & 31);

    const uint32_t sbase = smem_u32(gsm);

    if (!ext && tid < 128) sbias[tid] = bh1[bx*128 + tid];

    const char* A_g = (const char*)(g_A + (size_t)(by*128) * SD);
    const char* B_g = ext ? (const char*)g_Bx
                          : (const char*)(g_B + (size_t)(bx*128) * SD);

    const int id0 = tid, id1 = tid + 256;
    const int m0 = id0 >> 2, c0 = id0 & 3;
    const int m1 = id1 >> 2, c1 = id1 & 3;
    const uint32_t s_off0 = (uint32_t)(m0*5 + c0) * 16;
    const uint32_t s_off1 = (uint32_t)(m1*5 + c1) * 16;

    #define ISSUE_STAGE(stg, kt_) do { \
        const uint32_t sb_ = sbase + (stg) * STAGE_BYTES; \
        const size_t g0_ = ((size_t)m0 * SD + (size_t)(kt_)*32 + c0*8) * 2; \
        const size_t g1_ = ((size_t)m1 * SD + (size_t)(kt_)*32 + c1*8) * 2; \
        cp16(sb_ + 0*OP_BYTES + s_off0, A_g + g0_); \
        cp16(sb_ + 0*OP_BYTES + s_off1, A_g + g1_); \
        cp16(sb_ + 1*OP_BYTES + s_off0, B_g + g0_); \
        cp16(sb_ + 1*OP_BYTES + s_off1, B_g + g1_); \
        CP_COMMIT(); \
    } while (0)

    uint32_t offA[2][2], offB[4][2];
    {
        const int am = warpM*32 + (lane & 7) + ((lane >> 3) & 1) * 8;
        #pragma unroll
        for (int mt = 0; mt < 2; mt++)
            #pragma unroll
            for (int ks = 0; ks < 2; ks++)
                offA[mt][ks] = (uint32_t)((am + mt*16)*5 + ks*2 + (lane >> 4)) * 16;
        const int bn = warpN*64 + (lane & 7) + ((lane >> 4) & 1) * 8;
        #pragma unroll
        for (int ntp = 0; ntp < 4; ntp++)
            #pragma unroll
            for (int ks = 0; ks < 2; ks++)
                offB[ntp][ks] = (uint32_t)((bn + ntp*16)*5 + ks*2 + ((lane >> 3) & 1)) * 16;
    }

    float acc[2][8][4];
    #pragma unroll
    for (int mt = 0; mt < 2; mt++)
        #pragma unroll
        for (int nt = 0; nt < 8; nt++)
            #pragma unroll
            for (int q = 0; q < 4; q++) acc[mt][nt][q] = 0.f;

    ISSUE_STAGE(0, 0);
    ISSUE_STAGE(1, 1);
    ISSUE_STAGE(2, 2);

    for (int kt = 0; kt < NKT; kt++) {
        CP_WAIT2();
        __syncthreads();

        if (kt + 3 < NKT) ISSUE_STAGE((kt + 3) & 3, kt + 3);

        const uint32_t stg = sbase + (kt & 3) * STAGE_BYTES;
        const uint32_t aOp = stg + 0*OP_BYTES;
        const uint32_t bOp = stg + 1*OP_BYTES;

        #pragma unroll
        for (int ks = 0; ks < 2; ks++) {
            uint32_t aa[2][4], bb[8][2];
            #pragma unroll
            for (int mt = 0; mt < 2; mt++) {
                ldm4(aa[mt], aOp + offA[mt][ks]);
            }
            #pragma unroll
            for (int ntp = 0; ntp < 4; ntp++) {
                uint32_t r[4];
                ldm4(r, bOp + offB[ntp][ks]);
                bb[2*ntp][0] = r[0]; bb[2*ntp][1] = r[1];
                bb[2*ntp+1][0] = r[2]; bb[2*ntp+1][1] = r[3];
            }
            #pragma unroll
            for (int mt = 0; mt < 2; mt++)
                #pragma unroll
                for (int nt = 0; nt < 8; nt++) {
                    mma_fp16(acc[mt][nt], aa[mt], bb[nt]);
                }
        }
    }

    if (!ext) {
        // ---- main epilogue: fold qs * |acc + bias|, reduce agents ----
        const int slab = bx*2 + warpN;
        #pragma unroll
        for (int mt = 0; mt < 2; mt++) {
            #pragma unroll
            for (int rr = 0; rr < 2; rr++) {
                const int row = by*128 + warpM*32 + mt*16 + (lane >> 2) + rr*8;
                const float qv0 = g_qs[(size_t)row * AGENTS + bx*4 + warpN*2];
                const float qv1 = g_qs[(size_t)row * AGENTS + bx*4 + warpN*2 + 1];
                float part[8];
                #pragma unroll
                for (int s = 0; s < 8; s++) part[s] = 0.f;
                #pragma unroll
                for (int nt = 0; nt < 8; nt++) {
                    const float qv = (nt < 4) ? qv0 : qv1;
                    #pragma unroll
                    for (int j = 0; j < 2; j++) {
                        const int col = warpN*64 + nt*8 + (lane & 3)*2 + j;
                        float v = acc[mt][nt][rr*2 + j] + sbias[col];
                        part[(nt & 3)*2 + j] = fmaf(qv, fabsf(v), part[(nt & 3)*2 + j]);
                    }
                }
                float* dst = g_part + ((size_t)slab * BS + row) * EMB;
                #pragma unroll
                for (int k4 = 0; k4 < 4; k4++) {
                    const int e = k4*8 + (lane & 3)*2;
                    *(float2*)(dst + e) = make_float2(part[k4*2], part[k4*2 + 1]);
                }
            }
        }
    } else {
        // ---- ext epilogue: raw dots -> g_ext[row][col] ----
        #pragma unroll
        for (int mt = 0; mt < 2; mt++) {
            #pragma unroll
            for (int rr = 0; rr < 2; rr++) {
                const int row = by*128 + warpM*32 + mt*16 + (lane >> 2) + rr*8;
                float* dst = g_ext + (size_t)row * 128;
                #pragma unroll
                for (int nt = 0; nt < 8; nt++) {
                    const int col = warpN*64 + nt*8 + (lane & 3)*2;
                    *(float2*)(dst + col) =
                        make_float2(acc[mt][nt][rr*2 + 0], acc[mt][nt][rr*2 + 1]);
                }
            }
        }
    }
}

// =============================================================================
// Final mixing: hypernet dots from g_ext (+bias/abs/relu), GEMM slab reduce,
// elu, dot with w_final + V.
// =============================================================================
__global__ void __launch_bounds__(128) final_kernel(
    const float* __restrict__ bhb, const float* __restrict__ bhf,
    const float* __restrict__ bv1,
    const float* __restrict__ Wv2, const float* __restrict__ bv2,
    float* __restrict__ qtot)
{
    const int b = blockIdx.x * 4 + (threadIdx.x >> 5);
    const int e = threadIdx.x & 31;

    const float* ex = g_ext + (size_t)b * 128;
    float sb = ex[e] + bhb[e];
    float wf = fabsf(ex[32 + e] + bhf[e]);
    float rv = ex[64 + e] + bv1[e];
    rv = rv > 0.f ? rv : 0.f;

    float s = 0.f;
    #pragma unroll
    for (int sl = 0; sl < 64; sl++)
        s += g_part[((size_t)sl * BS + b) * EMB + e];
    float hp = s + sb;
    float hidden = hp > 0.f ? hp : expm1f(hp);
    float contrib = hidden * wf + rv * Wv2[e];
    #pragma unroll
    for (int o = 16; o > 0; o >>= 1)
        contrib += __shfl_down_sync(0xffffffffu, contrib, o);
    if (e == 0) qtot[b] = contrib + bv2[0];
}

// =============================================================================
extern "C" void kernel_launch(void* const* d_in, const int* in_sizes, int n_in,
                              void* d_out, int out_size)
{
    const float* obs    = (const float*)d_in[0];
    const float* states = (const float*)d_in[1];
    const float* W1  = (const float*)d_in[2];
    const float* b1  = (const float*)d_in[3];
    const float* W2  = (const float*)d_in[4];
    const float* b2  = (const float*)d_in[5];
    const float* W3  = (const float*)d_in[6];
    const float* b3  = (const float*)d_in[7];
    const float* Wh1 = (const float*)d_in[8];
    const float* bh1 = (const float*)d_in[9];
    const float* Whb = (const float*)d_in[10];
    const float* bhb = (const float*)d_in[11];
    const float* Whf = (const float*)d_in[12];
    const float* bhf = (const float*)d_in[13];
    const float* Wv1 = (const float*)d_in[14];
    const float* bv1 = (const float*)d_in[15];
    const float* Wv2 = (const float*)d_in[16];
    const float* bv2 = (const float*)d_in[17];
    float* out = (float*)d_out;

    cudaFuncSetAttribute(mlp_kernel, cudaFuncAttributeMaxDynamicSharedMemorySize, MLP_SMEM);
    cudaFuncSetAttribute(hyper_gemm_mma, cudaFuncAttributeMaxDynamicSharedMemorySize, GEMM_SMEM);

    float* act_dst;
    if (out_size >= (int)(BS + BS*AGENTS)) {
        act_dst = out + BS;
    } else {
        void* p = 0;
        cudaGetSymbolAddress(&p, g_act_fallback);
        act_dst = (float*)p;
    }

    // Strictly sequential, single stream (overlap regressed twice: L2 pollution).
    mlp_kernel<<<dim3(AGENTS, BS/MLP_BT), 512, MLP_SMEM>>>(
        obs, W1, b1, W2, b2, W3, b3, act_dst);
    conv_S_kernel<<<BS*SD/8/256, 256>>>(states);
    conv_W_kernel<<<4096, 256>>>(Wh1);
    conv_Wx_kernel<<<64, 256>>>(Whb, Whf, Wv1);
    hyper_gemm_mma<<<1056, 256, GEMM_SMEM>>>(bh1);
    final_kernel<<<BS/4, 128>>>(bhb, bhf, bv1, Wv2, bv2, out);
}

// round 14
// speedup vs baseline: 3.0778x; 1.1800x over previous
#include <cuda_runtime.h>
#include <cuda_fp16.h>
#include <stdint.h>
#include <math.h>

#define BS 4096
#define AGENTS 128
#define OBSD 128
#define ACT 8
#define SD 4096
#define EMB 32
#define H1 128
#define H2 64

// ---------------- scratch (static device globals; no allocation) ----------------
__device__ float g_qs[(size_t)BS * AGENTS];           // agent_qs [b][a]
__device__ float g_act_fallback[(size_t)BS * AGENTS];
__device__ float g_part[(size_t)64 * BS * EMB];       // GEMM partial sums [slab][b][e] 32MB
__device__ float g_ext[(size_t)BS * 128];             // raw states@{Whb|Whf|Wv1} dots (2MB)

// fp16 operands, plain row-major
__device__ __half g_A[(size_t)BS * SD];               // A [m][k] = states, fp16
__device__ __half g_B[(size_t)SD * SD];               // B [n][k] = Wh1[k][n], fp16
__device__ __half g_Bx[(size_t)128 * SD];             // Bx[n][k]: n<32 Whb, 32..63 Whf, 64..95 Wv1, 96..127 zero

// ============================ PTX helpers =====================================
__device__ __forceinline__ uint32_t smem_u32(const void* p) {
    uint32_t a;
    asm("{ .reg .u64 t; cvta.to.shared.u64 t, %1; cvt.u32.u64 %0, t; }" : "=r"(a) : "l"(p));
    return a;
}

__device__ __forceinline__ void cp16(uint32_t s, const void* g) {
    asm volatile("cp.async.cg.shared.global [%0], [%1], 16;" :: "r"(s), "l"(g));
}
#define CP_COMMIT() asm volatile("cp.async.commit_group;")
#define CP_WAIT2()  asm volatile("cp.async.wait_group 2;")

__device__ __forceinline__ void ldm4(uint32_t* r, uint32_t addr) {
    asm volatile("ldmatrix.sync.aligned.m8n8.x4.shared.b16 {%0,%1,%2,%3}, [%4];"
        : "=r"(r[0]), "=r"(r[1]), "=r"(r[2]), "=r"(r[3]) : "r"(addr));
}

__device__ __forceinline__ void mma_fp16(float* c, const uint32_t* a, const uint32_t* b) {
    asm volatile("mma.sync.aligned.m16n8k16.row.col.f32.f16.f16.f32 "
        "{%0,%1,%2,%3}, {%4,%5,%6,%7}, {%8,%9}, {%0,%1,%2,%3};"
        : "+f"(c[0]), "+f"(c[1]), "+f"(c[2]), "+f"(c[3])
        : "r"(a[0]), "r"(a[1]), "r"(a[2]), "r"(a[3]), "r"(b[0]), "r"(b[1]));
}

// ---- packed fp32x2 FMA (Blackwell; PTX-only) ----
__device__ __forceinline__ uint64_t pk2(float lo, float hi) {
    uint64_t r;
    asm("mov.b64 %0, {%1, %2};" : "=l"(r) : "f"(lo), "f"(hi));
    return r;
}
__device__ __forceinline__ void fma2(uint64_t& d, uint64_t a, uint64_t b) {
    asm("fma.rn.f32x2 %0, %1, %2, %0;" : "+l"(d) : "l"(a), "l"(b));
}
__device__ __forceinline__ float2 upk2(uint64_t v) {
    float2 f;
    asm("mov.b64 {%0, %1}, %2;" : "=f"(f.x), "=f"(f.y) : "l"(v));
    return f;
}

// =============================================================================
// Kernel 1: fused per-agent 3-layer MLP + max/argmax.
// BT=128 rows/CTA, 512 threads. W1 staged in two 64-output-column halves
// (halves weight-staging traffic + syncs vs BT=64). f32x2 math; per-
// accumulator k-order identical to BT=64 version -> bitwise-same outputs.
// smem: obss[128][132] + x1s[128][132] + x2s[128][68] + ws[8192] = 202,752 B
// =============================================================================
#define MLP_BT 128
#define MLP_SMEM ((128*132 + 128*132 + 128*68 + 8192) * 4)

__global__ void __launch_bounds__(512) mlp_kernel(
    const float* __restrict__ obs,
    const float* __restrict__ W1, const float* __restrict__ b1,
    const float* __restrict__ W2, const float* __restrict__ b2,
    const float* __restrict__ W3, const float* __restrict__ b3,
    float* __restrict__ actions_out)
{
    extern __shared__ float sm[];
    float* obss = sm;                               // [128][132]
    float* x1s  = sm + 128*132;                     // [128][132]
    float* x2s  = sm + 2*128*132;                   // [128][68]
    float* ws   = sm + 2*128*132 + 128*68;          // 8192 floats (32KB)
    __shared__ float b1s[H1];
    __shared__ float b2s[H2];
    __shared__ float b3s[ACT];

    const int a   = blockIdx.x;
    const int b0  = blockIdx.y * MLP_BT;
    const int tid = threadIdx.x;

    if (tid < H1) b1s[tid] = b1[a*H1 + tid];
    if (tid < H2) b2s[tid] = b2[a*H2 + tid];
    if (tid < ACT) b3s[tid] = b3[a*ACT + tid];

    // stage obs tile [128][128] -> padded stride 132
    for (int i = tid; i < MLP_BT * (OBSD/4); i += 512) {
        int r  = i >> 5;
        int c4 = i & 31;
        float4 v = ((const float4*)(obs + ((size_t)(b0 + r) * AGENTS + a) * OBSD))[c4];
        *(float4*)(obss + r*132 + c4*4) = v;
    }

    // ---- layer 1 in two output-column halves of 64; 4x4 per thread, f32x2 ----
    #pragma unroll
    for (int h = 0; h < 2; h++) {
        // stage W1[:, h*64 : h*64+64]: 128 k-rows x 16 float4
        for (int i = tid; i < 2048; i += 512) {
            int k = i >> 4, c4 = i & 15;
            *(float4*)(ws + k*64 + c4*4) =
                *(const float4*)(W1 + (size_t)a * OBSD * H1 + (size_t)k * H1 + h*64 + c4*4);
        }
        __syncthreads();

        const int ty = tid >> 4, tx = tid & 15;   // rows ty*4.., cols tx*4 within half
        uint64_t acc01[4], acc23[4];
        #pragma unroll
        for (int i = 0; i < 4; i++) { acc01[i] = 0ull; acc23[i] = 0ull; }

        #pragma unroll 4
        for (int k = 0; k < OBSD; k++) {
            float a0 = obss[(ty*4+0)*132 + k];
            float a1 = obss[(ty*4+1)*132 + k];
            float a2 = obss[(ty*4+2)*132 + k];
            float a3 = obss[(ty*4+3)*132 + k];
            float4 w = *(const float4*)(ws + k*64 + tx*4);
            uint64_t w01 = pk2(w.x, w.y);
            uint64_t w23 = pk2(w.z, w.w);
            uint64_t aa;
            aa = pk2(a0, a0); fma2(acc01[0], aa, w01); fma2(acc23[0], aa, w23);
            aa = pk2(a1, a1); fma2(acc01[1], aa, w01); fma2(acc23[1], aa, w23);
            aa = pk2(a2, a2); fma2(acc01[2], aa, w01); fma2(acc23[2], aa, w23);
            aa = pk2(a3, a3); fma2(acc01[3], aa, w01); fma2(acc23[3], aa, w23);
        }
        #pragma unroll
        for (int i = 0; i < 4; i++) {
            float2 p0 = upk2(acc01[i]);
            float2 p1 = upk2(acc23[i]);
            float4 o;
            o.x = p0.x + b1s[h*64 + tx*4 + 0]; o.x = o.x > 0.f ? o.x : 0.f;
            o.y = p0.y + b1s[h*64 + tx*4 + 1]; o.y = o.y > 0.f ? o.y : 0.f;
            o.z = p1.x + b1s[h*64 + tx*4 + 2]; o.z = o.z > 0.f ? o.z : 0.f;
            o.w = p1.y + b1s[h*64 + tx*4 + 3]; o.w = o.w > 0.f ? o.w : 0.f;
            *(float4*)(x1s + (ty*4+i)*132 + h*64 + tx*4) = o;
        }
        __syncthreads();   // ws reused next half / next layer
    }

    // ---- layer 2: stage W2 [128][64] fully (32KB); 4x4 per thread ----
    for (int i = tid; i < 2048; i += 512) {
        ((float4*)ws)[i] = ((const float4*)(W2 + (size_t)a * H1 * H2))[i];
    }
    __syncthreads();

    {
        const int ty = tid >> 4, tx = tid & 15;   // rows ty*4.., cols tx*4
        uint64_t acc01[4], acc23[4];
        #pragma unroll
        for (int i = 0; i < 4; i++) { acc01[i] = 0ull; acc23[i] = 0ull; }

        #pragma unroll 4
        for (int k = 0; k < H1; k++) {
            float a0 = x1s[(ty*4+0)*132 + k];
            float a1 = x1s[(ty*4+1)*132 + k];
            float a2 = x1s[(ty*4+2)*132 + k];
            float a3 = x1s[(ty*4+3)*132 + k];
            float4 w = *(const float4*)(ws + k*H2 + tx*4);
            uint64_t w01 = pk2(w.x, w.y);
            uint64_t w23 = pk2(w.z, w.w);
            uint64_t aa;
            aa = pk2(a0, a0); fma2(acc01[0], aa, w01); fma2(acc23[0], aa, w23);
            aa = pk2(a1, a1); fma2(acc01[1], aa, w01); fma2(acc23[1], aa, w23);
            aa = pk2(a2, a2); fma2(acc01[2], aa, w01); fma2(acc23[2], aa, w23);
            aa = pk2(a3, a3); fma2(acc01[3], aa, w01); fma2(acc23[3], aa, w23);
        }
        #pragma unroll
        for (int i = 0; i < 4; i++) {
            float2 p0 = upk2(acc01[i]);
            float2 p1 = upk2(acc23[i]);
            float4 o;
            o.x = p0.x + b2s[tx*4 + 0]; o.x = o.x > 0.f ? o.x : 0.f;
            o.y = p0.y + b2s[tx*4 + 1]; o.y = o.y > 0.f ? o.y : 0.f;
            o.z = p1.x + b2s[tx*4 + 2]; o.z = o.z > 0.f ? o.z : 0.f;
            o.w = p1.y + b2s[tx*4 + 3]; o.w = o.w > 0.f ? o.w : 0.f;
            *(float4*)(x2s + (ty*4+i)*68 + tx*4) = o;
        }
    }
    __syncthreads();

    // ---- layer 3: stage W3 [64][8] ----
    if (tid < 128) ((float4*)ws)[tid] = ((const float4*)(W3 + (size_t)a * H2 * ACT))[tid];
    __syncthreads();

    // layer 3 + argmax: one thread per batch row (128 rows)
    if (tid < MLP_BT) {
        const int r = tid;
        float acc[8];
        #pragma unroll
        for (int c = 0; c < 8; c++) acc[c] = 0.f;
        #pragma unroll 4
        for (int k = 0; k < H2; k++) {
            float x = x2s[r*68 + k];
            float4 w0  = *(const float4*)(ws + k*ACT);
            float4 w1v = *(const float4*)(ws + k*ACT + 4);
            acc[0] = fmaf(x, w0.x, acc[0]);
            acc[1] = fmaf(x, w0.y, acc[1]);
            acc[2] = fmaf(x, w0.z, acc[2]);
            acc[3] = fmaf(x, w0.w, acc[3]);
            acc[4] = fmaf(x, w1v.x, acc[4]);
            acc[5] = fmaf(x, w1v.y, acc[5]);
            acc[6] = fmaf(x, w1v.z, acc[6]);
            acc[7] = fmaf(x, w1v.w, acc[7]);
        }
        float best = acc[0] + b3s[0];
        int bi = 0;
        #pragma unroll
        for (int c = 1; c < 8; c++) {
            float q = acc[c] + b3s[c];
            if (q > best) { best = q; bi = c; }
        }
        g_qs[(size_t)(b0 + r) * AGENTS + a]        = best;
        actions_out[(size_t)(b0 + r) * AGENTS + a] = (float)bi;
    }
}

// =============================================================================
// Conversion: states -> single fp16 row-major
// =============================================================================
__global__ void __launch_bounds__(256) conv_S_kernel(const float* __restrict__ S)
{
    const size_t id = (size_t)blockIdx.x * 256 + threadIdx.x;
    const float4* src = (const float4*)(S + id * 8);
    float4 v0 = src[0], v1 = src[1];
    float x[8] = {v0.x, v0.y, v0.z, v0.w, v1.x, v1.y, v1.z, v1.w};
    uint32_t hw[4];
    #pragma unroll
    for (int p = 0; p < 4; p++) {
        __half h0 = __float2half(x[p*2]);
        __half h1 = __float2half(x[p*2+1]);
        hw[p] = (uint32_t)__half_as_ushort(h0) | ((uint32_t)__half_as_ushort(h1) << 16);
    }
    ((uint4*)g_A)[id] = make_uint4(hw[0], hw[1], hw[2], hw[3]);
}

// =============================================================================
// Conversion + transpose: Wh1[k][n] -> B[n][k] single fp16 (64x64 smem tiles)
// =============================================================================
__global__ void __launch_bounds__(256) conv_W_kernel(const float* __restrict__ Wh1)
{
    __shared__ float tile[64][65];
    const int kt = blockIdx.x & 63;
    const int nt = blockIdx.x >> 6;
    const int tid = threadIdx.x;

    #pragma unroll
    for (int p = 0; p < 16; p++) {
        int idx = p * 256 + tid;
        int r = idx >> 6, c = idx & 63;
        tile[r][c] = Wh1[(size_t)(kt*64 + r) * SD + nt*64 + c];
    }
    __syncthreads();

    #pragma unroll
    for (int p = 0; p < 2; p++) {
        int id = p * 256 + tid;
        int n = id >> 3, kc = id & 7;
        uint32_t hw[4];
        #pragma unroll
        for (int q = 0; q < 4; q++) {
            __half h0 = __float2half(tile[kc*8 + q*2][n]);
            __half h1 = __float2half(tile[kc*8 + q*2 + 1][n]);
            hw[q] = (uint32_t)__half_as_ushort(h0) | ((uint32_t)__half_as_ushort(h1) << 16);
        }
        size_t off = ((size_t)(nt*64 + n) * SD + kt*64 + kc*8) / 8;
        ((uint4*)g_B)[off] = make_uint4(hw[0], hw[1], hw[2], hw[3]);
    }
}

// =============================================================================
// Conversion + transpose of the skinny weights into g_Bx[n][k]
// =============================================================================
__global__ void __launch_bounds__(256) conv_Wx_kernel(
    const float* __restrict__ Whb,
    const float* __restrict__ Whf,
    const float* __restrict__ Wv1)
{
    __shared__ float tile[64][100];
    const int kt = blockIdx.x;
    const int tid = threadIdx.x;

    for (int i = tid; i < 64*32; i += 256) {
        int k = i >> 5, c = i & 31;
        tile[k][c]      = Whb[(size_t)(kt*64 + k) * EMB + c];
        tile[k][32 + c] = Whf[(size_t)(kt*64 + k) * EMB + c];
        tile[k][64 + c] = Wv1[(size_t)(kt*64 + k) * EMB + c];
    }
    __syncthreads();

    for (int i = tid; i < 128*64; i += 256) {
        int n = i >> 6, kk = i & 63;
        float v = (n < 96) ? tile[kk][n] : 0.f;
        g_Bx[(size_t)n * SD + kt*64 + kk] = __float2half(v);
    }
}

// =============================================================================
// mma.sync fp16 single-pass GEMM, 2 CTAs/SM. Grid 1056 (R13 version).
// =============================================================================
#define GSTAGES 4
#define OP_BYTES 10240
#define STAGE_BYTES (2 * OP_BYTES)
#define GEMM_SMEM (GSTAGES * STAGE_BYTES)
#define NKT (SD / 32)

__global__ void __launch_bounds__(256, 2) hyper_gemm_mma(const float* __restrict__ bh1)
{
    extern __shared__ char gsm[];
    __shared__ float sbias[128];

    const int tid = threadIdx.x;
    const int wid = tid >> 5, lane = tid & 31;
    const int warpM = wid & 3, warpN = wid >> 2;

    const int bidx = blockIdx.x;
    const bool ext = (bidx >= 1024);
    const int bx = ext ? 32 : (bidx >> 5);
    const int by = ext ? (bidx - 1024) : (bidx & 31);

    const uint32_t sbase = smem_u32(gsm);

    if (!ext && tid < 128) sbias[tid] = bh1[bx*128 + tid];

    const char* A_g = (const char*)(g_A + (size_t)(by*128) * SD);
    const char* B_g = ext ? (const char*)g_Bx
                          : (const char*)(g_B + (size_t)(bx*128) * SD);

    const int id0 = tid, id1 = tid + 256;
    const int m0 = id0 >> 2, c0 = id0 & 3;
    const int m1 = id1 >> 2, c1 = id1 & 3;
    const uint32_t s_off0 = (uint32_t)(m0*5 + c0) * 16;
    const uint32_t s_off1 = (uint32_t)(m1*5 + c1) * 16;

    #define ISSUE_STAGE(stg, kt_) do { \
        const uint32_t sb_ = sbase + (stg) * STAGE_BYTES; \
        const size_t g0_ = ((size_t)m0 * SD + (size_t)(kt_)*32 + c0*8) * 2; \
        const size_t g1_ = ((size_t)m1 * SD + (size_t)(kt_)*32 + c1*8) * 2; \
        cp16(sb_ + 0*OP_BYTES + s_off0, A_g + g0_); \
        cp16(sb_ + 0*OP_BYTES + s_off1, A_g + g1_); \
        cp16(sb_ + 1*OP_BYTES + s_off0, B_g + g0_); \
        cp16(sb_ + 1*OP_BYTES + s_off1, B_g + g1_); \
        CP_COMMIT(); \
    } while (0)

    uint32_t offA[2][2], offB[4][2];
    {
        const int am = warpM*32 + (lane & 7) + ((lane >> 3) & 1) * 8;
        #pragma unroll
        for (int mt = 0; mt < 2; mt++)
            #pragma unroll
            for (int ks = 0; ks < 2; ks++)
                offA[mt][ks] = (uint32_t)((am + mt*16)*5 + ks*2 + (lane >> 4)) * 16;
        const int bn = warpN*64 + (lane & 7) + ((lane >> 4) & 1) * 8;
        #pragma unroll
        for (int ntp = 0; ntp < 4; ntp++)
            #pragma unroll
            for (int ks = 0; ks < 2; ks++)
                offB[ntp][ks] = (uint32_t)((bn + ntp*16)*5 + ks*2 + ((lane >> 3) & 1)) * 16;
    }

    float acc[2][8][4];
    #pragma unroll
    for (int mt = 0; mt < 2; mt++)
        #pragma unroll
        for (int nt = 0; nt < 8; nt++)
            #pragma unroll
            for (int q = 0; q < 4; q++) acc[mt][nt][q] = 0.f;

    ISSUE_STAGE(0, 0);
    ISSUE_STAGE(1, 1);
    ISSUE_STAGE(2, 2);

    for (int kt = 0; kt < NKT; kt++) {
        CP_WAIT2();
        __syncthreads();

        if (kt + 3 < NKT) ISSUE_STAGE((kt + 3) & 3, kt + 3);

        const uint32_t stg = sbase + (kt & 3) * STAGE_BYTES;
        const uint32_t aOp = stg + 0*OP_BYTES;
        const uint32_t bOp = stg + 1*OP_BYTES;

        #pragma unroll
        for (int ks = 0; ks < 2; ks++) {
            uint32_t aa[2][4], bb[8][2];
            #pragma unroll
            for (int mt = 0; mt < 2; mt++) {
                ldm4(aa[mt], aOp + offA[mt][ks]);
            }
            #pragma unroll
            for (int ntp = 0; ntp < 4; ntp++) {
                uint32_t r[4];
                ldm4(r, bOp + offB[ntp][ks]);
                bb[2*ntp][0] = r[0]; bb[2*ntp][1] = r[1];
                bb[2*ntp+1][0] = r[2]; bb[2*ntp+1][1] = r[3];
            }
            #pragma unroll
            for (int mt = 0; mt < 2; mt++)
                #pragma unroll
                for (int nt = 0; nt < 8; nt++) {
                    mma_fp16(acc[mt][nt], aa[mt], bb[nt]);
                }
        }
    }

    if (!ext) {
        const int slab = bx*2 + warpN;
        #pragma unroll
        for (int mt = 0; mt < 2; mt++) {
            #pragma unroll
            for (int rr = 0; rr < 2; rr++) {
                const int row = by*128 + warpM*32 + mt*16 + (lane >> 2) + rr*8;
                const float qv0 = g_qs[(size_t)row * AGENTS + bx*4 + warpN*2];
                const float qv1 = g_qs[(size_t)row * AGENTS + bx*4 + warpN*2 + 1];
                float part[8];
                #pragma unroll
                for (int s = 0; s < 8; s++) part[s] = 0.f;
                #pragma unroll
                for (int nt = 0; nt < 8; nt++) {
                    const float qv = (nt < 4) ? qv0 : qv1;
                    #pragma unroll
                    for (int j = 0; j < 2; j++) {
                        const int col = warpN*64 + nt*8 + (lane & 3)*2 + j;
                        float v = acc[mt][nt][rr*2 + j] + sbias[col];
                        part[(nt & 3)*2 + j] = fmaf(qv, fabsf(v), part[(nt & 3)*2 + j]);
                    }
                }
                float* dst = g_part + ((size_t)slab * BS + row) * EMB;
                #pragma unroll
                for (int k4 = 0; k4 < 4; k4++) {
                    const int e = k4*8 + (lane & 3)*2;
                    *(float2*)(dst + e) = make_float2(part[k4*2], part[k4*2 + 1]);
                }
            }
        }
    } else {
        #pragma unroll
        for (int mt = 0; mt < 2; mt++) {
            #pragma unroll
            for (int rr = 0; rr < 2; rr++) {
                const int row = by*128 + warpM*32 + mt*16 + (lane >> 2) + rr*8;
                float* dst = g_ext + (size_t)row * 128;
                #pragma unroll
                for (int nt = 0; nt < 8; nt++) {
                    const int col = warpN*64 + nt*8 + (lane & 3)*2;
                    *(float2*)(dst + col) =
                        make_float2(acc[mt][nt][rr*2 + 0], acc[mt][nt][rr*2 + 1]);
                }
            }
        }
    }
}

// =============================================================================
// Final mixing (R13 version)
// =============================================================================
__global__ void __launch_bounds__(128) final_kernel(
    const float* __restrict__ bhb, const float* __restrict__ bhf,
    const float* __restrict__ bv1,
    const float* __restrict__ Wv2, const float* __restrict__ bv2,
    float* __restrict__ qtot)
{
    const int b = blockIdx.x * 4 + (threadIdx.x >> 5);
    const int e = threadIdx.x & 31;

    const float* ex = g_ext + (size_t)b * 128;
    float sb = ex[e] + bhb[e];
    float wf = fabsf(ex[32 + e] + bhf[e]);
    float rv = ex[64 + e] + bv1[e];
    rv = rv > 0.f ? rv : 0.f;

    float s = 0.f;
    #pragma unroll
    for (int sl = 0; sl < 64; sl++)
        s += g_part[((size_t)sl * BS + b) * EMB + e];
    float hp = s + sb;
    float hidden = hp > 0.f ? hp : expm1f(hp);
    float contrib = hidden * wf + rv * Wv2[e];
    #pragma unroll
    for (int o = 16; o > 0; o >>= 1)
        contrib += __shfl_down_sync(0xffffffffu, contrib, o);
    if (e == 0) qtot[b] = contrib + bv2[0];
}

// =============================================================================
extern "C" void kernel_launch(void* const* d_in, const int* in_sizes, int n_in,
                              void* d_out, int out_size)
{
    const float* obs    = (const float*)d_in[0];
    const float* states = (const float*)d_in[1];
    const float* W1  = (const float*)d_in[2];
    const float* b1  = (const float*)d_in[3];
    const float* W2  = (const float*)d_in[4];
    const float* b2  = (const float*)d_in[5];
    const float* W3  = (const float*)d_in[6];
    const float* b3  = (const float*)d_in[7];
    const float* Wh1 = (const float*)d_in[8];
    const float* bh1 = (const float*)d_in[9];
    const float* Whb = (const float*)d_in[10];
    const float* bhb = (const float*)d_in[11];
    const float* Whf = (const float*)d_in[12];
    const float* bhf = (const float*)d_in[13];
    const float* Wv1 = (const float*)d_in[14];
    const float* bv1 = (const float*)d_in[15];
    const float* Wv2 = (const float*)d_in[16];
    const float* bv2 = (const float*)d_in[17];
    float* out = (float*)d_out;

    cudaFuncSetAttribute(mlp_kernel, cudaFuncAttributeMaxDynamicSharedMemorySize, MLP_SMEM);
    cudaFuncSetAttribute(hyper_gemm_mma, cudaFuncAttributeMaxDynamicSharedMemorySize, GEMM_SMEM);

    float* act_dst;
    if (out_size >= (int)(BS + BS*AGENTS)) {
        act_dst = out + BS;
    } else {
        void* p = 0;
        cudaGetSymbolAddress(&p, g_act_fallback);
        act_dst = (float*)p;
    }

    // Strictly sequential, single stream (overlap regressed twice: L2 pollution).
    mlp_kernel<<<dim3(AGENTS, BS/MLP_BT), 512, MLP_SMEM>>>(
        obs, W1, b1, W2, b2, W3, b3, act_dst);
    conv_S_kernel<<<BS*SD/8/256, 256>>>(states);
    conv_W_kernel<<<4096, 256>>>(Wh1);
    conv_Wx_kernel<<<64, 256>>>(Whb, Whf, Wv1);
    hyper_gemm_mma<<<1056, 256, GEMM_SMEM>>>(bh1);
    final_kernel<<<BS/4, 128>>>(bhb, bhf, bv1, Wv2, bv2, out);
}

// round 15
// speedup vs baseline: 3.1746x; 1.0315x over previous
#include <cuda_runtime.h>
#include <cuda_fp16.h>
#include <stdint.h>
#include <math.h>

#define BS 4096
#define AGENTS 128
#define OBSD 128
#define ACT 8
#define SD 4096
#define EMB 32
#define H1 128
#define H2 64

// ---------------- scratch (static device globals; no allocation) ----------------
__device__ float g_qs[(size_t)BS * AGENTS];           // agent_qs [b][a]
__device__ float g_act_fallback[(size_t)BS * AGENTS];
__device__ float g_part[(size_t)64 * BS * EMB];       // GEMM partial sums [slab][b][e] 32MB
__device__ float g_ext[(size_t)BS * 128];             // raw states@{Whb|Whf|Wv1} dots (2MB)

// fp16 operands, plain row-major
__device__ __half g_A[(size_t)BS * SD];               // A [m][k] = states, fp16
__device__ __half g_B[(size_t)SD * SD];               // B [n][k] = Wh1[k][n], fp16
__device__ __half g_Bx[(size_t)128 * SD];             // Bx[n][k]: n<32 Whb, 32..63 Whf, 64..95 Wv1, 96..127 zero

// ============================ PTX helpers =====================================
__device__ __forceinline__ uint32_t smem_u32(const void* p) {
    uint32_t a;
    asm("{ .reg .u64 t; cvta.to.shared.u64 t, %1; cvt.u32.u64 %0, t; }" : "=r"(a) : "l"(p));
    return a;
}

__device__ __forceinline__ void cp16(uint32_t s, const void* g) {
    asm volatile("cp.async.cg.shared.global [%0], [%1], 16;" :: "r"(s), "l"(g));
}
#define CP_COMMIT() asm volatile("cp.async.commit_group;")
#define CP_WAIT1()  asm volatile("cp.async.wait_group 1;")

__device__ __forceinline__ void ldm4(uint32_t* r, uint32_t addr) {
    asm volatile("ldmatrix.sync.aligned.m8n8.x4.shared.b16 {%0,%1,%2,%3}, [%4];"
        : "=r"(r[0]), "=r"(r[1]), "=r"(r[2]), "=r"(r[3]) : "r"(addr));
}

__device__ __forceinline__ void mma_fp16(float* c, const uint32_t* a, const uint32_t* b) {
    asm volatile("mma.sync.aligned.m16n8k16.row.col.f32.f16.f16.f32 "
        "{%0,%1,%2,%3}, {%4,%5,%6,%7}, {%8,%9}, {%0,%1,%2,%3};"
        : "+f"(c[0]), "+f"(c[1]), "+f"(c[2]), "+f"(c[3])
        : "r"(a[0]), "r"(a[1]), "r"(a[2]), "r"(a[3]), "r"(b[0]), "r"(b[1]));
}

// ---- packed fp32x2 FMA (Blackwell; PTX-only) ----
__device__ __forceinline__ uint64_t pk2(float lo, float hi) {
    uint64_t r;
    asm("mov.b64 %0, {%1, %2};" : "=l"(r) : "f"(lo), "f"(hi));
    return r;
}
__device__ __forceinline__ void fma2(uint64_t& d, uint64_t a, uint64_t b) {
    asm("fma.rn.f32x2 %0, %1, %2, %0;" : "+l"(d) : "l"(a), "l"(b));
}
__device__ __forceinline__ float2 upk2(uint64_t v) {
    float2 f;
    asm("mov.b64 {%0, %1}, %2;" : "=f"(f.x), "=f"(f.y) : "l"(v));
    return f;
}

// =============================================================================
// Kernel 1: fused per-agent 3-layer MLP + max/argmax. (R14 version, at the
// f32x2 ceiling: BT=128, 512 threads, W1 in two halves)
// =============================================================================
#define MLP_BT 128
#define MLP_SMEM ((128*132 + 128*132 + 128*68 + 8192) * 4)

__global__ void __launch_bounds__(512) mlp_kernel(
    const float* __restrict__ obs,
    const float* __restrict__ W1, const float* __restrict__ b1,
    const float* __restrict__ W2, const float* __restrict__ b2,
    const float* __restrict__ W3, const float* __restrict__ b3,
    float* __restrict__ actions_out)
{
    extern __shared__ float sm[];
    float* obss = sm;                               // [128][132]
    float* x1s  = sm + 128*132;                     // [128][132]
    float* x2s  = sm + 2*128*132;                   // [128][68]
    float* ws   = sm + 2*128*132 + 128*68;          // 8192 floats (32KB)
    __shared__ float b1s[H1];
    __shared__ float b2s[H2];
    __shared__ float b3s[ACT];

    const int a   = blockIdx.x;
    const int b0  = blockIdx.y * MLP_BT;
    const int tid = threadIdx.x;

    if (tid < H1) b1s[tid] = b1[a*H1 + tid];
    if (tid < H2) b2s[tid] = b2[a*H2 + tid];
    if (tid < ACT) b3s[tid] = b3[a*ACT + tid];

    for (int i = tid; i < MLP_BT * (OBSD/4); i += 512) {
        int r  = i >> 5;
        int c4 = i & 31;
        float4 v = ((const float4*)(obs + ((size_t)(b0 + r) * AGENTS + a) * OBSD))[c4];
        *(float4*)(obss + r*132 + c4*4) = v;
    }

    #pragma unroll
    for (int h = 0; h < 2; h++) {
        for (int i = tid; i < 2048; i += 512) {
            int k = i >> 4, c4 = i & 15;
            *(float4*)(ws + k*64 + c4*4) =
                *(const float4*)(W1 + (size_t)a * OBSD * H1 + (size_t)k * H1 + h*64 + c4*4);
        }
        __syncthreads();

        const int ty = tid >> 4, tx = tid & 15;
        uint64_t acc01[4], acc23[4];
        #pragma unroll
        for (int i = 0; i < 4; i++) { acc01[i] = 0ull; acc23[i] = 0ull; }

        #pragma unroll 4
        for (int k = 0; k < OBSD; k++) {
            float a0 = obss[(ty*4+0)*132 + k];
            float a1 = obss[(ty*4+1)*132 + k];
            float a2 = obss[(ty*4+2)*132 + k];
            float a3 = obss[(ty*4+3)*132 + k];
            float4 w = *(const float4*)(ws + k*64 + tx*4);
            uint64_t w01 = pk2(w.x, w.y);
            uint64_t w23 = pk2(w.z, w.w);
            uint64_t aa;
            aa = pk2(a0, a0); fma2(acc01[0], aa, w01); fma2(acc23[0], aa, w23);
            aa = pk2(a1, a1); fma2(acc01[1], aa, w01); fma2(acc23[1], aa, w23);
            aa = pk2(a2, a2); fma2(acc01[2], aa, w01); fma2(acc23[2], aa, w23);
            aa = pk2(a3, a3); fma2(acc01[3], aa, w01); fma2(acc23[3], aa, w23);
        }
        #pragma unroll
        for (int i = 0; i < 4; i++) {
            float2 p0 = upk2(acc01[i]);
            float2 p1 = upk2(acc23[i]);
            float4 o;
            o.x = p0.x + b1s[h*64 + tx*4 + 0]; o.x = o.x > 0.f ? o.x : 0.f;
            o.y = p0.y + b1s[h*64 + tx*4 + 1]; o.y = o.y > 0.f ? o.y : 0.f;
            o.z = p1.x + b1s[h*64 + tx*4 + 2]; o.z = o.z > 0.f ? o.z : 0.f;
            o.w = p1.y + b1s[h*64 + tx*4 + 3]; o.w = o.w > 0.f ? o.w : 0.f;
            *(float4*)(x1s + (ty*4+i)*132 + h*64 + tx*4) = o;
        }
        __syncthreads();
    }

    for (int i = tid; i < 2048; i += 512) {
        ((float4*)ws)[i] = ((const float4*)(W2 + (size_t)a * H1 * H2))[i];
    }
    __syncthreads();

    {
        const int ty = tid >> 4, tx = tid & 15;
        uint64_t acc01[4], acc23[4];
        #pragma unroll
        for (int i = 0; i < 4; i++) { acc01[i] = 0ull; acc23[i] = 0ull; }

        #pragma unroll 4
        for (int k = 0; k < H1; k++) {
            float a0 = x1s[(ty*4+0)*132 + k];
            float a1 = x1s[(ty*4+1)*132 + k];
            float a2 = x1s[(ty*4+2)*132 + k];
            float a3 = x1s[(ty*4+3)*132 + k];
            float4 w = *(const float4*)(ws + k*H2 + tx*4);
            uint64_t w01 = pk2(w.x, w.y);
            uint64_t w23 = pk2(w.z, w.w);
            uint64_t aa;
            aa = pk2(a0, a0); fma2(acc01[0], aa, w01); fma2(acc23[0], aa, w23);
            aa = pk2(a1, a1); fma2(acc01[1], aa, w01); fma2(acc23[1], aa, w23);
            aa = pk2(a2, a2); fma2(acc01[2], aa, w01); fma2(acc23[2], aa, w23);
            aa = pk2(a3, a3); fma2(acc01[3], aa, w01); fma2(acc23[3], aa, w23);
        }
        #pragma unroll
        for (int i = 0; i < 4; i++) {
            float2 p0 = upk2(acc01[i]);
            float2 p1 = upk2(acc23[i]);
            float4 o;
            o.x = p0.x + b2s[tx*4 + 0]; o.x = o.x > 0.f ? o.x : 0.f;
            o.y = p0.y + b2s[tx*4 + 1]; o.y = o.y > 0.f ? o.y : 0.f;
            o.z = p1.x + b2s[tx*4 + 2]; o.z = o.z > 0.f ? o.z : 0.f;
            o.w = p1.y + b2s[tx*4 + 3]; o.w = o.w > 0.f ? o.w : 0.f;
            *(float4*)(x2s + (ty*4+i)*68 + tx*4) = o;
        }
    }
    __syncthreads();

    if (tid < 128) ((float4*)ws)[tid] = ((const float4*)(W3 + (size_t)a * H2 * ACT))[tid];
    __syncthreads();

    if (tid < MLP_BT) {
        const int r = tid;
        float acc[8];
        #pragma unroll
        for (int c = 0; c < 8; c++) acc[c] = 0.f;
        #pragma unroll 4
        for (int k = 0; k < H2; k++) {
            float x = x2s[r*68 + k];
            float4 w0  = *(const float4*)(ws + k*ACT);
            float4 w1v = *(const float4*)(ws + k*ACT + 4);
            acc[0] = fmaf(x, w0.x, acc[0]);
            acc[1] = fmaf(x, w0.y, acc[1]);
            acc[2] = fmaf(x, w0.z, acc[2]);
            acc[3] = fmaf(x, w0.w, acc[3]);
            acc[4] = fmaf(x, w1v.x, acc[4]);
            acc[5] = fmaf(x, w1v.y, acc[5]);
            acc[6] = fmaf(x, w1v.z, acc[6]);
            acc[7] = fmaf(x, w1v.w, acc[7]);
        }
        float best = acc[0] + b3s[0];
        int bi = 0;
        #pragma unroll
        for (int c = 1; c < 8; c++) {
            float q = acc[c] + b3s[c];
            if (q > best) { best = q; bi = c; }
        }
        g_qs[(size_t)(b0 + r) * AGENTS + a]        = best;
        actions_out[(size_t)(b0 + r) * AGENTS + a] = (float)bi;
    }
}

// =============================================================================
// Conversion: states -> single fp16 row-major
// =============================================================================
__global__ void __launch_bounds__(256) conv_S_kernel(const float* __restrict__ S)
{
    const size_t id = (size_t)blockIdx.x * 256 + threadIdx.x;
    const float4* src = (const float4*)(S + id * 8);
    float4 v0 = src[0], v1 = src[1];
    float x[8] = {v0.x, v0.y, v0.z, v0.w, v1.x, v1.y, v1.z, v1.w};
    uint32_t hw[4];
    #pragma unroll
    for (int p = 0; p < 4; p++) {
        __half h0 = __float2half(x[p*2]);
        __half h1 = __float2half(x[p*2+1]);
        hw[p] = (uint32_t)__half_as_ushort(h0) | ((uint32_t)__half_as_ushort(h1) << 16);
    }
    ((uint4*)g_A)[id] = make_uint4(hw[0], hw[1], hw[2], hw[3]);
}

// =============================================================================
// Conversion + transpose: Wh1[k][n] -> B[n][k] single fp16 (64x64 smem tiles)
// =============================================================================
__global__ void __launch_bounds__(256) conv_W_kernel(const float* __restrict__ Wh1)
{
    __shared__ float tile[64][65];
    const int kt = blockIdx.x & 63;
    const int nt = blockIdx.x >> 6;
    const int tid = threadIdx.x;

    #pragma unroll
    for (int p = 0; p < 16; p++) {
        int idx = p * 256 + tid;
        int r = idx >> 6, c = idx & 63;
        tile[r][c] = Wh1[(size_t)(kt*64 + r) * SD + nt*64 + c];
    }
    __syncthreads();

    #pragma unroll
    for (int p = 0; p < 2; p++) {
        int id = p * 256 + tid;
        int n = id >> 3, kc = id & 7;
        uint32_t hw[4];
        #pragma unroll
        for (int q = 0; q < 4; q++) {
            __half h0 = __float2half(tile[kc*8 + q*2][n]);
            __half h1 = __float2half(tile[kc*8 + q*2 + 1][n]);
            hw[q] = (uint32_t)__half_as_ushort(h0) | ((uint32_t)__half_as_ushort(h1) << 16);
        }
        size_t off = ((size_t)(nt*64 + n) * SD + kt*64 + kc*8) / 8;
        ((uint4*)g_B)[off] = make_uint4(hw[0], hw[1], hw[2], hw[3]);
    }
}

// =============================================================================
// Conversion + transpose of the skinny weights into g_Bx[n][k]
// =============================================================================
__global__ void __launch_bounds__(256) conv_Wx_kernel(
    const float* __restrict__ Whb,
    const float* __restrict__ Whf,
    const float* __restrict__ Wv1)
{
    __shared__ float tile[64][100];
    const int kt = blockIdx.x;
    const int tid = threadIdx.x;

    for (int i = tid; i < 64*32; i += 256) {
        int k = i >> 5, c = i & 31;
        tile[k][c]      = Whb[(size_t)(kt*64 + k) * EMB + c];
        tile[k][32 + c] = Whf[(size_t)(kt*64 + k) * EMB + c];
        tile[k][64 + c] = Wv1[(size_t)(kt*64 + k) * EMB + c];
    }
    __syncthreads();

    for (int i = tid; i < 128*64; i += 256) {
        int n = i >> 6, kk = i & 63;
        float v = (n < 96) ? tile[kk][n] : 0.f;
        g_Bx[(size_t)n * SD + kt*64 + kk] = __float2half(v);
    }
}

// =============================================================================
// mma.sync fp16 single-pass GEMM, BK=64, 3 stages, 2 CTAs/SM. Grid 1056.
// Stage layout per operand: 128 rows x 9 float4 (8 data + 1 pad) = 18KB.
// 9m mod 8 = m mod 8 -> ldmatrix stays conflict-free. 64 K-iters (half the
// barriers of BK=32), 4 k-steps per iter. MMA k-order unchanged -> bitwise-
// identical accumulators vs R14.
// =============================================================================
#define GSTAGES 3
#define OP_BYTES 18432                 // 128 * 9 * 16
#define STAGE_BYTES (2 * OP_BYTES)     // 36864
#define GEMM_SMEM (GSTAGES * STAGE_BYTES)   // 110592 (108KB)
#define NKT (SD / 64)                  // 64

__global__ void __launch_bounds__(256, 2) hyper_gemm_mma(const float* __restrict__ bh1)
{
    extern __shared__ char gsm[];
    __shared__ float sbias[128];

    const int tid = threadIdx.x;
    const int wid = tid >> 5, lane = tid & 31;
    const int warpM = wid & 3, warpN = wid >> 2;

    const int bidx = blockIdx.x;
    const bool ext = (bidx >= 1024);
    const int bx = ext ? 32 : (bidx >> 5);
    const int by = ext ? (bidx - 1024) : (bidx & 31);

    const uint32_t sbase = smem_u32(gsm);

    if (!ext && tid < 128) sbias[tid] = bh1[bx*128 + tid];

    const char* A_g = (const char*)(g_A + (size_t)(by*128) * SD);
    const char* B_g = ext ? (const char*)g_Bx
                          : (const char*)(g_B + (size_t)(bx*128) * SD);

    // cp.async: 1024 16B-chunks per operand per stage; 256 threads x 4 chunks.
    // chunk id: m = id>>3 (row 0..127), c = id&7 (16B col 0..7)
    const int mA[4] = { tid >> 3, (tid + 256) >> 3, (tid + 512) >> 3, (tid + 768) >> 3 };
    const int cA[4] = { tid & 7,  (tid + 256) & 7,  (tid + 512) & 7,  (tid + 768) & 7 };

    #define ISSUE_STAGE(stg, kt_) do { \
        const uint32_t sb_ = sbase + (stg) * STAGE_BYTES; \
        _Pragma("unroll") \
        for (int q = 0; q < 4; q++) { \
            const uint32_t so_ = (uint32_t)(mA[q]*9 + cA[q]) * 16; \
            const size_t gg_ = ((size_t)mA[q] * SD + (size_t)(kt_)*64 + cA[q]*8) * 2; \
            cp16(sb_ + so_, A_g + gg_); \
            cp16(sb_ + OP_BYTES + so_, B_g + gg_); \
        } \
        CP_COMMIT(); \
    } while (0)

    // ldmatrix lane offsets: base per tile, +ks*32B per k-step (ks 0..3)
    uint32_t offA[2], offB[4];
    {
        const int am = warpM*32 + (lane & 7) + ((lane >> 3) & 1) * 8;
        #pragma unroll
        for (int mt = 0; mt < 2; mt++)
            offA[mt] = (uint32_t)((am + mt*16)*9 + (lane >> 4)) * 16;
        const int bn = warpN*64 + (lane & 7) + ((lane >> 4) & 1) * 8;
        #pragma unroll
        for (int ntp = 0; ntp < 4; ntp++)
            offB[ntp] = (uint32_t)((bn + ntp*16)*9 + ((lane >> 3) & 1)) * 16;
    }

    float acc[2][8][4];
    #pragma unroll
    for (int mt = 0; mt < 2; mt++)
        #pragma unroll
        for (int nt = 0; nt < 8; nt++)
            #pragma unroll
            for (int q = 0; q < 4; q++) acc[mt][nt][q] = 0.f;

    // prologue: 2 stages ahead
    ISSUE_STAGE(0, 0);
    ISSUE_STAGE(1, 1);

    for (int kt = 0; kt < NKT; kt++) {
        CP_WAIT1();
        __syncthreads();

        if (kt + 2 < NKT) ISSUE_STAGE((kt + 2) % GSTAGES, kt + 2);

        const uint32_t stg = sbase + (kt % GSTAGES) * STAGE_BYTES;
        const uint32_t aOp = stg;
        const uint32_t bOp = stg + OP_BYTES;

        #pragma unroll
        for (int ks = 0; ks < 4; ks++) {
            const uint32_t ko = (uint32_t)ks * 32;
            uint32_t aa[2][4], bb[8][2];
            #pragma unroll
            for (int mt = 0; mt < 2; mt++) {
                ldm4(aa[mt], aOp + offA[mt] + ko);
            }
            #pragma unroll
            for (int ntp = 0; ntp < 4; ntp++) {
                uint32_t r[4];
                ldm4(r, bOp + offB[ntp] + ko);
                bb[2*ntp][0] = r[0]; bb[2*ntp][1] = r[1];
                bb[2*ntp+1][0] = r[2]; bb[2*ntp+1][1] = r[3];
            }
            #pragma unroll
            for (int mt = 0; mt < 2; mt++)
                #pragma unroll
                for (int nt = 0; nt < 8; nt++) {
                    mma_fp16(acc[mt][nt], aa[mt], bb[nt]);
                }
        }
        __syncthreads();
    }

    if (!ext) {
        const int slab = bx*2 + warpN;
        #pragma unroll
        for (int mt = 0; mt < 2; mt++) {
            #pragma unroll
            for (int rr = 0; rr < 2; rr++) {
                const int row = by*128 + warpM*32 + mt*16 + (lane >> 2) + rr*8;
                const float qv0 = g_qs[(size_t)row * AGENTS + bx*4 + warpN*2];
                const float qv1 = g_qs[(size_t)row * AGENTS + bx*4 + warpN*2 + 1];
                float part[8];
                #pragma unroll
                for (int s = 0; s < 8; s++) part[s] = 0.f;
                #pragma unroll
                for (int nt = 0; nt < 8; nt++) {
                    const float qv = (nt < 4) ? qv0 : qv1;
                    #pragma unroll
                    for (int j = 0; j < 2; j++) {
                        const int col = warpN*64 + nt*8 + (lane & 3)*2 + j;
                        float v = acc[mt][nt][rr*2 + j] + sbias[col];
                        part[(nt & 3)*2 + j] = fmaf(qv, fabsf(v), part[(nt & 3)*2 + j]);
                    }
                }
                float* dst = g_part + ((size_t)slab * BS + row) * EMB;
                #pragma unroll
                for (int k4 = 0; k4 < 4; k4++) {
                    const int e = k4*8 + (lane & 3)*2;
                    *(float2*)(dst + e) = make_float2(part[k4*2], part[k4*2 + 1]);
                }
            }
        }
    } else {
        #pragma unroll
        for (int mt = 0; mt < 2; mt++) {
            #pragma unroll
            for (int rr = 0; rr < 2; rr++) {
                const int row = by*128 + warpM*32 + mt*16 + (lane >> 2) + rr*8;
                float* dst = g_ext + (size_t)row * 128;
                #pragma unroll
                for (int nt = 0; nt < 8; nt++) {
                    const int col = warpN*64 + nt*8 + (lane & 3)*2;
                    *(float2*)(dst + col) =
                        make_float2(acc[mt][nt][rr*2 + 0], acc[mt][nt][rr*2 + 1]);
                }
            }
        }
    }
}

// =============================================================================
// Final mixing (R13 version)
// =============================================================================
__global__ void __launch_bounds__(128) final_kernel(
    const float* __restrict__ bhb, const float* __restrict__ bhf,
    const float* __restrict__ bv1,
    const float* __restrict__ Wv2, const float* __restrict__ bv2,
    float* __restrict__ qtot)
{
    const int b = blockIdx.x * 4 + (threadIdx.x >> 5);
    const int e = threadIdx.x & 31;

    const float* ex = g_ext + (size_t)b * 128;
    float sb = ex[e] + bhb[e];
    float wf = fabsf(ex[32 + e] + bhf[e]);
    float rv = ex[64 + e] + bv1[e];
    rv = rv > 0.f ? rv : 0.f;

    float s = 0.f;
    #pragma unroll
    for (int sl = 0; sl < 64; sl++)
        s += g_part[((size_t)sl * BS + b) * EMB + e];
    float hp = s + sb;
    float hidden = hp > 0.f ? hp : expm1f(hp);
    float contrib = hidden * wf + rv * Wv2[e];
    #pragma unroll
    for (int o = 16; o > 0; o >>= 1)
        contrib += __shfl_down_sync(0xffffffffu, contrib, o);
    if (e == 0) qtot[b] = contrib + bv2[0];
}

// =============================================================================
extern "C" void kernel_launch(void* const* d_in, const int* in_sizes, int n_in,
                              void* d_out, int out_size)
{
    const float* obs    = (const float*)d_in[0];
    const float* states = (const float*)d_in[1];
    const float* W1  = (const float*)d_in[2];
    const float* b1  = (const float*)d_in[3];
    const float* W2  = (const float*)d_in[4];
    const float* b2  = (const float*)d_in[5];
    const float* W3  = (const float*)d_in[6];
    const float* b3  = (const float*)d_in[7];
    const float* Wh1 = (const float*)d_in[8];
    const float* bh1 = (const float*)d_in[9];
    const float* Whb = (const float*)d_in[10];
    const float* bhb = (const float*)d_in[11];
    const float* Whf = (const float*)d_in[12];
    const float* bhf = (const float*)d_in[13];
    const float* Wv1 = (const float*)d_in[14];
    const float* bv1 = (const float*)d_in[15];
    const float* Wv2 = (const float*)d_in[16];
    const float* bv2 = (const float*)d_in[17];
    float* out = (float*)d_out;

    cudaFuncSetAttribute(mlp_kernel, cudaFuncAttributeMaxDynamicSharedMemorySize, MLP_SMEM);
    cudaFuncSetAttribute(hyper_gemm_mma, cudaFuncAttributeMaxDynamicSharedMemorySize, GEMM_SMEM);

    float* act_dst;
    if (out_size >= (int)(BS + BS*AGENTS)) {
        act_dst = out + BS;
    } else {
        void* p = 0;
        cudaGetSymbolAddress(&p, g_act_fallback);
        act_dst = (float*)p;
    }

    // Strictly sequential, single stream (overlap regressed twice: L2 pollution).
    mlp_kernel<<<dim3(AGENTS, BS/MLP_BT), 512, MLP_SMEM>>>(
        obs, W1, b1, W2, b2, W3, b3, act_dst);
    conv_S_kernel<<<BS*SD/8/256, 256>>>(states);
    conv_W_kernel<<<4096, 256>>>(Wh1);
    conv_Wx_kernel<<<64, 256>>>(Whb, Whf, Wv1);
    hyper_gemm_mma<<<1056, 256, GEMM_SMEM>>>(bh1);
    final_kernel<<<BS/4, 128>>>(bhb, bhf, bv1, Wv2, bv2, out);
}

// round 16
// speedup vs baseline: 3.1969x; 1.0070x over previous
#include <cuda_runtime.h>
#include <cuda_fp16.h>
#include <stdint.h>
#include <math.h>

#define BS 4096
#define AGENTS 128
#define OBSD 128
#define ACT 8
#define SD 4096
#define EMB 32
#define H1 128
#define H2 64

// ---------------- scratch (static device globals; no allocation) ----------------
__device__ float g_qs[(size_t)BS * AGENTS];           // agent_qs [b][a]
__device__ float g_act_fallback[(size_t)BS * AGENTS];
__device__ float g_part[(size_t)64 * BS * EMB];       // GEMM partial sums [slab][b][e] 32MB
__device__ float g_ext[(size_t)BS * 128];             // raw states@{Whb|Whf|Wv1} dots (2MB)

// fp16 operands, plain row-major
__device__ __half g_A[(size_t)BS * SD];               // A [m][k] = states, fp16
__device__ __half g_B[(size_t)SD * SD];               // B [n][k] = Wh1[k][n], fp16
__device__ __half g_Bx[(size_t)128 * SD];             // Bx[n][k]: n<32 Whb, 32..63 Whf, 64..95 Wv1, 96..127 zero

// ============================ PTX helpers =====================================
__device__ __forceinline__ uint32_t smem_u32(const void* p) {
    uint32_t a;
    asm("{ .reg .u64 t; cvta.to.shared.u64 t, %1; cvt.u32.u64 %0, t; }" : "=r"(a) : "l"(p));
    return a;
}

__device__ __forceinline__ void cp16(uint32_t s, const void* g) {
    asm volatile("cp.async.cg.shared.global [%0], [%1], 16;" :: "r"(s), "l"(g));
}
#define CP_COMMIT() asm volatile("cp.async.commit_group;")
#define CP_WAIT1()  asm volatile("cp.async.wait_group 1;")

__device__ __forceinline__ void ldm4(uint32_t* r, uint32_t addr) {
    asm volatile("ldmatrix.sync.aligned.m8n8.x4.shared.b16 {%0,%1,%2,%3}, [%4];"
        : "=r"(r[0]), "=r"(r[1]), "=r"(r[2]), "=r"(r[3]) : "r"(addr));
}

__device__ __forceinline__ void mma_fp16(float* c, const uint32_t* a, const uint32_t* b) {
    asm volatile("mma.sync.aligned.m16n8k16.row.col.f32.f16.f16.f32 "
        "{%0,%1,%2,%3}, {%4,%5,%6,%7}, {%8,%9}, {%0,%1,%2,%3};"
        : "+f"(c[0]), "+f"(c[1]), "+f"(c[2]), "+f"(c[3])
        : "r"(a[0]), "r"(a[1]), "r"(a[2]), "r"(a[3]), "r"(b[0]), "r"(b[1]));
}

// ---- packed fp32x2 FMA (Blackwell; PTX-only) ----
__device__ __forceinline__ uint64_t pk2(float lo, float hi) {
    uint64_t r;
    asm("mov.b64 %0, {%1, %2};" : "=l"(r) : "f"(lo), "f"(hi));
    return r;
}
__device__ __forceinline__ void fma2(uint64_t& d, uint64_t a, uint64_t b) {
    asm("fma.rn.f32x2 %0, %1, %2, %0;" : "+l"(d) : "l"(a), "l"(b));
}
__device__ __forceinline__ float2 upk2(uint64_t v) {
    float2 f;
    asm("mov.b64 {%0, %1}, %2;" : "=f"(f.x), "=f"(f.y) : "l"(v));
    return f;
}

// =============================================================================
// Kernel 1: fused per-agent 3-layer MLP + max/argmax. (R14/R15 version, at the
// f32x2 ceiling: BT=128, 512 threads, W1 in two halves)
// =============================================================================
#define MLP_BT 128
#define MLP_SMEM ((128*132 + 128*132 + 128*68 + 8192) * 4)

__global__ void __launch_bounds__(512) mlp_kernel(
    const float* __restrict__ obs,
    const float* __restrict__ W1, const float* __restrict__ b1,
    const float* __restrict__ W2, const float* __restrict__ b2,
    const float* __restrict__ W3, const float* __restrict__ b3,
    float* __restrict__ actions_out)
{
    extern __shared__ float sm[];
    float* obss = sm;                               // [128][132]
    float* x1s  = sm + 128*132;                     // [128][132]
    float* x2s  = sm + 2*128*132;                   // [128][68]
    float* ws   = sm + 2*128*132 + 128*68;          // 8192 floats (32KB)
    __shared__ float b1s[H1];
    __shared__ float b2s[H2];
    __shared__ float b3s[ACT];

    const int a   = blockIdx.x;
    const int b0  = blockIdx.y * MLP_BT;
    const int tid = threadIdx.x;

    if (tid < H1) b1s[tid] = b1[a*H1 + tid];
    if (tid < H2) b2s[tid] = b2[a*H2 + tid];
    if (tid < ACT) b3s[tid] = b3[a*ACT + tid];

    for (int i = tid; i < MLP_BT * (OBSD/4); i += 512) {
        int r  = i >> 5;
        int c4 = i & 31;
        float4 v = ((const float4*)(obs + ((size_t)(b0 + r) * AGENTS + a) * OBSD))[c4];
        *(float4*)(obss + r*132 + c4*4) = v;
    }

    #pragma unroll
    for (int h = 0; h < 2; h++) {
        for (int i = tid; i < 2048; i += 512) {
            int k = i >> 4, c4 = i & 15;
            *(float4*)(ws + k*64 + c4*4) =
                *(const float4*)(W1 + (size_t)a * OBSD * H1 + (size_t)k * H1 + h*64 + c4*4);
        }
        __syncthreads();

        const int ty = tid >> 4, tx = tid & 15;
        uint64_t acc01[4], acc23[4];
        #pragma unroll
        for (int i = 0; i < 4; i++) { acc01[i] = 0ull; acc23[i] = 0ull; }

        #pragma unroll 4
        for (int k = 0; k < OBSD; k++) {
            float a0 = obss[(ty*4+0)*132 + k];
            float a1 = obss[(ty*4+1)*132 + k];
            float a2 = obss[(ty*4+2)*132 + k];
            float a3 = obss[(ty*4+3)*132 + k];
            float4 w = *(const float4*)(ws + k*64 + tx*4);
            uint64_t w01 = pk2(w.x, w.y);
            uint64_t w23 = pk2(w.z, w.w);
            uint64_t aa;
            aa = pk2(a0, a0); fma2(acc01[0], aa, w01); fma2(acc23[0], aa, w23);
            aa = pk2(a1, a1); fma2(acc01[1], aa, w01); fma2(acc23[1], aa, w23);
            aa = pk2(a2, a2); fma2(acc01[2], aa, w01); fma2(acc23[2], aa, w23);
            aa = pk2(a3, a3); fma2(acc01[3], aa, w01); fma2(acc23[3], aa, w23);
        }
        #pragma unroll
        for (int i = 0; i < 4; i++) {
            float2 p0 = upk2(acc01[i]);
            float2 p1 = upk2(acc23[i]);
            float4 o;
            o.x = p0.x + b1s[h*64 + tx*4 + 0]; o.x = o.x > 0.f ? o.x : 0.f;
            o.y = p0.y + b1s[h*64 + tx*4 + 1]; o.y = o.y > 0.f ? o.y : 0.f;
            o.z = p1.x + b1s[h*64 + tx*4 + 2]; o.z = o.z > 0.f ? o.z : 0.f;
            o.w = p1.y + b1s[h*64 + tx*4 + 3]; o.w = o.w > 0.f ? o.w : 0.f;
            *(float4*)(x1s + (ty*4+i)*132 + h*64 + tx*4) = o;
        }
        __syncthreads();
    }

    for (int i = tid; i < 2048; i += 512) {
        ((float4*)ws)[i] = ((const float4*)(W2 + (size_t)a * H1 * H2))[i];
    }
    __syncthreads();

    {
        const int ty = tid >> 4, tx = tid & 15;
        uint64_t acc01[4], acc23[4];
        #pragma unroll
        for (int i = 0; i < 4; i++) { acc01[i] = 0ull; acc23[i] = 0ull; }

        #pragma unroll 4
        for (int k = 0; k < H1; k++) {
            float a0 = x1s[(ty*4+0)*132 + k];
            float a1 = x1s[(ty*4+1)*132 + k];
            float a2 = x1s[(ty*4+2)*132 + k];
            float a3 = x1s[(ty*4+3)*132 + k];
            float4 w = *(const float4*)(ws + k*H2 + tx*4);
            uint64_t w01 = pk2(w.x, w.y);
            uint64_t w23 = pk2(w.z, w.w);
            uint64_t aa;
            aa = pk2(a0, a0); fma2(acc01[0], aa, w01); fma2(acc23[0], aa, w23);
            aa = pk2(a1, a1); fma2(acc01[1], aa, w01); fma2(acc23[1], aa, w23);
            aa = pk2(a2, a2); fma2(acc01[2], aa, w01); fma2(acc23[2], aa, w23);
            aa = pk2(a3, a3); fma2(acc01[3], aa, w01); fma2(acc23[3], aa, w23);
        }
        #pragma unroll
        for (int i = 0; i < 4; i++) {
            float2 p0 = upk2(acc01[i]);
            float2 p1 = upk2(acc23[i]);
            float4 o;
            o.x = p0.x + b2s[tx*4 + 0]; o.x = o.x > 0.f ? o.x : 0.f;
            o.y = p0.y + b2s[tx*4 + 1]; o.y = o.y > 0.f ? o.y : 0.f;
            o.z = p1.x + b2s[tx*4 + 2]; o.z = o.z > 0.f ? o.z : 0.f;
            o.w = p1.y + b2s[tx*4 + 3]; o.w = o.w > 0.f ? o.w : 0.f;
            *(float4*)(x2s + (ty*4+i)*68 + tx*4) = o;
        }
    }
    __syncthreads();

    if (tid < 128) ((float4*)ws)[tid] = ((const float4*)(W3 + (size_t)a * H2 * ACT))[tid];
    __syncthreads();

    if (tid < MLP_BT) {
        const int r = tid;
        float acc[8];
        #pragma unroll
        for (int c = 0; c < 8; c++) acc[c] = 0.f;
        #pragma unroll 4
        for (int k = 0; k < H2; k++) {
            float x = x2s[r*68 + k];
            float4 w0  = *(const float4*)(ws + k*ACT);
            float4 w1v = *(const float4*)(ws + k*ACT + 4);
            acc[0] = fmaf(x, w0.x, acc[0]);
            acc[1] = fmaf(x, w0.y, acc[1]);
            acc[2] = fmaf(x, w0.z, acc[2]);
            acc[3] = fmaf(x, w0.w, acc[3]);
            acc[4] = fmaf(x, w1v.x, acc[4]);
            acc[5] = fmaf(x, w1v.y, acc[5]);
            acc[6] = fmaf(x, w1v.z, acc[6]);
            acc[7] = fmaf(x, w1v.w, acc[7]);
        }
        float best = acc[0] + b3s[0];
        int bi = 0;
        #pragma unroll
        for (int c = 1; c < 8; c++) {
            float q = acc[c] + b3s[c];
            if (q > best) { best = q; bi = c; }
        }
        g_qs[(size_t)(b0 + r) * AGENTS + a]        = best;
        actions_out[(size_t)(b0 + r) * AGENTS + a] = (float)bi;
    }
}

// =============================================================================
// Merged conversion kernel (one launch, block-range dispatch):
//   blocks [0, 8192):        states -> g_A fp16 (elementwise)
//   blocks [8192, 12288):    Wh1[k][n] -> g_B[n][k] fp16 (64x64 transpose)
//   blocks [12288, 12352):   {Whb|Whf|Wv1} -> g_Bx[n][k] fp16 (+zero pad)
// =============================================================================
#define CONV_S_BLOCKS (BS*SD/8/256)        // 8192
#define CONV_W_BLOCKS 4096
#define CONV_WX_BLOCKS 64
#define CONV_TOTAL (CONV_S_BLOCKS + CONV_W_BLOCKS + CONV_WX_BLOCKS)

__global__ void __launch_bounds__(256) conv_all_kernel(
    const float* __restrict__ S,
    const float* __restrict__ Wh1,
    const float* __restrict__ Whb,
    const float* __restrict__ Whf,
    const float* __restrict__ Wv1)
{
    __shared__ float tsm[6400];       // conv_W: [64][65]; conv_Wx: [64][100]
    const int bid = blockIdx.x;
    const int tid = threadIdx.x;

    if (bid < CONV_S_BLOCKS) {
        // ---- states -> fp16 ----
        const size_t id = (size_t)bid * 256 + tid;
        const float4* src = (const float4*)(S + id * 8);
        float4 v0 = src[0], v1 = src[1];
        float x[8] = {v0.x, v0.y, v0.z, v0.w, v1.x, v1.y, v1.z, v1.w};
        uint32_t hw[4];
        #pragma unroll
        for (int p = 0; p < 4; p++) {
            __half h0 = __float2half(x[p*2]);
            __half h1 = __float2half(x[p*2+1]);
            hw[p] = (uint32_t)__half_as_ushort(h0) | ((uint32_t)__half_as_ushort(h1) << 16);
        }
        ((uint4*)g_A)[id] = make_uint4(hw[0], hw[1], hw[2], hw[3]);
    } else if (bid < CONV_S_BLOCKS + CONV_W_BLOCKS) {
        // ---- Wh1 transpose -> g_B fp16 ----
        const int wb = bid - CONV_S_BLOCKS;
        const int kt = wb & 63;
        const int nt = wb >> 6;

        #pragma unroll
        for (int p = 0; p < 16; p++) {
            int idx = p * 256 + tid;
            int r = idx >> 6, c = idx & 63;
            tsm[r*65 + c] = Wh1[(size_t)(kt*64 + r) * SD + nt*64 + c];
        }
        __syncthreads();

        #pragma unroll
        for (int p = 0; p < 2; p++) {
            int id = p * 256 + tid;
            int n = id >> 3, kc = id & 7;
            uint32_t hw[4];
            #pragma unroll
            for (int q = 0; q < 4; q++) {
                __half h0 = __float2half(tsm[(kc*8 + q*2)*65 + n]);
                __half h1 = __float2half(tsm[(kc*8 + q*2 + 1)*65 + n]);
                hw[q] = (uint32_t)__half_as_ushort(h0) | ((uint32_t)__half_as_ushort(h1) << 16);
            }
            size_t off = ((size_t)(nt*64 + n) * SD + kt*64 + kc*8) / 8;
            ((uint4*)g_B)[off] = make_uint4(hw[0], hw[1], hw[2], hw[3]);
        }
    } else {
        // ---- skinny weights -> g_Bx fp16 ----
        const int kt = bid - CONV_S_BLOCKS - CONV_W_BLOCKS;

        for (int i = tid; i < 64*32; i += 256) {
            int k = i >> 5, c = i & 31;
            tsm[k*100 + c]      = Whb[(size_t)(kt*64 + k) * EMB + c];
            tsm[k*100 + 32 + c] = Whf[(size_t)(kt*64 + k) * EMB + c];
            tsm[k*100 + 64 + c] = Wv1[(size_t)(kt*64 + k) * EMB + c];
        }
        __syncthreads();

        for (int i = tid; i < 128*64; i += 256) {
            int n = i >> 6, kk = i & 63;
            float v = (n < 96) ? tsm[kk*100 + n] : 0.f;
            g_Bx[(size_t)n * SD + kt*64 + kk] = __float2half(v);
        }
    }
}

// =============================================================================
// mma.sync fp16 single-pass GEMM, BK=64, 3 stages, 2 CTAs/SM. Grid 1056.
// Single __syncthreads per K-iter (trailing barrier removed: with 3 stages
// the issue target (kt+2)%3 never collides with in-flight reads within the
// one-iteration warp-skew window the top barrier enforces).
// =============================================================================
#define GSTAGES 3
#define OP_BYTES 18432                 // 128 * 9 * 16
#define STAGE_BYTES (2 * OP_BYTES)     // 36864
#define GEMM_SMEM (GSTAGES * STAGE_BYTES)   // 110592 (108KB)
#define NKT (SD / 64)                  // 64

__global__ void __launch_bounds__(256, 2) hyper_gemm_mma(const float* __restrict__ bh1)
{
    extern __shared__ char gsm[];
    __shared__ float sbias[128];

    const int tid = threadIdx.x;
    const int wid = tid >> 5, lane = tid & 31;
    const int warpM = wid & 3, warpN = wid >> 2;

    const int bidx = blockIdx.x;
    const bool ext = (bidx >= 1024);
    const int bx = ext ? 32 : (bidx >> 5);
    const int by = ext ? (bidx - 1024) : (bidx & 31);

    const uint32_t sbase = smem_u32(gsm);

    if (!ext && tid < 128) sbias[tid] = bh1[bx*128 + tid];

    const char* A_g = (const char*)(g_A + (size_t)(by*128) * SD);
    const char* B_g = ext ? (const char*)g_Bx
                          : (const char*)(g_B + (size_t)(bx*128) * SD);

    const int mA[4] = { tid >> 3, (tid + 256) >> 3, (tid + 512) >> 3, (tid + 768) >> 3 };
    const int cA[4] = { tid & 7,  (tid + 256) & 7,  (tid + 512) & 7,  (tid + 768) & 7 };

    #define ISSUE_STAGE(stg, kt_) do { \
        const uint32_t sb_ = sbase + (stg) * STAGE_BYTES; \
        _Pragma("unroll") \
        for (int q = 0; q < 4; q++) { \
            const uint32_t so_ = (uint32_t)(mA[q]*9 + cA[q]) * 16; \
            const size_t gg_ = ((size_t)mA[q] * SD + (size_t)(kt_)*64 + cA[q]*8) * 2; \
            cp16(sb_ + so_, A_g + gg_); \
            cp16(sb_ + OP_BYTES + so_, B_g + gg_); \
        } \
        CP_COMMIT(); \
    } while (0)

    uint32_t offA[2], offB[4];
    {
        const int am = warpM*32 + (lane & 7) + ((lane >> 3) & 1) * 8;
        #pragma unroll
        for (int mt = 0; mt < 2; mt++)
            offA[mt] = (uint32_t)((am + mt*16)*9 + (lane >> 4)) * 16;
        const int bn = warpN*64 + (lane & 7) + ((lane >> 4) & 1) * 8;
        #pragma unroll
        for (int ntp = 0; ntp < 4; ntp++)
            offB[ntp] = (uint32_t)((bn + ntp*16)*9 + ((lane >> 3) & 1)) * 16;
    }

    float acc[2][8][4];
    #pragma unroll
    for (int mt = 0; mt < 2; mt++)
        #pragma unroll
        for (int nt = 0; nt < 8; nt++)
            #pragma unroll
            for (int q = 0; q < 4; q++) acc[mt][nt][q] = 0.f;

    ISSUE_STAGE(0, 0);
    ISSUE_STAGE(1, 1);

    for (int kt = 0; kt < NKT; kt++) {
        CP_WAIT1();
        __syncthreads();

        if (kt + 2 < NKT) ISSUE_STAGE((kt + 2) % GSTAGES, kt + 2);

        const uint32_t stg = sbase + (kt % GSTAGES) * STAGE_BYTES;
        const uint32_t aOp = stg;
        const uint32_t bOp = stg + OP_BYTES;

        #pragma unroll
        for (int ks = 0; ks < 4; ks++) {
            const uint32_t ko = (uint32_t)ks * 32;
            uint32_t aa[2][4], bb[8][2];
            #pragma unroll
            for (int mt = 0; mt < 2; mt++) {
                ldm4(aa[mt], aOp + offA[mt] + ko);
            }
            #pragma unroll
            for (int ntp = 0; ntp < 4; ntp++) {
                uint32_t r[4];
                ldm4(r, bOp + offB[ntp] + ko);
                bb[2*ntp][0] = r[0]; bb[2*ntp][1] = r[1];
                bb[2*ntp+1][0] = r[2]; bb[2*ntp+1][1] = r[3];
            }
            #pragma unroll
            for (int mt = 0; mt < 2; mt++)
                #pragma unroll
                for (int nt = 0; nt < 8; nt++) {
                    mma_fp16(acc[mt][nt], aa[mt], bb[nt]);
                }
        }
    }

    if (!ext) {
        const int slab = bx*2 + warpN;
        #pragma unroll
        for (int mt = 0; mt < 2; mt++) {
            #pragma unroll
            for (int rr = 0; rr < 2; rr++) {
                const int row = by*128 + warpM*32 + mt*16 + (lane >> 2) + rr*8;
                const float qv0 = g_qs[(size_t)row * AGENTS + bx*4 + warpN*2];
                const float qv1 = g_qs[(size_t)row * AGENTS + bx*4 + warpN*2 + 1];
                float part[8];
                #pragma unroll
                for (int s = 0; s < 8; s++) part[s] = 0.f;
                #pragma unroll
                for (int nt = 0; nt < 8; nt++) {
                    const float qv = (nt < 4) ? qv0 : qv1;
                    #pragma unroll
                    for (int j = 0; j < 2; j++) {
                        const int col = warpN*64 + nt*8 + (lane & 3)*2 + j;
                        float v = acc[mt][nt][rr*2 + j] + sbias[col];
                        part[(nt & 3)*2 + j] = fmaf(qv, fabsf(v), part[(nt & 3)*2 + j]);
                    }
                }
                float* dst = g_part + ((size_t)slab * BS + row) * EMB;
                #pragma unroll
                for (int k4 = 0; k4 < 4; k4++) {
                    const int e = k4*8 + (lane & 3)*2;
                    *(float2*)(dst + e) = make_float2(part[k4*2], part[k4*2 + 1]);
                }
            }
        }
    } else {
        #pragma unroll
        for (int mt = 0; mt < 2; mt++) {
            #pragma unroll
            for (int rr = 0; rr < 2; rr++) {
                const int row = by*128 + warpM*32 + mt*16 + (lane >> 2) + rr*8;
                float* dst = g_ext + (size_t)row * 128;
                #pragma unroll
                for (int nt = 0; nt < 8; nt++) {
                    const int col = warpN*64 + nt*8 + (lane & 3)*2;
                    *(float2*)(dst + col) =
                        make_float2(acc[mt][nt][rr*2 + 0], acc[mt][nt][rr*2 + 1]);
                }
            }
        }
    }
}

// =============================================================================
// Final mixing
// =============================================================================
__global__ void __launch_bounds__(128) final_kernel(
    const float* __restrict__ bhb, const float* __restrict__ bhf,
    const float* __restrict__ bv1,
    const float* __restrict__ Wv2, const float* __restrict__ bv2,
    float* __restrict__ qtot)
{
    const int b = blockIdx.x * 4 + (threadIdx.x >> 5);
    const int e = threadIdx.x & 31;

    const float* ex = g_ext + (size_t)b * 128;
    float sb = ex[e] + bhb[e];
    float wf = fabsf(ex[32 + e] + bhf[e]);
    float rv = ex[64 + e] + bv1[e];
    rv = rv > 0.f ? rv : 0.f;

    float s = 0.f;
    #pragma unroll
    for (int sl = 0; sl < 64; sl++)
        s += g_part[((size_t)sl * BS + b) * EMB + e];
    float hp = s + sb;
    float hidden = hp > 0.f ? hp : expm1f(hp);
    float contrib = hidden * wf + rv * Wv2[e];
    #pragma unroll
    for (int o = 16; o > 0; o >>= 1)
        contrib += __shfl_down_sync(0xffffffffu, contrib, o);
    if (e == 0) qtot[b] = contrib + bv2[0];
}

// =============================================================================
extern "C" void kernel_launch(void* const* d_in, const int* in_sizes, int n_in,
                              void* d_out, int out_size)
{
    const float* obs    = (const float*)d_in[0];
    const float* states = (const float*)d_in[1];
    const float* W1  = (const float*)d_in[2];
    const float* b1  = (const float*)d_in[3];
    const float* W2  = (const float*)d_in[4];
    const float* b2  = (const float*)d_in[5];
    const float* W3  = (const float*)d_in[6];
    const float* b3  = (const float*)d_in[7];
    const float* Wh1 = (const float*)d_in[8];
    const float* bh1 = (const float*)d_in[9];
    const float* Whb = (const float*)d_in[10];
    const float* bhb = (const float*)d_in[11];
    const float* Whf = (const float*)d_in[12];
    const float* bhf = (const float*)d_in[13];
    const float* Wv1 = (const float*)d_in[14];
    const float* bv1 = (const float*)d_in[15];
    const float* Wv2 = (const float*)d_in[16];
    const float* bv2 = (const float*)d_in[17];
    float* out = (float*)d_out;

    cudaFuncSetAttribute(mlp_kernel, cudaFuncAttributeMaxDynamicSharedMemorySize, MLP_SMEM);
    cudaFuncSetAttribute(hyper_gemm_mma, cudaFuncAttributeMaxDynamicSharedMemorySize, GEMM_SMEM);

    float* act_dst;
    if (out_size >= (int)(BS + BS*AGENTS)) {
        act_dst = out + BS;
    } else {
        void* p = 0;
        cudaGetSymbolAddress(&p, g_act_fallback);
        act_dst = (float*)p;
    }

    // Strictly sequential, single stream (overlap regressed twice: L2 pollution).
    mlp_kernel<<<dim3(AGENTS, BS/MLP_BT), 512, MLP_SMEM>>>(
        obs, W1, b1, W2, b2, W3, b3, act_dst);
    conv_all_kernel<<<CONV_TOTAL, 256>>>(states, Wh1, Whb, Whf, Wv1);
    hyper_gemm_mma<<<1056, 256, GEMM_SMEM>>>(bh1);
    final_kernel<<<BS/4, 128>>>(bhb, bhf, bv1, Wv2, bv2, out);
}